// round 6
// baseline (speedup 1.0000x reference)
#include <cuda_runtime.h>
#include <math.h>

#define B_    2
#define L_    2048
#define DIM_  1024
#define NH    16
#define NKV   4
#define HD    64
#define KVD   (NKV*HD)      // 256
#define NTOK  (B_*L_)       // 4096

typedef unsigned long long u64;

// Scratch (no cudaMalloc allowed)
__device__ float g_q[NTOK*DIM_];     // 16 MB
__device__ float g_k[NTOK*KVD];      // 4 MB
__device__ float g_v[NTOK*KVD];      // 4 MB
__device__ float g_ao[NTOK*DIM_];    // 16 MB

// ---------------- packed f32x2 helpers (B300 FFMA2 path) -------------------
__device__ __forceinline__ u64 pk2(float x) {
    u64 r; asm("mov.b64 %0,{%1,%1};" : "=l"(r) : "f"(x)); return r;
}
__device__ __forceinline__ void fma2(u64 &d, u64 a, u64 b) {
    asm("fma.rn.f32x2 %0, %1, %2, %0;" : "+l"(d) : "l"(a), "l"(b));
}
__device__ __forceinline__ void mul2(u64 &d, u64 a) {
    asm("mul.rn.f32x2 %0, %0, %1;" : "+l"(d) : "l"(a));
}
__device__ __forceinline__ u64 add2(u64 a, u64 b) {
    u64 r; asm("add.rn.f32x2 %0, %1, %2;" : "=l"(r) : "l"(a), "l"(b)); return r;
}
__device__ __forceinline__ float2 up2(u64 a) {
    float2 f; asm("mov.b64 {%0,%1}, %2;" : "=f"(f.x), "=f"(f.y) : "l"(a)); return f;
}

// ---------------------------------------------------------------------------
// 128x128x16 fp32 GEMM using FFMA2, double-buffered smem (1 sync per k-tile).
// Row-major A[M,K], B[K,N], C[M,N]. 256 threads, 8x8 outputs/thread.
// ---------------------------------------------------------------------------
__device__ __forceinline__ void gemm128_body(const float* __restrict__ A,
                                             const float* __restrict__ B,
                                             float* __restrict__ C,
                                             int m0, int n0, int N, int K) {
    __shared__ __align__(16) float As[2][16][132];   // As[buf][k][m]
    __shared__ __align__(16) float Bs[2][16][128];   // Bs[buf][k][n]

    const int tid = threadIdx.x;
    const int tx  = tid & 15;          // N sub-tile
    const int ty  = tid >> 4;          // M sub-tile

    const int arow = tid >> 2;             // 0..63 (two row-chunks)
    const int acol = (tid & 3) << 2;       // 0,4,8,12
    const int brow = tid >> 5;             // 0..7 (two row-chunks)
    const int bcol = (tid & 31) << 2;      // 0..124

    u64 acc[8][4];
    #pragma unroll
    for (int i = 0; i < 8; i++)
        #pragma unroll
        for (int j = 0; j < 4; j++) acc[i][j] = 0ull;

    float4 ra[2], rb[2];
    const int NKB = K >> 4;

    // prologue: load tile 0 -> regs -> smem buf 0
    #pragma unroll
    for (int l = 0; l < 2; l++) {
        ra[l] = *(const float4*)&A[(size_t)(m0 + arow + l * 64) * K + acol];
        rb[l] = *(const float4*)&B[(size_t)(brow + l * 8) * N + n0 + bcol];
    }
    #pragma unroll
    for (int l = 0; l < 2; l++) {
        As[0][acol + 0][arow + l * 64] = ra[l].x;
        As[0][acol + 1][arow + l * 64] = ra[l].y;
        As[0][acol + 2][arow + l * 64] = ra[l].z;
        As[0][acol + 3][arow + l * 64] = ra[l].w;
        *(float4*)&Bs[0][brow + l * 8][bcol] = rb[l];
    }
    __syncthreads();

    int buf = 0;
    for (int kb = 0; kb < NKB; kb++) {
        if (kb + 1 < NKB) {
            const int k0 = (kb + 1) << 4;
            #pragma unroll
            for (int l = 0; l < 2; l++) {
                ra[l] = *(const float4*)&A[(size_t)(m0 + arow + l * 64) * K + k0 + acol];
                rb[l] = *(const float4*)&B[(size_t)(k0 + brow + l * 8) * N + n0 + bcol];
            }
        }
        #pragma unroll
        for (int kk = 0; kk < 16; kk++) {
            const ulonglong2* bp = (const ulonglong2*)&Bs[buf][kk][tx << 3];
            ulonglong2 b01 = bp[0], b23 = bp[1];
            u64 bv[4] = {b01.x, b01.y, b23.x, b23.y};
            float4 a0 = *(const float4*)&As[buf][kk][ty << 3];
            float4 a1 = *(const float4*)&As[buf][kk][(ty << 3) + 4];
            float av[8] = {a0.x, a0.y, a0.z, a0.w, a1.x, a1.y, a1.z, a1.w};
            #pragma unroll
            for (int i = 0; i < 8; i++) {
                u64 ap = pk2(av[i]);
                #pragma unroll
                for (int j = 0; j < 4; j++) fma2(acc[i][j], ap, bv[j]);
            }
        }
        if (kb + 1 < NKB) {
            const int nb = buf ^ 1;
            #pragma unroll
            for (int l = 0; l < 2; l++) {
                As[nb][acol + 0][arow + l * 64] = ra[l].x;
                As[nb][acol + 1][arow + l * 64] = ra[l].y;
                As[nb][acol + 2][arow + l * 64] = ra[l].z;
                As[nb][acol + 3][arow + l * 64] = ra[l].w;
                *(float4*)&Bs[nb][brow + l * 8][bcol] = rb[l];
            }
            __syncthreads();
            buf = nb;
        }
    }

    #pragma unroll
    for (int i = 0; i < 8; i++) {
        float* crow = &C[(size_t)(m0 + (ty << 3) + i) * N + n0 + (tx << 3)];
        ulonglong2 s0; s0.x = acc[i][0]; s0.y = acc[i][1];
        ulonglong2 s1; s1.x = acc[i][2]; s1.y = acc[i][3];
        ((ulonglong2*)crow)[0] = s0;
        ((ulonglong2*)crow)[1] = s1;
    }
}

__global__ __launch_bounds__(256) void sgemm128(const float* __restrict__ A,
                                                const float* __restrict__ B,
                                                float* __restrict__ C,
                                                int N, int K) {
    gemm128_body(A, B, C, blockIdx.y * 128, blockIdx.x * 128, N, K);
}

// Fused K+V projection: grid.x = 4; x<2 -> wk/g_k, else wv/g_v (N=256 each).
__global__ __launch_bounds__(256) void sgemm128_kv(const float* __restrict__ A,
                                                   const float* __restrict__ Bk,
                                                   const float* __restrict__ Bv,
                                                   float* __restrict__ Ck,
                                                   float* __restrict__ Cv,
                                                   int K) {
    const int bx = blockIdx.x;
    if (bx < 2) gemm128_body(A, Bk, Ck, blockIdx.y * 128, bx * 128, KVD, K);
    else        gemm128_body(A, Bv, Cv, blockIdx.y * 128, (bx - 2) * 128, KVD, K);
}

// ---------------------------------------------------------------------------
// Fused per-head RMSNorm + RoPE, in place on g_q / g_k. One warp per row.
// ---------------------------------------------------------------------------
__global__ __launch_bounds__(256) void rmsrope_kernel(const float* __restrict__ gq,
                                                      const float* __restrict__ gk) {
    const int gw   = blockIdx.x * 8 + (threadIdx.x >> 5);
    const int lane = threadIdx.x & 31;

    float* row;
    const float* g;
    int tok;
    if (gw < NTOK * NH) {
        tok = gw >> 4;
        int h = gw & 15;
        row = g_q + (size_t)tok * DIM_ + h * HD;
        g   = gq;
    } else {
        int r = gw - NTOK * NH;
        tok = r >> 2;
        int hk = r & 3;
        row = g_k + (size_t)tok * KVD + hk * HD;
        g   = gk;
    }
    const int pos = tok & (L_ - 1);

    float2 v = ((const float2*)row)[lane];
    float ss = v.x * v.x + v.y * v.y;
    #pragma unroll
    for (int off = 16; off > 0; off >>= 1)
        ss += __shfl_xor_sync(0xffffffffu, ss, off);
    float rn = rsqrtf(ss * (1.0f / 64.0f) + 1e-6f);

    float2 gg = ((const float2*)g)[lane];
    float t1 = v.x * rn * gg.x;
    float t2 = v.y * rn * gg.y;

    float inv_freq = exp2f((float)lane * (-13.287712379549449f / 32.0f));
    float ang = (float)pos * inv_freq;
    float s, c;
    sincosf(ang, &s, &c);

    ((float2*)row)[lane] = make_float2(t1 * c - t2 * s, t1 * s + t2 * c);
}

// ---------------------------------------------------------------------------
// Tiled sliding-window + global attention, split head-dim across thread pairs.
// Block = 128 threads: 64 queries x 2 half-rows, ONE head per block.
// grid: x=4 (head in kv-group), y=32 (q tile), z=8 (b*NKV + hk).
// ---------------------------------------------------------------------------
__global__ __launch_bounds__(128) void attn3_kernel() {
    __shared__ __align__(16) float Ks[64][64];
    __shared__ __align__(16) float Vs[64][64];

    const int tid  = threadIdx.x;
    const int row  = tid >> 1;           // 0..63 query in tile
    const int half = tid & 1;            // 0/1 half of head-dim
    const int t    = blockIdx.y;         // q tile
    const int hq   = blockIdx.x;         // head within kv group
    const int bz   = blockIdx.z;
    const int b    = bz >> 2;
    const int hk   = bz & 3;
    const int h    = hk * 4 + hq;
    const int i    = t * 64 + row;

    // q half-row -> registers (pre-scaled by 1/sqrt(64))
    u64 q2[16];
    {
        const ulonglong2* qp = (const ulonglong2*)
            (g_q + ((size_t)(b * L_ + i)) * DIM_ + h * HD + half * 32);
        u64 sc = pk2(0.125f);
        #pragma unroll
        for (int c = 0; c < 8; c++) {
            ulonglong2 u = qp[c];
            q2[2 * c] = u.x; q2[2 * c + 1] = u.y;
            mul2(q2[2 * c], sc); mul2(q2[2 * c + 1], sc);
        }
    }

    u64 o2[16];
    #pragma unroll
    for (int c = 0; c < 16; c++) o2[c] = 0ull;
    float m = -1e30f, s = 0.0f;

    const float* kg = g_k + ((size_t)(b * L_)) * KVD + hk * HD;
    const float* vg = g_v + ((size_t)(b * L_)) * KVD + hk * HD;

    auto process_chunk = [&](int cc) {
        const int kb = cc * 64;
        __syncthreads();   // previous chunk fully consumed
        #pragma unroll
        for (int l = 0; l < 8; l++) {
            int idx = tid + l * 128;
            int r = idx >> 4, c = (idx & 15) << 2;
            *(float4*)&Ks[r][c] = *(const float4*)&kg[(size_t)(kb + r) * KVD + c];
            *(float4*)&Vs[r][c] = *(const float4*)&vg[(size_t)(kb + r) * KVD + c];
        }
        __syncthreads();

        #pragma unroll 1
        for (int jj = 0; jj < 64; jj++) {
            const int j = kb + jj;
            const ulonglong2* kv = (const ulonglong2*)(&Ks[jj][half * 32]);
            u64 d2[4];
            #pragma unroll
            for (int c = 0; c < 4; c++) d2[c] = 0ull;
            #pragma unroll
            for (int c = 0; c < 8; c++) {
                ulonglong2 l = kv[c];
                fma2(d2[(2 * c) & 3],     q2[2 * c],     l.x);
                fma2(d2[(2 * c + 1) & 3], q2[2 * c + 1], l.y);
            }
            float2 pf = up2(add2(add2(d2[0], d2[1]), add2(d2[2], d2[3])));
            float p = pf.x + pf.y;
            p += __shfl_xor_sync(0xffffffffu, p, 1);   // combine halves

            bool valid = (j <= i) && ((j >= i - 256) || (j < 64));
            float pv = valid ? p : -INFINITY;
            float mo = m;
            m = fmaxf(m, pv);
            float e = __expf(pv - m);
            u64 ep = pk2(e);
            const ulonglong2* vv = (const ulonglong2*)(&Vs[jj][half * 32]);

            if (__any_sync(0xffffffffu, m > mo)) {
                float corr = __expf(mo - m);
                s = s * corr + e;
                u64 cp = pk2(corr);
                #pragma unroll
                for (int c = 0; c < 8; c++) {
                    ulonglong2 l = vv[c];
                    mul2(o2[2 * c], cp);     fma2(o2[2 * c], ep, l.x);
                    mul2(o2[2 * c + 1], cp); fma2(o2[2 * c + 1], ep, l.y);
                }
            } else {
                s += e;
                #pragma unroll
                for (int c = 0; c < 8; c++) {
                    ulonglong2 l = vv[c];
                    fma2(o2[2 * c],     ep, l.x);
                    fma2(o2[2 * c + 1], ep, l.y);
                }
            }
        }
    };

    // chunks: global chunk 0, plus window chunks [max(0,t-4) .. t]
    if (t > 4) process_chunk(0);
    int c0 = t - 4; if (c0 < 0) c0 = 0;
    for (int cc = c0; cc <= t; cc++) process_chunk(cc);

    // normalize + store half-row
    float inv = 1.0f / s;
    u64 ip = pk2(inv);
    ulonglong2* op = (ulonglong2*)
        (g_ao + ((size_t)(b * L_ + i)) * DIM_ + h * HD + half * 32);
    #pragma unroll
    for (int c = 0; c < 8; c++) {
        mul2(o2[2 * c], ip); mul2(o2[2 * c + 1], ip);
        ulonglong2 u; u.x = o2[2 * c]; u.y = o2[2 * c + 1];
        op[c] = u;
    }
}

// ---------------------------------------------------------------------------
extern "C" void kernel_launch(void* const* d_in, const int* in_sizes, int n_in,
                              void* d_out, int out_size) {
    const float* x  = (const float*)d_in[0];
    const float* wq = (const float*)d_in[1];
    const float* wk = (const float*)d_in[2];
    const float* wv = (const float*)d_in[3];
    const float* wo = (const float*)d_in[4];
    const float* gq = (const float*)d_in[5];
    const float* gk = (const float*)d_in[6];

    float *q, *k, *v, *ao;
    cudaGetSymbolAddress((void**)&q,  g_q);
    cudaGetSymbolAddress((void**)&k,  g_k);
    cudaGetSymbolAddress((void**)&v,  g_v);
    cudaGetSymbolAddress((void**)&ao, g_ao);

    // Q projection + fused K/V projections
    sgemm128<<<dim3(DIM_ / 128, NTOK / 128), 256>>>(x, wq, q, DIM_, DIM_);
    sgemm128_kv<<<dim3(4, NTOK / 128), 256>>>(x, wk, wv, k, v, DIM_);

    // RMSNorm + RoPE on q and k (in place)
    const int nrows = NTOK * NH + NTOK * NKV;   // 81920
    rmsrope_kernel<<<nrows / 8, 256>>>(gq, gk);

    // Attention
    attn3_kernel<<<dim3(4, 32, 8), 128>>>();

    // Output projection -> d_out
    sgemm128<<<dim3(DIM_ / 128, NTOK / 128), 256>>>(ao, wo, (float*)d_out, DIM_, DIM_);
}

// round 8
// speedup vs baseline: 1.6687x; 1.6687x over previous
#include <cuda_runtime.h>
#include <cuda_bf16.h>
#include <cstdint>
#include <math.h>

#define B_    2
#define L_    2048
#define DIM_  1024
#define NH    16
#define NKV   4
#define HD    64
#define NTOK  (B_*L_)       // 4096
#define KVW   512           // fused k|v row width

typedef unsigned long long u64;

// ------------------------- scratch (__device__, no mallocs) -----------------
__device__ __align__(16) float g_q  [NTOK*DIM_];
__device__ __align__(16) float g_kv [NTOK*KVW];
__device__ __align__(16) float g_ao [NTOK*DIM_];

__device__ __align__(16) __nv_bfloat16 g_xh [NTOK*DIM_];
__device__ __align__(16) __nv_bfloat16 g_xl [NTOK*DIM_];
__device__ __align__(16) __nv_bfloat16 g_aoh[NTOK*DIM_];
__device__ __align__(16) __nv_bfloat16 g_aol[NTOK*DIM_];

__device__ __align__(16) __nv_bfloat16 g_wqt_h [DIM_*DIM_];   // [n][k]
__device__ __align__(16) __nv_bfloat16 g_wqt_l [DIM_*DIM_];
__device__ __align__(16) __nv_bfloat16 g_wkvt_h[KVW*DIM_];
__device__ __align__(16) __nv_bfloat16 g_wkvt_l[KVW*DIM_];
__device__ __align__(16) __nv_bfloat16 g_wot_h [DIM_*DIM_];
__device__ __align__(16) __nv_bfloat16 g_wot_l [DIM_*DIM_];

// ------------------------- mma.sync helpers (base ISA, works on sm_103) -----
__device__ __forceinline__ uint32_t smem_u32(const void* p) {
    uint32_t a;
    asm("{ .reg .u64 t; cvta.to.shared.u64 t, %1; cvt.u32.u64 %0, t; }"
        : "=r"(a) : "l"(p));
    return a;
}
__device__ __forceinline__ void ldm4(uint32_t f[4], uint32_t addr) {
    asm volatile("ldmatrix.sync.aligned.m8n8.x4.shared.b16 {%0,%1,%2,%3}, [%4];"
                 : "=r"(f[0]), "=r"(f[1]), "=r"(f[2]), "=r"(f[3]) : "r"(addr));
}
__device__ __forceinline__ void mma16816(float c[4], const uint32_t a[4],
                                         uint32_t b0, uint32_t b1) {
    asm volatile("mma.sync.aligned.m16n8k16.row.col.f32.bf16.bf16.f32 "
                 "{%0,%1,%2,%3},{%4,%5,%6,%7},{%8,%9},{%0,%1,%2,%3};"
                 : "+f"(c[0]), "+f"(c[1]), "+f"(c[2]), "+f"(c[3])
                 : "r"(a[0]), "r"(a[1]), "r"(a[2]), "r"(a[3]), "r"(b0), "r"(b1));
}

// ---------------------------------------------------------------------------
// HMMA split-bf16 GEMM: C[4096][Ncols] = A @ B^T, fp32 via hi/lo bf16
// (AhBh + AhBl + AlBh). A*: [4096][1024] bf16 K-major; B*: [Ncols][1024].
// Block 128x128, BK=32, 256 threads (8 warps, 4x2), warp tile 32x64.
// Double-buffered smem, pitch-40 b16 rows (conflict-free ldmatrix).
// ---------------------------------------------------------------------------
#define PITCH     40
#define TILE_B16  (128*PITCH)          // 5120 b16 per tile
#define TILE_BY   (TILE_B16*2)         // 10240 bytes
#define BUF_B16   (4*TILE_B16)         // Ah,Al,Bh,Bl
#define BUF_BY    (BUF_B16*2)          // 40960 bytes
#define GSMEM     (2*BUF_BY)           // 81920 bytes
#define NKB       (DIM_/32)            // 32

__global__ __launch_bounds__(256) void hmma_gemm(const __nv_bfloat16* __restrict__ Ah_,
                                                 const __nv_bfloat16* __restrict__ Al_,
                                                 const __nv_bfloat16* __restrict__ Bh_,
                                                 const __nv_bfloat16* __restrict__ Bl_,
                                                 float* __restrict__ C, int Ncols) {
    extern __shared__ __align__(128) __nv_bfloat16 sm[];

    const int tid  = threadIdx.x;
    const int wid  = tid >> 5;
    const int lane = tid & 31;
    const int wm   = (wid & 3) * 32;       // warp m offset in tile
    const int wn   = (wid >> 2) * 64;      // warp n offset in tile
    const int m0   = blockIdx.y * 128;
    const int n0   = blockIdx.x * 128;

    const uint32_t smb = smem_u32(sm);

    // per-thread ldmatrix byte offsets within a buffer
    uint32_t aoff[2], boff[4];
    #pragma unroll
    for (int mt = 0; mt < 2; mt++)
        aoff[mt] = ((wm + mt * 16 + (lane & 15)) * PITCH + ((lane >> 4) << 3)) * 2;
    #pragma unroll
    for (int pr = 0; pr < 4; pr++)
        boff[pr] = ((wn + pr * 16 + (lane & 7) + ((lane >> 4) & 1) * 8) * PITCH
                    + (((lane >> 3) & 1) << 3)) * 2;

    float acc[2][8][4];
    #pragma unroll
    for (int mt = 0; mt < 2; mt++)
        #pragma unroll
        for (int nt = 0; nt < 8; nt++)
            #pragma unroll
            for (int r = 0; r < 4; r++) acc[mt][nt][r] = 0.0f;

    auto stage = [&](int k0, int buf) {
        __nv_bfloat16* sb = sm + (size_t)buf * BUF_B16;
        #pragma unroll
        for (int i = 0; i < 2; i++) {
            int chunk = tid * 2 + i;            // 0..511
            int r  = chunk >> 2;
            int c8 = (chunk & 3) << 3;
            size_t goA = (size_t)(m0 + r) * DIM_ + k0 + c8;
            size_t goB = (size_t)(n0 + r) * DIM_ + k0 + c8;
            uint32_t so = r * PITCH + c8;
            *(uint4*)(sb + so)                 = *(const uint4*)(Ah_ + goA);
            *(uint4*)(sb + TILE_B16 + so)      = *(const uint4*)(Al_ + goA);
            *(uint4*)(sb + 2 * TILE_B16 + so)  = *(const uint4*)(Bh_ + goB);
            *(uint4*)(sb + 3 * TILE_B16 + so)  = *(const uint4*)(Bl_ + goB);
        }
    };

    stage(0, 0);
    __syncthreads();

    #pragma unroll 1
    for (int kb = 0; kb < NKB; kb++) {
        const int buf = kb & 1;
        if (kb + 1 < NKB) stage((kb + 1) * 32, buf ^ 1);   // overlap LDG with MMA

        const uint32_t sb = smb + buf * BUF_BY;
        #pragma unroll
        for (int ks = 0; ks < 2; ks++) {
            uint32_t ah[2][4], al[2][4], bh[4][4], bl[4][4];
            #pragma unroll
            for (int mt = 0; mt < 2; mt++) {
                uint32_t ao = sb + aoff[mt] + ks * 32;
                ldm4(ah[mt], ao);
                ldm4(al[mt], ao + TILE_BY);
            }
            #pragma unroll
            for (int pr = 0; pr < 4; pr++) {
                uint32_t bo = sb + boff[pr] + ks * 32;
                ldm4(bh[pr], bo + 2 * TILE_BY);
                ldm4(bl[pr], bo + 3 * TILE_BY);
            }
            #pragma unroll
            for (int mt = 0; mt < 2; mt++)
                #pragma unroll
                for (int nt = 0; nt < 8; nt++) {
                    const uint32_t* f = bh[nt >> 1];
                    uint32_t b0 = (nt & 1) ? f[2] : f[0];
                    uint32_t b1 = (nt & 1) ? f[3] : f[1];
                    mma16816(acc[mt][nt], ah[mt], b0, b1);
                }
            #pragma unroll
            for (int mt = 0; mt < 2; mt++)
                #pragma unroll
                for (int nt = 0; nt < 8; nt++) {
                    const uint32_t* f = bl[nt >> 1];
                    uint32_t b0 = (nt & 1) ? f[2] : f[0];
                    uint32_t b1 = (nt & 1) ? f[3] : f[1];
                    mma16816(acc[mt][nt], ah[mt], b0, b1);
                }
            #pragma unroll
            for (int mt = 0; mt < 2; mt++)
                #pragma unroll
                for (int nt = 0; nt < 8; nt++) {
                    const uint32_t* f = bh[nt >> 1];
                    uint32_t b0 = (nt & 1) ? f[2] : f[0];
                    uint32_t b1 = (nt & 1) ? f[3] : f[1];
                    mma16816(acc[mt][nt], al[mt], b0, b1);
                }
        }
        __syncthreads();
    }

    // epilogue: c0,c1 -> (row, col..col+1); c2,c3 -> (row+8, ...)
    #pragma unroll
    for (int mt = 0; mt < 2; mt++) {
        const int row = m0 + wm + mt * 16 + (lane >> 2);
        #pragma unroll
        for (int nt = 0; nt < 8; nt++) {
            const int col = n0 + wn + nt * 8 + (lane & 3) * 2;
            float2 lo; lo.x = acc[mt][nt][0]; lo.y = acc[mt][nt][1];
            float2 hi; hi.x = acc[mt][nt][2]; hi.y = acc[mt][nt][3];
            *(float2*)&C[(size_t)row * Ncols + col]       = lo;
            *(float2*)&C[(size_t)(row + 8) * Ncols + col] = hi;
        }
    }
}

// ---------------------------------------------------------------------------
// fp32 -> bf16 hi/lo split (4 elems/thread)
// ---------------------------------------------------------------------------
__global__ __launch_bounds__(256) void split4(const float* __restrict__ src,
                                              __nv_bfloat16* __restrict__ hi,
                                              __nv_bfloat16* __restrict__ lo) {
    size_t i = ((size_t)blockIdx.x * 256 + threadIdx.x) * 4;
    float4 v = *(const float4*)(src + i);
    float vv[4] = {v.x, v.y, v.z, v.w};
    ushort4 H, Lo;
    unsigned short* hp = &H.x;
    unsigned short* lp = &Lo.x;
    #pragma unroll
    for (int j = 0; j < 4; j++) {
        __nv_bfloat16 h = __float2bfloat16(vv[j]);
        float res = vv[j] - __bfloat162float(h);
        hp[j] = __bfloat16_as_ushort(h);
        lp[j] = __bfloat16_as_ushort(__float2bfloat16(res));
    }
    *(ushort4*)(hi + i) = H;
    *(ushort4*)(lo + i) = Lo;
}

// ---------------------------------------------------------------------------
// Weight transpose + split: W[1024][N] fp32 -> T*[N][1024] bf16 hi/lo.
// ---------------------------------------------------------------------------
__global__ void wtrans(const float* __restrict__ W,
                       __nv_bfloat16* __restrict__ Th,
                       __nv_bfloat16* __restrict__ Tl, int N) {
    __shared__ float t[32][33];
    const int tx = threadIdx.x, ty = threadIdx.y;
    const int n0 = blockIdx.x * 32, k0 = blockIdx.y * 32;
    #pragma unroll
    for (int i = 0; i < 4; i++) {
        int r = ty + i * 8;
        t[r][tx] = W[(size_t)(k0 + r) * N + n0 + tx];
    }
    __syncthreads();
    #pragma unroll
    for (int i = 0; i < 4; i++) {
        int r = ty + i * 8;
        float val = t[tx][r];
        __nv_bfloat16 h = __float2bfloat16(val);
        float res = val - __bfloat162float(h);
        size_t o = (size_t)(n0 + r) * DIM_ + k0 + tx;
        Th[o] = h;
        Tl[o] = __float2bfloat16(res);
    }
}

// ---------------------------------------------------------------------------
// Fused per-head RMSNorm + RoPE, in place on g_q / g_kv(K half). Warp per row.
// ---------------------------------------------------------------------------
__global__ __launch_bounds__(256) void rmsrope_kernel(const float* __restrict__ gq,
                                                      const float* __restrict__ gk) {
    const int gw   = blockIdx.x * 8 + (threadIdx.x >> 5);
    const int lane = threadIdx.x & 31;

    float* row;
    const float* g;
    int tok;
    if (gw < NTOK * NH) {
        tok = gw >> 4;
        int h = gw & 15;
        row = g_q + (size_t)tok * DIM_ + h * HD;
        g   = gq;
    } else {
        int r = gw - NTOK * NH;
        tok = r >> 2;
        int hk = r & 3;
        row = g_kv + (size_t)tok * KVW + hk * HD;
        g   = gk;
    }
    const int pos = tok & (L_ - 1);

    float2 v = ((const float2*)row)[lane];
    float ss = v.x * v.x + v.y * v.y;
    #pragma unroll
    for (int off = 16; off > 0; off >>= 1)
        ss += __shfl_xor_sync(0xffffffffu, ss, off);
    float rn = rsqrtf(ss * (1.0f / 64.0f) + 1e-6f);

    float2 gg = ((const float2*)g)[lane];
    float t1 = v.x * rn * gg.x;
    float t2 = v.y * rn * gg.y;

    float inv_freq = exp2f((float)lane * (-13.287712379549449f / 32.0f));
    float ang = (float)pos * inv_freq;
    float s, c;
    sincosf(ang, &s, &c);

    ((float2*)row)[lane] = make_float2(t1 * c - t2 * s, t1 * s + t2 * c);
}

// ---------------- packed f32x2 helpers (attention) --------------------------
__device__ __forceinline__ u64 pk2(float x) {
    u64 r; asm("mov.b64 %0,{%1,%1};" : "=l"(r) : "f"(x)); return r;
}
__device__ __forceinline__ void fma2(u64 &d, u64 a, u64 b) {
    asm("fma.rn.f32x2 %0, %1, %2, %0;" : "+l"(d) : "l"(a), "l"(b));
}
__device__ __forceinline__ void mul2(u64 &d, u64 a) {
    asm("mul.rn.f32x2 %0, %0, %1;" : "+l"(d) : "l"(a));
}
__device__ __forceinline__ u64 add2(u64 a, u64 b) {
    u64 r; asm("add.rn.f32x2 %0, %1, %2;" : "=l"(r) : "l"(a), "l"(b)); return r;
}
__device__ __forceinline__ float2 up2(u64 a) {
    float2 f; asm("mov.b64 {%0,%1}, %2;" : "=f"(f.x), "=f"(f.y) : "l"(a)); return f;
}

// ---------------------------------------------------------------------------
// Sliding-window + global attention (best measured config).
// Block 128 = 2 heads x 64 queries; one thread per q row.
// grid: x=2 (head pair), y=32 (q tile), z=8 (b*NKV + hk).
// ---------------------------------------------------------------------------
__global__ __launch_bounds__(128) void attn2_kernel() {
    __shared__ __align__(16) float Ks[64][64];
    __shared__ __align__(16) float Vs[64][64];

    const int tid = threadIdx.x;
    const int hr  = tid >> 6;
    const int qi  = tid & 63;
    const int t   = blockIdx.y;
    const int hp  = blockIdx.x;
    const int bz  = blockIdx.z;
    const int b   = bz >> 2;
    const int hk  = bz & 3;
    const int h   = hk * 4 + hp * 2 + hr;
    const int i   = t * 64 + qi;

    u64 q2[32];
    {
        const ulonglong2* qp =
            (const ulonglong2*)(g_q + ((size_t)(b * L_ + i)) * DIM_ + h * HD);
        u64 sc = pk2(0.125f);
        #pragma unroll
        for (int c = 0; c < 16; c++) {
            ulonglong2 u = qp[c];
            q2[2 * c] = u.x; q2[2 * c + 1] = u.y;
            mul2(q2[2 * c], sc); mul2(q2[2 * c + 1], sc);
        }
    }

    u64 o2[32];
    #pragma unroll
    for (int c = 0; c < 32; c++) o2[c] = 0ull;
    float m = -1e30f, s = 0.0f;

    const float* kg = g_kv + ((size_t)(b * L_)) * KVW + hk * HD;
    const float* vg = kg + 256;

    auto process_chunk = [&](int cc) {
        const int kb = cc * 64;
        __syncthreads();
        #pragma unroll
        for (int l = 0; l < 8; l++) {
            int idx = tid + l * 128;
            int r = idx >> 4, c = (idx & 15) << 2;
            *(float4*)&Ks[r][c] = *(const float4*)&kg[(size_t)(kb + r) * KVW + c];
            *(float4*)&Vs[r][c] = *(const float4*)&vg[(size_t)(kb + r) * KVW + c];
        }
        __syncthreads();

        #pragma unroll 1
        for (int jj = 0; jj < 64; jj++) {
            const int j = kb + jj;
            const ulonglong2* kv = (const ulonglong2*)Ks[jj];
            u64 d2[8];
            #pragma unroll
            for (int c = 0; c < 8; c++) d2[c] = 0ull;
            #pragma unroll
            for (int c = 0; c < 16; c++) {
                ulonglong2 l = kv[c];
                fma2(d2[(2 * c) & 7],     q2[2 * c],     l.x);
                fma2(d2[(2 * c + 1) & 7], q2[2 * c + 1], l.y);
            }
            u64 r0 = add2(add2(d2[0], d2[1]), add2(d2[2], d2[3]));
            u64 r1 = add2(add2(d2[4], d2[5]), add2(d2[6], d2[7]));
            float2 pf = up2(add2(r0, r1));
            float p = pf.x + pf.y;

            bool valid = (j <= i) && ((j >= i - 256) || (j < 64));
            float pv = valid ? p : -INFINITY;
            float mo = m;
            m = fmaxf(m, pv);
            float e = __expf(pv - m);
            u64 ep = pk2(e);
            const ulonglong2* vv = (const ulonglong2*)Vs[jj];

            if (__any_sync(0xffffffffu, m > mo)) {
                float corr = __expf(mo - m);
                s = s * corr + e;
                u64 cp = pk2(corr);
                #pragma unroll
                for (int c = 0; c < 16; c++) {
                    ulonglong2 l = vv[c];
                    mul2(o2[2 * c], cp);     fma2(o2[2 * c], ep, l.x);
                    mul2(o2[2 * c + 1], cp); fma2(o2[2 * c + 1], ep, l.y);
                }
            } else {
                s += e;
                #pragma unroll
                for (int c = 0; c < 16; c++) {
                    ulonglong2 l = vv[c];
                    fma2(o2[2 * c],     ep, l.x);
                    fma2(o2[2 * c + 1], ep, l.y);
                }
            }
        }
    };

    if (t > 4) process_chunk(0);
    int c0 = t - 4; if (c0 < 0) c0 = 0;
    for (int cc = c0; cc <= t; cc++) process_chunk(cc);

    float inv = 1.0f / s;
    u64 ip = pk2(inv);
    ulonglong2* op = (ulonglong2*)(g_ao + ((size_t)(b * L_ + i)) * DIM_ + h * HD);
    #pragma unroll
    for (int c = 0; c < 16; c++) {
        mul2(o2[2 * c], ip); mul2(o2[2 * c + 1], ip);
        ulonglong2 u; u.x = o2[2 * c]; u.y = o2[2 * c + 1];
        op[c] = u;
    }
}

// ---------------------------------------------------------------------------
extern "C" void kernel_launch(void* const* d_in, const int* in_sizes, int n_in,
                              void* d_out, int out_size) {
    const float* x  = (const float*)d_in[0];
    const float* wq = (const float*)d_in[1];
    const float* wk = (const float*)d_in[2];
    const float* wv = (const float*)d_in[3];
    const float* wo = (const float*)d_in[4];
    const float* gq = (const float*)d_in[5];
    const float* gk = (const float*)d_in[6];

    float *q, *kv, *ao;
    __nv_bfloat16 *xh, *xl, *aoh, *aol, *wqth, *wqtl, *wkvth, *wkvtl, *woth, *wotl;
    cudaGetSymbolAddress((void**)&q,    g_q);
    cudaGetSymbolAddress((void**)&kv,   g_kv);
    cudaGetSymbolAddress((void**)&ao,   g_ao);
    cudaGetSymbolAddress((void**)&xh,   g_xh);
    cudaGetSymbolAddress((void**)&xl,   g_xl);
    cudaGetSymbolAddress((void**)&aoh,  g_aoh);
    cudaGetSymbolAddress((void**)&aol,  g_aol);
    cudaGetSymbolAddress((void**)&wqth, g_wqt_h);
    cudaGetSymbolAddress((void**)&wqtl, g_wqt_l);
    cudaGetSymbolAddress((void**)&wkvth,g_wkvt_h);
    cudaGetSymbolAddress((void**)&wkvtl,g_wkvt_l);
    cudaGetSymbolAddress((void**)&woth, g_wot_h);
    cudaGetSymbolAddress((void**)&wotl, g_wot_l);

    cudaFuncSetAttribute(hmma_gemm, cudaFuncAttributeMaxDynamicSharedMemorySize,
                         GSMEM);

    // input splits / weight transposes
    split4<<<NTOK * DIM_ / 1024, 256>>>(x, xh, xl);
    wtrans<<<dim3(DIM_ / 32, 32), dim3(32, 8)>>>(wq, wqth, wqtl, DIM_);
    wtrans<<<dim3(256 / 32, 32), dim3(32, 8)>>>(wk, wkvth, wkvtl, 256);
    wtrans<<<dim3(256 / 32, 32), dim3(32, 8)>>>(wv, wkvth + 256 * DIM_,
                                                wkvtl + 256 * DIM_, 256);
    wtrans<<<dim3(DIM_ / 32, 32), dim3(32, 8)>>>(wo, woth, wotl, DIM_);

    // projections via HMMA split-bf16 GEMM
    hmma_gemm<<<dim3(DIM_ / 128, NTOK / 128), 256, GSMEM>>>(xh, xl, wqth, wqtl, q, DIM_);
    hmma_gemm<<<dim3(KVW  / 128, NTOK / 128), 256, GSMEM>>>(xh, xl, wkvth, wkvtl, kv, KVW);

    // RMSNorm + RoPE (q and k in place)
    const int nrows = NTOK * NH + NTOK * NKV;
    rmsrope_kernel<<<nrows / 8, 256>>>(gq, gk);

    // attention
    attn2_kernel<<<dim3(2, 32, 8), 128>>>();

    // output projection
    split4<<<NTOK * DIM_ / 1024, 256>>>(ao, aoh, aol);
    hmma_gemm<<<dim3(DIM_ / 128, NTOK / 128), 256, GSMEM>>>(aoh, aol, woth, wotl,
                                                            (float*)d_out, DIM_);
}

// round 9
// speedup vs baseline: 1.7978x; 1.0774x over previous
#include <cuda_runtime.h>
#include <cuda_bf16.h>
#include <cstdint>
#include <math.h>

#define B_    2
#define L_    2048
#define DIM_  1024
#define NH    16
#define NKV   4
#define HD    64
#define NTOK  (B_*L_)       // 4096
#define KVW   512           // fused k|v row width

typedef unsigned long long u64;

// ------------------------- scratch (__device__, no mallocs) -----------------
__device__ __align__(16) float g_q  [NTOK*DIM_];
__device__ __align__(16) float g_kv [NTOK*KVW];
__device__ __align__(16) float g_ao [NTOK*DIM_];

__device__ __align__(16) __nv_bfloat16 g_xh [NTOK*DIM_];
__device__ __align__(16) __nv_bfloat16 g_xl [NTOK*DIM_];
__device__ __align__(16) __nv_bfloat16 g_aoh[NTOK*DIM_];
__device__ __align__(16) __nv_bfloat16 g_aol[NTOK*DIM_];

__device__ __align__(16) __nv_bfloat16 g_wqt_h [DIM_*DIM_];   // [n][k]
__device__ __align__(16) __nv_bfloat16 g_wqt_l [DIM_*DIM_];
__device__ __align__(16) __nv_bfloat16 g_wkvt_h[KVW*DIM_];
__device__ __align__(16) __nv_bfloat16 g_wkvt_l[KVW*DIM_];
__device__ __align__(16) __nv_bfloat16 g_wot_h [DIM_*DIM_];
__device__ __align__(16) __nv_bfloat16 g_wot_l [DIM_*DIM_];

// ------------------------- mma.sync helpers (base ISA, works on sm_103) -----
__device__ __forceinline__ uint32_t smem_u32(const void* p) {
    uint32_t a;
    asm("{ .reg .u64 t; cvta.to.shared.u64 t, %1; cvt.u32.u64 %0, t; }"
        : "=r"(a) : "l"(p));
    return a;
}
__device__ __forceinline__ void ldm4(uint32_t f[4], uint32_t addr) {
    asm volatile("ldmatrix.sync.aligned.m8n8.x4.shared.b16 {%0,%1,%2,%3}, [%4];"
                 : "=r"(f[0]), "=r"(f[1]), "=r"(f[2]), "=r"(f[3]) : "r"(addr));
}
__device__ __forceinline__ void mma16816(float c[4], const uint32_t a[4],
                                         uint32_t b0, uint32_t b1) {
    asm volatile("mma.sync.aligned.m16n8k16.row.col.f32.bf16.bf16.f32 "
                 "{%0,%1,%2,%3},{%4,%5,%6,%7},{%8,%9},{%0,%1,%2,%3};"
                 : "+f"(c[0]), "+f"(c[1]), "+f"(c[2]), "+f"(c[3])
                 : "r"(a[0]), "r"(a[1]), "r"(a[2]), "r"(a[3]), "r"(b0), "r"(b1));
}

// ---------------------------------------------------------------------------
// HMMA split-bf16 GEMM: C[4096][Ncols] = A @ B^T, fp32 via hi/lo bf16
// (AhBh + AhBl + AlBh). A*: [4096][1024] bf16 K-major; B*: [Ncols][1024].
// Block 128x128, BK=32, 256 threads (8 warps, 4x2), warp tile 32x64.
// ---------------------------------------------------------------------------
#define PITCH     40
#define TILE_B16  (128*PITCH)
#define TILE_BY   (TILE_B16*2)
#define BUF_B16   (4*TILE_B16)
#define BUF_BY    (BUF_B16*2)
#define GSMEM     (2*BUF_BY)
#define NKB       (DIM_/32)

__global__ __launch_bounds__(256) void hmma_gemm(const __nv_bfloat16* __restrict__ Ah_,
                                                 const __nv_bfloat16* __restrict__ Al_,
                                                 const __nv_bfloat16* __restrict__ Bh_,
                                                 const __nv_bfloat16* __restrict__ Bl_,
                                                 float* __restrict__ C, int Ncols) {
    extern __shared__ __align__(128) __nv_bfloat16 sm[];

    const int tid  = threadIdx.x;
    const int wid  = tid >> 5;
    const int lane = tid & 31;
    const int wm   = (wid & 3) * 32;
    const int wn   = (wid >> 2) * 64;
    const int m0   = blockIdx.y * 128;
    const int n0   = blockIdx.x * 128;

    const uint32_t smb = smem_u32(sm);

    uint32_t aoff[2], boff[4];
    #pragma unroll
    for (int mt = 0; mt < 2; mt++)
        aoff[mt] = ((wm + mt * 16 + (lane & 15)) * PITCH + ((lane >> 4) << 3)) * 2;
    #pragma unroll
    for (int pr = 0; pr < 4; pr++)
        boff[pr] = ((wn + pr * 16 + (lane & 7) + ((lane >> 4) & 1) * 8) * PITCH
                    + (((lane >> 3) & 1) << 3)) * 2;

    float acc[2][8][4];
    #pragma unroll
    for (int mt = 0; mt < 2; mt++)
        #pragma unroll
        for (int nt = 0; nt < 8; nt++)
            #pragma unroll
            for (int r = 0; r < 4; r++) acc[mt][nt][r] = 0.0f;

    auto stage = [&](int k0, int buf) {
        __nv_bfloat16* sb = sm + (size_t)buf * BUF_B16;
        #pragma unroll
        for (int i = 0; i < 2; i++) {
            int chunk = tid * 2 + i;
            int r  = chunk >> 2;
            int c8 = (chunk & 3) << 3;
            size_t goA = (size_t)(m0 + r) * DIM_ + k0 + c8;
            size_t goB = (size_t)(n0 + r) * DIM_ + k0 + c8;
            uint32_t so = r * PITCH + c8;
            *(uint4*)(sb + so)                 = *(const uint4*)(Ah_ + goA);
            *(uint4*)(sb + TILE_B16 + so)      = *(const uint4*)(Al_ + goA);
            *(uint4*)(sb + 2 * TILE_B16 + so)  = *(const uint4*)(Bh_ + goB);
            *(uint4*)(sb + 3 * TILE_B16 + so)  = *(const uint4*)(Bl_ + goB);
        }
    };

    stage(0, 0);
    __syncthreads();

    #pragma unroll 1
    for (int kb = 0; kb < NKB; kb++) {
        const int buf = kb & 1;
        if (kb + 1 < NKB) stage((kb + 1) * 32, buf ^ 1);

        const uint32_t sb = smb + buf * BUF_BY;
        #pragma unroll
        for (int ks = 0; ks < 2; ks++) {
            uint32_t ah[2][4], al[2][4], bh[4][4], bl[4][4];
            #pragma unroll
            for (int mt = 0; mt < 2; mt++) {
                uint32_t ao = sb + aoff[mt] + ks * 32;
                ldm4(ah[mt], ao);
                ldm4(al[mt], ao + TILE_BY);
            }
            #pragma unroll
            for (int pr = 0; pr < 4; pr++) {
                uint32_t bo = sb + boff[pr] + ks * 32;
                ldm4(bh[pr], bo + 2 * TILE_BY);
                ldm4(bl[pr], bo + 3 * TILE_BY);
            }
            #pragma unroll
            for (int mt = 0; mt < 2; mt++)
                #pragma unroll
                for (int nt = 0; nt < 8; nt++) {
                    const uint32_t* f = bh[nt >> 1];
                    uint32_t b0 = (nt & 1) ? f[2] : f[0];
                    uint32_t b1 = (nt & 1) ? f[3] : f[1];
                    mma16816(acc[mt][nt], ah[mt], b0, b1);
                }
            #pragma unroll
            for (int mt = 0; mt < 2; mt++)
                #pragma unroll
                for (int nt = 0; nt < 8; nt++) {
                    const uint32_t* f = bl[nt >> 1];
                    uint32_t b0 = (nt & 1) ? f[2] : f[0];
                    uint32_t b1 = (nt & 1) ? f[3] : f[1];
                    mma16816(acc[mt][nt], ah[mt], b0, b1);
                }
            #pragma unroll
            for (int mt = 0; mt < 2; mt++)
                #pragma unroll
                for (int nt = 0; nt < 8; nt++) {
                    const uint32_t* f = bh[nt >> 1];
                    uint32_t b0 = (nt & 1) ? f[2] : f[0];
                    uint32_t b1 = (nt & 1) ? f[3] : f[1];
                    mma16816(acc[mt][nt], al[mt], b0, b1);
                }
        }
        __syncthreads();
    }

    #pragma unroll
    for (int mt = 0; mt < 2; mt++) {
        const int row = m0 + wm + mt * 16 + (lane >> 2);
        #pragma unroll
        for (int nt = 0; nt < 8; nt++) {
            const int col = n0 + wn + nt * 8 + (lane & 3) * 2;
            float2 lo; lo.x = acc[mt][nt][0]; lo.y = acc[mt][nt][1];
            float2 hi; hi.x = acc[mt][nt][2]; hi.y = acc[mt][nt][3];
            *(float2*)&C[(size_t)row * Ncols + col]       = lo;
            *(float2*)&C[(size_t)(row + 8) * Ncols + col] = hi;
        }
    }
}

// ---------------------------------------------------------------------------
__global__ __launch_bounds__(256) void split4(const float* __restrict__ src,
                                              __nv_bfloat16* __restrict__ hi,
                                              __nv_bfloat16* __restrict__ lo) {
    size_t i = ((size_t)blockIdx.x * 256 + threadIdx.x) * 4;
    float4 v = *(const float4*)(src + i);
    float vv[4] = {v.x, v.y, v.z, v.w};
    ushort4 H, Lo;
    unsigned short* hp = &H.x;
    unsigned short* lp = &Lo.x;
    #pragma unroll
    for (int j = 0; j < 4; j++) {
        __nv_bfloat16 h = __float2bfloat16(vv[j]);
        float res = vv[j] - __bfloat162float(h);
        hp[j] = __bfloat16_as_ushort(h);
        lp[j] = __bfloat16_as_ushort(__float2bfloat16(res));
    }
    *(ushort4*)(hi + i) = H;
    *(ushort4*)(lo + i) = Lo;
}

// ---------------------------------------------------------------------------
__global__ void wtrans(const float* __restrict__ W,
                       __nv_bfloat16* __restrict__ Th,
                       __nv_bfloat16* __restrict__ Tl, int N) {
    __shared__ float t[32][33];
    const int tx = threadIdx.x, ty = threadIdx.y;
    const int n0 = blockIdx.x * 32, k0 = blockIdx.y * 32;
    #pragma unroll
    for (int i = 0; i < 4; i++) {
        int r = ty + i * 8;
        t[r][tx] = W[(size_t)(k0 + r) * N + n0 + tx];
    }
    __syncthreads();
    #pragma unroll
    for (int i = 0; i < 4; i++) {
        int r = ty + i * 8;
        float val = t[tx][r];
        __nv_bfloat16 h = __float2bfloat16(val);
        float res = val - __bfloat162float(h);
        size_t o = (size_t)(n0 + r) * DIM_ + k0 + tx;
        Th[o] = h;
        Tl[o] = __float2bfloat16(res);
    }
}

// ---------------------------------------------------------------------------
__global__ __launch_bounds__(256) void rmsrope_kernel(const float* __restrict__ gq,
                                                      const float* __restrict__ gk) {
    const int gw   = blockIdx.x * 8 + (threadIdx.x >> 5);
    const int lane = threadIdx.x & 31;

    float* row;
    const float* g;
    int tok;
    if (gw < NTOK * NH) {
        tok = gw >> 4;
        int h = gw & 15;
        row = g_q + (size_t)tok * DIM_ + h * HD;
        g   = gq;
    } else {
        int r = gw - NTOK * NH;
        tok = r >> 2;
        int hk = r & 3;
        row = g_kv + (size_t)tok * KVW + hk * HD;
        g   = gk;
    }
    const int pos = tok & (L_ - 1);

    float2 v = ((const float2*)row)[lane];
    float ss = v.x * v.x + v.y * v.y;
    #pragma unroll
    for (int off = 16; off > 0; off >>= 1)
        ss += __shfl_xor_sync(0xffffffffu, ss, off);
    float rn = rsqrtf(ss * (1.0f / 64.0f) + 1e-6f);

    float2 gg = ((const float2*)g)[lane];
    float t1 = v.x * rn * gg.x;
    float t2 = v.y * rn * gg.y;

    float inv_freq = exp2f((float)lane * (-13.287712379549449f / 32.0f));
    float ang = (float)pos * inv_freq;
    float s, c;
    sincosf(ang, &s, &c);

    ((float2*)row)[lane] = make_float2(t1 * c - t2 * s, t1 * s + t2 * c);
}

// ---------------- packed f32x2 helpers (attention) --------------------------
__device__ __forceinline__ u64 pk2(float x) {
    u64 r; asm("mov.b64 %0,{%1,%1};" : "=l"(r) : "f"(x)); return r;
}
__device__ __forceinline__ void fma2(u64 &d, u64 a, u64 b) {
    asm("fma.rn.f32x2 %0, %1, %2, %0;" : "+l"(d) : "l"(a), "l"(b));
}
__device__ __forceinline__ void mul2(u64 &d, u64 a) {
    asm("mul.rn.f32x2 %0, %0, %1;" : "+l"(d) : "l"(a));
}
__device__ __forceinline__ u64 add2(u64 a, u64 b) {
    u64 r; asm("add.rn.f32x2 %0, %1, %2;" : "=l"(r) : "l"(a), "l"(b)); return r;
}
__device__ __forceinline__ float2 up2(u64 a) {
    float2 f; asm("mov.b64 {%0,%1}, %2;" : "=f"(f.x), "=f"(f.y) : "l"(a)); return f;
}

// ---------------------------------------------------------------------------
// Sliding-window + global attention, 4-key-batched online softmax.
// Block 128 = 2 heads x 64 queries; one thread per q row.
// grid: x=2 (head pair), y=32 (q tile), z=8 (b*NKV + hk).
// ---------------------------------------------------------------------------
__global__ __launch_bounds__(128) void attn4_kernel() {
    __shared__ __align__(16) float Ks[64][64];
    __shared__ __align__(16) float Vs[64][64];

    const int tid = threadIdx.x;
    const int hr  = tid >> 6;
    const int qi  = tid & 63;
    const int t   = blockIdx.y;
    const int hp  = blockIdx.x;
    const int bz  = blockIdx.z;
    const int b   = bz >> 2;
    const int hk  = bz & 3;
    const int h   = hk * 4 + hp * 2 + hr;
    const int i   = t * 64 + qi;

    u64 q2[32];
    {
        const ulonglong2* qp =
            (const ulonglong2*)(g_q + ((size_t)(b * L_ + i)) * DIM_ + h * HD);
        u64 sc = pk2(0.125f);
        #pragma unroll
        for (int c = 0; c < 16; c++) {
            ulonglong2 u = qp[c];
            q2[2 * c] = u.x; q2[2 * c + 1] = u.y;
            mul2(q2[2 * c], sc); mul2(q2[2 * c + 1], sc);
        }
    }

    u64 o2[32];
    #pragma unroll
    for (int c = 0; c < 32; c++) o2[c] = 0ull;
    float m = -1e30f, s = 0.0f;

    const float* kg = g_kv + ((size_t)(b * L_)) * KVW + hk * HD;
    const float* vg = kg + 256;

    auto process_chunk = [&](int cc, bool full) {
        const int kb = cc * 64;
        __syncthreads();
        #pragma unroll
        for (int l = 0; l < 8; l++) {
            int idx = tid + l * 128;
            int r = idx >> 4, c = (idx & 15) << 2;
            *(float4*)&Ks[r][c] = *(const float4*)&kg[(size_t)(kb + r) * KVW + c];
            *(float4*)&Vs[r][c] = *(const float4*)&vg[(size_t)(kb + r) * KVW + c];
        }
        __syncthreads();

        #pragma unroll 1
        for (int g4 = 0; g4 < 16; g4++) {
            const int j0 = kb + g4 * 4;
            const ulonglong2* k0p = (const ulonglong2*)Ks[g4 * 4 + 0];
            const ulonglong2* k1p = (const ulonglong2*)Ks[g4 * 4 + 1];
            const ulonglong2* k2p = (const ulonglong2*)Ks[g4 * 4 + 2];
            const ulonglong2* k3p = (const ulonglong2*)Ks[g4 * 4 + 3];

            u64 dk[4][4];
            #pragma unroll
            for (int k = 0; k < 4; k++)
                #pragma unroll
                for (int c = 0; c < 4; c++) dk[k][c] = 0ull;

            #pragma unroll
            for (int c = 0; c < 16; c++) {
                ulonglong2 l0 = k0p[c], l1 = k1p[c], l2 = k2p[c], l3 = k3p[c];
                const int i0 = (2 * c) & 3, i1 = (2 * c + 1) & 3;
                fma2(dk[0][i0], q2[2 * c], l0.x); fma2(dk[0][i1], q2[2 * c + 1], l0.y);
                fma2(dk[1][i0], q2[2 * c], l1.x); fma2(dk[1][i1], q2[2 * c + 1], l1.y);
                fma2(dk[2][i0], q2[2 * c], l2.x); fma2(dk[2][i1], q2[2 * c + 1], l2.y);
                fma2(dk[3][i0], q2[2 * c], l3.x); fma2(dk[3][i1], q2[2 * c + 1], l3.y);
            }

            float p[4];
            #pragma unroll
            for (int k = 0; k < 4; k++) {
                float2 pf = up2(add2(add2(dk[k][0], dk[k][1]),
                                     add2(dk[k][2], dk[k][3])));
                p[k] = pf.x + pf.y;
            }

            if (!full) {
                #pragma unroll
                for (int k = 0; k < 4; k++) {
                    int j = j0 + k;
                    bool valid = (j <= i) && ((j >= i - 256) || (j < 64));
                    p[k] = valid ? p[k] : -INFINITY;
                }
            }

            float pmax = fmaxf(fmaxf(p[0], p[1]), fmaxf(p[2], p[3]));
            float mn   = fmaxf(m, pmax);
            float corr = __expf(m - mn);
            float e0 = __expf(p[0] - mn);
            float e1 = __expf(p[1] - mn);
            float e2 = __expf(p[2] - mn);
            float e3 = __expf(p[3] - mn);
            s = s * corr + (e0 + e1) + (e2 + e3);
            m = mn;

            u64 cp  = pk2(corr);
            u64 ep0 = pk2(e0), ep1 = pk2(e1), ep2 = pk2(e2), ep3 = pk2(e3);
            const ulonglong2* v0p = (const ulonglong2*)Vs[g4 * 4 + 0];
            const ulonglong2* v1p = (const ulonglong2*)Vs[g4 * 4 + 1];
            const ulonglong2* v2p = (const ulonglong2*)Vs[g4 * 4 + 2];
            const ulonglong2* v3p = (const ulonglong2*)Vs[g4 * 4 + 3];

            #pragma unroll
            for (int c = 0; c < 16; c++) {
                ulonglong2 l0 = v0p[c], l1 = v1p[c], l2 = v2p[c], l3 = v3p[c];
                u64 &ox = o2[2 * c], &oy = o2[2 * c + 1];
                mul2(ox, cp);
                fma2(ox, ep0, l0.x); fma2(ox, ep1, l1.x);
                fma2(ox, ep2, l2.x); fma2(ox, ep3, l3.x);
                mul2(oy, cp);
                fma2(oy, ep0, l0.y); fma2(oy, ep1, l1.y);
                fma2(oy, ep2, l2.y); fma2(oy, ep3, l3.y);
            }
        }
    };

    // chunk schedule: global chunk 0 (full iff t>4), window chunks:
    //   cc = t-4 : partial (lower window bound cuts in)
    //   cc in [t-3, t-1] : full
    //   cc = t   : partial (causal triangle)
    if (t > 4) process_chunk(0, true);
    int c0 = t - 4; if (c0 < 0) c0 = 0;
    for (int cc = c0; cc < t; cc++)
        process_chunk(cc, (t - cc) <= 3 && t <= 4 ? true : (t - cc) <= 3);
    process_chunk(t, false);

    float inv = 1.0f / s;
    u64 ip = pk2(inv);
    ulonglong2* op = (ulonglong2*)(g_ao + ((size_t)(b * L_ + i)) * DIM_ + h * HD);
    #pragma unroll
    for (int c = 0; c < 16; c++) {
        mul2(o2[2 * c], ip); mul2(o2[2 * c + 1], ip);
        ulonglong2 u; u.x = o2[2 * c]; u.y = o2[2 * c + 1];
        op[c] = u;
    }
}

// ---------------------------------------------------------------------------
extern "C" void kernel_launch(void* const* d_in, const int* in_sizes, int n_in,
                              void* d_out, int out_size) {
    const float* x  = (const float*)d_in[0];
    const float* wq = (const float*)d_in[1];
    const float* wk = (const float*)d_in[2];
    const float* wv = (const float*)d_in[3];
    const float* wo = (const float*)d_in[4];
    const float* gq = (const float*)d_in[5];
    const float* gk = (const float*)d_in[6];

    float *q, *kv, *ao;
    __nv_bfloat16 *xh, *xl, *aoh, *aol, *wqth, *wqtl, *wkvth, *wkvtl, *woth, *wotl;
    cudaGetSymbolAddress((void**)&q,    g_q);
    cudaGetSymbolAddress((void**)&kv,   g_kv);
    cudaGetSymbolAddress((void**)&ao,   g_ao);
    cudaGetSymbolAddress((void**)&xh,   g_xh);
    cudaGetSymbolAddress((void**)&xl,   g_xl);
    cudaGetSymbolAddress((void**)&aoh,  g_aoh);
    cudaGetSymbolAddress((void**)&aol,  g_aol);
    cudaGetSymbolAddress((void**)&wqth, g_wqt_h);
    cudaGetSymbolAddress((void**)&wqtl, g_wqt_l);
    cudaGetSymbolAddress((void**)&wkvth,g_wkvt_h);
    cudaGetSymbolAddress((void**)&wkvtl,g_wkvt_l);
    cudaGetSymbolAddress((void**)&woth, g_wot_h);
    cudaGetSymbolAddress((void**)&wotl, g_wot_l);

    cudaFuncSetAttribute(hmma_gemm, cudaFuncAttributeMaxDynamicSharedMemorySize,
                         GSMEM);

    // input splits / weight transposes
    split4<<<NTOK * DIM_ / 1024, 256>>>(x, xh, xl);
    wtrans<<<dim3(DIM_ / 32, 32), dim3(32, 8)>>>(wq, wqth, wqtl, DIM_);
    wtrans<<<dim3(256 / 32, 32), dim3(32, 8)>>>(wk, wkvth, wkvtl, 256);
    wtrans<<<dim3(256 / 32, 32), dim3(32, 8)>>>(wv, wkvth + 256 * DIM_,
                                                wkvtl + 256 * DIM_, 256);
    wtrans<<<dim3(DIM_ / 32, 32), dim3(32, 8)>>>(wo, woth, wotl, DIM_);

    // projections via HMMA split-bf16 GEMM
    hmma_gemm<<<dim3(DIM_ / 128, NTOK / 128), 256, GSMEM>>>(xh, xl, wqth, wqtl, q, DIM_);
    hmma_gemm<<<dim3(KVW  / 128, NTOK / 128), 256, GSMEM>>>(xh, xl, wkvth, wkvtl, kv, KVW);

    // RMSNorm + RoPE (q and k in place)
    const int nrows = NTOK * NH + NTOK * NKV;
    rmsrope_kernel<<<nrows / 8, 256>>>(gq, gk);

    // attention
    attn4_kernel<<<dim3(2, 32, 8), 128>>>();

    // output projection
    split4<<<NTOK * DIM_ / 1024, 256>>>(ao, aoh, aol);
    hmma_gemm<<<dim3(DIM_ / 128, NTOK / 128), 256, GSMEM>>>(aoh, aol, woth, wotl,
                                                            (float*)d_out, DIM_);
}

// round 10
// speedup vs baseline: 2.5473x; 1.4169x over previous
#include <cuda_runtime.h>
#include <cuda_bf16.h>
#include <cstdint>
#include <math.h>

#define B_    2
#define L_    2048
#define DIM_  1024
#define NH    16
#define NKV   4
#define HD    64
#define NTOK  (B_*L_)       // 4096
#define KVW   512           // fused k|v row width

typedef unsigned long long u64;

// ------------------------- scratch (__device__, no mallocs) -----------------
__device__ __align__(16) float g_q  [NTOK*DIM_];
__device__ __align__(16) float g_kv [NTOK*KVW];

__device__ __align__(16) __nv_bfloat16 g_xh [NTOK*DIM_];
__device__ __align__(16) __nv_bfloat16 g_xl [NTOK*DIM_];
__device__ __align__(16) __nv_bfloat16 g_aoh[NTOK*DIM_];
__device__ __align__(16) __nv_bfloat16 g_aol[NTOK*DIM_];

__device__ __align__(16) __nv_bfloat16 g_wqt_h [DIM_*DIM_];   // [n][k]
__device__ __align__(16) __nv_bfloat16 g_wqt_l [DIM_*DIM_];
__device__ __align__(16) __nv_bfloat16 g_wkvt_h[KVW*DIM_];
__device__ __align__(16) __nv_bfloat16 g_wkvt_l[KVW*DIM_];
__device__ __align__(16) __nv_bfloat16 g_wot_h [DIM_*DIM_];
__device__ __align__(16) __nv_bfloat16 g_wot_l [DIM_*DIM_];

// ------------------------- mma.sync helpers (base ISA) ----------------------
__device__ __forceinline__ uint32_t smem_u32(const void* p) {
    uint32_t a;
    asm("{ .reg .u64 t; cvta.to.shared.u64 t, %1; cvt.u32.u64 %0, t; }"
        : "=r"(a) : "l"(p));
    return a;
}
__device__ __forceinline__ void ldm4(uint32_t f[4], uint32_t addr) {
    asm volatile("ldmatrix.sync.aligned.m8n8.x4.shared.b16 {%0,%1,%2,%3}, [%4];"
                 : "=r"(f[0]), "=r"(f[1]), "=r"(f[2]), "=r"(f[3]) : "r"(addr));
}
__device__ __forceinline__ void ldm4t(uint32_t f[4], uint32_t addr) {
    asm volatile("ldmatrix.sync.aligned.m8n8.x4.trans.shared.b16 {%0,%1,%2,%3}, [%4];"
                 : "=r"(f[0]), "=r"(f[1]), "=r"(f[2]), "=r"(f[3]) : "r"(addr));
}
__device__ __forceinline__ void mma16816(float c[4], const uint32_t a[4],
                                         uint32_t b0, uint32_t b1) {
    asm volatile("mma.sync.aligned.m16n8k16.row.col.f32.bf16.bf16.f32 "
                 "{%0,%1,%2,%3},{%4,%5,%6,%7},{%8,%9},{%0,%1,%2,%3};"
                 : "+f"(c[0]), "+f"(c[1]), "+f"(c[2]), "+f"(c[3])
                 : "r"(a[0]), "r"(a[1]), "r"(a[2]), "r"(a[3]), "r"(b0), "r"(b1));
}
__device__ __forceinline__ uint32_t pack2(__nv_bfloat16 a, __nv_bfloat16 b) {
    return (uint32_t)__bfloat16_as_ushort(a) |
           ((uint32_t)__bfloat16_as_ushort(b) << 16);
}

// ---------------------------------------------------------------------------
// HMMA split-bf16 GEMM (unchanged from passing R8 kernel).
// ---------------------------------------------------------------------------
#define PITCH     40
#define TILE_B16  (128*PITCH)
#define TILE_BY   (TILE_B16*2)
#define BUF_B16   (4*TILE_B16)
#define BUF_BY    (BUF_B16*2)
#define GSMEM     (2*BUF_BY)
#define NKB       (DIM_/32)

__global__ __launch_bounds__(256) void hmma_gemm(const __nv_bfloat16* __restrict__ Ah_,
                                                 const __nv_bfloat16* __restrict__ Al_,
                                                 const __nv_bfloat16* __restrict__ Bh_,
                                                 const __nv_bfloat16* __restrict__ Bl_,
                                                 float* __restrict__ C, int Ncols) {
    extern __shared__ __align__(128) __nv_bfloat16 sm[];

    const int tid  = threadIdx.x;
    const int wid  = tid >> 5;
    const int lane = tid & 31;
    const int wm   = (wid & 3) * 32;
    const int wn   = (wid >> 2) * 64;
    const int m0   = blockIdx.y * 128;
    const int n0   = blockIdx.x * 128;

    const uint32_t smb = smem_u32(sm);

    uint32_t aoff[2], boff[4];
    #pragma unroll
    for (int mt = 0; mt < 2; mt++)
        aoff[mt] = ((wm + mt * 16 + (lane & 15)) * PITCH + ((lane >> 4) << 3)) * 2;
    #pragma unroll
    for (int pr = 0; pr < 4; pr++)
        boff[pr] = ((wn + pr * 16 + (lane & 7) + ((lane >> 4) & 1) * 8) * PITCH
                    + (((lane >> 3) & 1) << 3)) * 2;

    float acc[2][8][4];
    #pragma unroll
    for (int i = 0; i < 2; i++)
        #pragma unroll
        for (int j = 0; j < 8; j++)
            #pragma unroll
            for (int r = 0; r < 4; r++) acc[i][j][r] = 0.0f;

    auto stage = [&](int k0, int buf) {
        __nv_bfloat16* sb = sm + (size_t)buf * BUF_B16;
        #pragma unroll
        for (int i = 0; i < 2; i++) {
            int chunk = tid * 2 + i;
            int r  = chunk >> 2;
            int c8 = (chunk & 3) << 3;
            size_t goA = (size_t)(m0 + r) * DIM_ + k0 + c8;
            size_t goB = (size_t)(n0 + r) * DIM_ + k0 + c8;
            uint32_t so = r * PITCH + c8;
            *(uint4*)(sb + so)                 = *(const uint4*)(Ah_ + goA);
            *(uint4*)(sb + TILE_B16 + so)      = *(const uint4*)(Al_ + goA);
            *(uint4*)(sb + 2 * TILE_B16 + so)  = *(const uint4*)(Bh_ + goB);
            *(uint4*)(sb + 3 * TILE_B16 + so)  = *(const uint4*)(Bl_ + goB);
        }
    };

    stage(0, 0);
    __syncthreads();

    #pragma unroll 1
    for (int kb = 0; kb < NKB; kb++) {
        const int buf = kb & 1;
        if (kb + 1 < NKB) stage((kb + 1) * 32, buf ^ 1);

        const uint32_t sb = smb + buf * BUF_BY;
        #pragma unroll
        for (int ks = 0; ks < 2; ks++) {
            uint32_t ah[2][4], al[2][4], bh[4][4], bl[4][4];
            #pragma unroll
            for (int mt = 0; mt < 2; mt++) {
                uint32_t ao = sb + aoff[mt] + ks * 32;
                ldm4(ah[mt], ao);
                ldm4(al[mt], ao + TILE_BY);
            }
            #pragma unroll
            for (int pr = 0; pr < 4; pr++) {
                uint32_t bo = sb + boff[pr] + ks * 32;
                ldm4(bh[pr], bo + 2 * TILE_BY);
                ldm4(bl[pr], bo + 3 * TILE_BY);
            }
            #pragma unroll
            for (int mt = 0; mt < 2; mt++)
                #pragma unroll
                for (int nt = 0; nt < 8; nt++) {
                    const uint32_t* f = bh[nt >> 1];
                    mma16816(acc[mt][nt], ah[mt], (nt & 1) ? f[2] : f[0],
                             (nt & 1) ? f[3] : f[1]);
                }
            #pragma unroll
            for (int mt = 0; mt < 2; mt++)
                #pragma unroll
                for (int nt = 0; nt < 8; nt++) {
                    const uint32_t* f = bl[nt >> 1];
                    mma16816(acc[mt][nt], ah[mt], (nt & 1) ? f[2] : f[0],
                             (nt & 1) ? f[3] : f[1]);
                }
            #pragma unroll
            for (int mt = 0; mt < 2; mt++)
                #pragma unroll
                for (int nt = 0; nt < 8; nt++) {
                    const uint32_t* f = bh[nt >> 1];
                    mma16816(acc[mt][nt], al[mt], (nt & 1) ? f[2] : f[0],
                             (nt & 1) ? f[3] : f[1]);
                }
        }
        __syncthreads();
    }

    #pragma unroll
    for (int mt = 0; mt < 2; mt++) {
        const int row = m0 + wm + mt * 16 + (lane >> 2);
        #pragma unroll
        for (int nt = 0; nt < 8; nt++) {
            const int col = n0 + wn + nt * 8 + (lane & 3) * 2;
            float2 lo; lo.x = acc[mt][nt][0]; lo.y = acc[mt][nt][1];
            float2 hi; hi.x = acc[mt][nt][2]; hi.y = acc[mt][nt][3];
            *(float2*)&C[(size_t)row * Ncols + col]       = lo;
            *(float2*)&C[(size_t)(row + 8) * Ncols + col] = hi;
        }
    }
}

// ---------------------------------------------------------------------------
__global__ __launch_bounds__(256) void split4(const float* __restrict__ src,
                                              __nv_bfloat16* __restrict__ hi,
                                              __nv_bfloat16* __restrict__ lo) {
    size_t i = ((size_t)blockIdx.x * 256 + threadIdx.x) * 4;
    float4 v = *(const float4*)(src + i);
    float vv[4] = {v.x, v.y, v.z, v.w};
    ushort4 H, Lo;
    unsigned short* hp = &H.x;
    unsigned short* lp = &Lo.x;
    #pragma unroll
    for (int j = 0; j < 4; j++) {
        __nv_bfloat16 h = __float2bfloat16(vv[j]);
        float res = vv[j] - __bfloat162float(h);
        hp[j] = __bfloat16_as_ushort(h);
        lp[j] = __bfloat16_as_ushort(__float2bfloat16(res));
    }
    *(ushort4*)(hi + i) = H;
    *(ushort4*)(lo + i) = Lo;
}

// ---------------------------------------------------------------------------
__global__ void wtrans(const float* __restrict__ W,
                       __nv_bfloat16* __restrict__ Th,
                       __nv_bfloat16* __restrict__ Tl, int N) {
    __shared__ float t[32][33];
    const int tx = threadIdx.x, ty = threadIdx.y;
    const int n0 = blockIdx.x * 32, k0 = blockIdx.y * 32;
    #pragma unroll
    for (int i = 0; i < 4; i++) {
        int r = ty + i * 8;
        t[r][tx] = W[(size_t)(k0 + r) * N + n0 + tx];
    }
    __syncthreads();
    #pragma unroll
    for (int i = 0; i < 4; i++) {
        int r = ty + i * 8;
        float val = t[tx][r];
        __nv_bfloat16 h = __float2bfloat16(val);
        float res = val - __bfloat162float(h);
        size_t o = (size_t)(n0 + r) * DIM_ + k0 + tx;
        Th[o] = h;
        Tl[o] = __float2bfloat16(res);
    }
}

// ---------------------------------------------------------------------------
__global__ __launch_bounds__(256) void rmsrope_kernel(const float* __restrict__ gq,
                                                      const float* __restrict__ gk) {
    const int gw   = blockIdx.x * 8 + (threadIdx.x >> 5);
    const int lane = threadIdx.x & 31;

    float* row;
    const float* g;
    int tok;
    if (gw < NTOK * NH) {
        tok = gw >> 4;
        int h = gw & 15;
        row = g_q + (size_t)tok * DIM_ + h * HD;
        g   = gq;
    } else {
        int r = gw - NTOK * NH;
        tok = r >> 2;
        int hk = r & 3;
        row = g_kv + (size_t)tok * KVW + hk * HD;
        g   = gk;
    }
    const int pos = tok & (L_ - 1);

    float2 v = ((const float2*)row)[lane];
    float ss = v.x * v.x + v.y * v.y;
    #pragma unroll
    for (int off = 16; off > 0; off >>= 1)
        ss += __shfl_xor_sync(0xffffffffu, ss, off);
    float rn = rsqrtf(ss * (1.0f / 64.0f) + 1e-6f);

    float2 gg = ((const float2*)g)[lane];
    float t1 = v.x * rn * gg.x;
    float t2 = v.y * rn * gg.y;

    float inv_freq = exp2f((float)lane * (-13.287712379549449f / 32.0f));
    float ang = (float)pos * inv_freq;
    float s, c;
    sincosf(ang, &s, &c);

    ((float2*)row)[lane] = make_float2(t1 * c - t2 * s, t1 * s + t2 * c);
}

// ---------------------------------------------------------------------------
// HMMA flash attention. Block = q-tile(64) x 4 heads of one kv group.
// grid: (32 tiles, 8 = b*NKV+hk). 256 threads = 8 warps; warp = (head, m-half).
// S = QK^T via 3-term split-bf16; online softmax on C frags; O = P.V via
// 3-term split. Output written directly as bf16 hi/lo (g_aoh/g_aol).
// ---------------------------------------------------------------------------
#define AP      72                     // smem pitch, b16 units
#define QH_OFF  0
#define QL_OFF  (4*64*AP)              // 18432
#define KH_OFF  (2*QL_OFF)             // 36864
#define KL_OFF  (KH_OFF + 64*AP)
#define VH_OFF  (KL_OFF + 64*AP)
#define VL_OFF  (VH_OFF + 64*AP)
#define P_OFF   (VL_OFF + 64*AP)       // 55296
#define PW_SZ   (32*AP)                // 2304
#define FSMEM   ((P_OFF + 8*PW_SZ)*2)  // 147456 bytes

__global__ __launch_bounds__(256, 1) void fattn_kernel() {
    extern __shared__ __align__(16) __nv_bfloat16 fsm[];

    const int tid   = threadIdx.x;
    const int w     = tid >> 5;
    const int lane  = tid & 31;
    const int t     = blockIdx.x;
    const int bz    = blockIdx.y;
    const int b     = bz >> 2;
    const int hk    = bz & 3;
    const int hl    = w >> 1;            // head within kv group
    const int h     = hk * 4 + hl;
    const int mhalf = w & 1;             // which 32-q half
    const uint32_t smb = smem_u32(fsm);

    // ---- load Q for all 4 heads: scale by 1/8, split into bf16 hi/lo ----
    #pragma unroll
    for (int u = 0; u < 8; u++) {
        int idx = tid + (u << 8);            // 0..2047 chunks of 8
        int hh  = idx >> 9;
        int rem = idx & 511;
        int row = rem >> 3, c8 = (rem & 7) << 3;
        const float* src = g_q + (size_t)(b * L_ + t * 64 + row) * DIM_
                         + (hk * 4 + hh) * 64 + c8;
        float4 v0 = *(const float4*)src, v1 = *(const float4*)(src + 4);
        float f[8] = {v0.x, v0.y, v0.z, v0.w, v1.x, v1.y, v1.z, v1.w};
        uint32_t hi[4], lo[4];
        #pragma unroll
        for (int j = 0; j < 4; j++) {
            float a = f[2*j] * 0.125f, c = f[2*j+1] * 0.125f;
            __nv_bfloat16 ha = __float2bfloat16(a), hc = __float2bfloat16(c);
            hi[j] = pack2(ha, hc);
            lo[j] = pack2(__float2bfloat16(a - __bfloat162float(ha)),
                          __float2bfloat16(c - __bfloat162float(hc)));
        }
        int off = hh * 64 * AP + row * AP + c8;
        *(uint4*)(fsm + QH_OFF + off) = make_uint4(hi[0], hi[1], hi[2], hi[3]);
        *(uint4*)(fsm + QL_OFF + off) = make_uint4(lo[0], lo[1], lo[2], lo[3]);
    }

    float sO[2][8][4];
    #pragma unroll
    for (int i = 0; i < 2; i++)
        #pragma unroll
        for (int j = 0; j < 8; j++)
            #pragma unroll
            for (int r = 0; r < 4; r++) sO[i][j][r] = 0.0f;
    float ms[2][2] = {{-1e30f, -1e30f}, {-1e30f, -1e30f}};
    float ssum[2][2] = {{0.0f, 0.0f}, {0.0f, 0.0f}};

    const uint32_t pw = P_OFF + w * PW_SZ;

    auto do_chunk = [&](int kb, bool partial) {
        __syncthreads();   // previous chunk's V reads complete
        // ---- convert K/V chunk to split bf16 smem ----
        #pragma unroll
        for (int u = 0; u < 2; u++) {
            int c = (tid << 1) + u;          // 0..511
            int row = c >> 3, c8 = (c & 7) << 3;
            const float* base = g_kv + (size_t)(b * L_ + kb + row) * KVW
                              + hk * 64 + c8;
            float4 k0 = *(const float4*)base, k1 = *(const float4*)(base + 4);
            float4 q0 = *(const float4*)(base + 256), q1 = *(const float4*)(base + 260);
            float fk[8] = {k0.x, k0.y, k0.z, k0.w, k1.x, k1.y, k1.z, k1.w};
            float fv[8] = {q0.x, q0.y, q0.z, q0.w, q1.x, q1.y, q1.z, q1.w};
            uint32_t kh[4], kl[4], vh[4], vl[4];
            #pragma unroll
            for (int j = 0; j < 4; j++) {
                float a = fk[2*j], cc = fk[2*j+1];
                __nv_bfloat16 ha = __float2bfloat16(a), hc = __float2bfloat16(cc);
                kh[j] = pack2(ha, hc);
                kl[j] = pack2(__float2bfloat16(a - __bfloat162float(ha)),
                              __float2bfloat16(cc - __bfloat162float(hc)));
                a = fv[2*j]; cc = fv[2*j+1];
                ha = __float2bfloat16(a); hc = __float2bfloat16(cc);
                vh[j] = pack2(ha, hc);
                vl[j] = pack2(__float2bfloat16(a - __bfloat162float(ha)),
                              __float2bfloat16(cc - __bfloat162float(hc)));
            }
            int off = row * AP + c8;
            *(uint4*)(fsm + KH_OFF + off) = make_uint4(kh[0], kh[1], kh[2], kh[3]);
            *(uint4*)(fsm + KL_OFF + off) = make_uint4(kl[0], kl[1], kl[2], kl[3]);
            *(uint4*)(fsm + VH_OFF + off) = make_uint4(vh[0], vh[1], vh[2], vh[3]);
            *(uint4*)(fsm + VL_OFF + off) = make_uint4(vl[0], vl[1], vl[2], vl[3]);
        }
        __syncthreads();

        // ---- S = Q K^T (3-term split) ----
        float sS[2][8][4];
        #pragma unroll
        for (int i = 0; i < 2; i++)
            #pragma unroll
            for (int j = 0; j < 8; j++)
                #pragma unroll
                for (int r = 0; r < 4; r++) sS[i][j][r] = 0.0f;

        #pragma unroll
        for (int kt = 0; kt < 4; kt++) {
            uint32_t ah[2][4], al[2][4], bh[4][4], bl[4][4];
            #pragma unroll
            for (int mt = 0; mt < 2; mt++) {
                uint32_t ao = smb + 2 * (QH_OFF + hl * 64 * AP
                    + (mhalf * 32 + mt * 16 + (lane & 15)) * AP
                    + kt * 16 + ((lane >> 4) << 3));
                ldm4(ah[mt], ao);
                ldm4(al[mt], ao + 2 * QL_OFF);
            }
            #pragma unroll
            for (int pr = 0; pr < 4; pr++) {
                uint32_t bo = smb + 2 * (KH_OFF
                    + (pr * 16 + (lane & 7) + ((lane >> 4) & 1) * 8) * AP
                    + kt * 16 + (((lane >> 3) & 1) << 3));
                ldm4(bh[pr], bo);
                ldm4(bl[pr], bo + 2 * (KL_OFF - KH_OFF));
            }
            #pragma unroll
            for (int mt = 0; mt < 2; mt++)
                #pragma unroll
                for (int nt = 0; nt < 8; nt++) {
                    const uint32_t* f = bh[nt >> 1];
                    mma16816(sS[mt][nt], ah[mt], (nt & 1) ? f[2] : f[0],
                             (nt & 1) ? f[3] : f[1]);
                }
            #pragma unroll
            for (int mt = 0; mt < 2; mt++)
                #pragma unroll
                for (int nt = 0; nt < 8; nt++) {
                    const uint32_t* f = bl[nt >> 1];
                    mma16816(sS[mt][nt], ah[mt], (nt & 1) ? f[2] : f[0],
                             (nt & 1) ? f[3] : f[1]);
                }
            #pragma unroll
            for (int mt = 0; mt < 2; mt++)
                #pragma unroll
                for (int nt = 0; nt < 8; nt++) {
                    const uint32_t* f = bh[nt >> 1];
                    mma16816(sS[mt][nt], al[mt], (nt & 1) ? f[2] : f[0],
                             (nt & 1) ? f[3] : f[1]);
                }
        }

        // ---- mask (partial chunks only) ----
        if (partial) {
            #pragma unroll
            for (int mt = 0; mt < 2; mt++)
                #pragma unroll
                for (int rh = 0; rh < 2; rh++) {
                    int iq = t * 64 + mhalf * 32 + mt * 16 + (lane >> 2) + rh * 8;
                    #pragma unroll
                    for (int nt = 0; nt < 8; nt++)
                        #pragma unroll
                        for (int c = 0; c < 2; c++) {
                            int j = kb + nt * 8 + (lane & 3) * 2 + c;
                            bool valid = (j <= iq) && ((j >= iq - 256) || (j < 64));
                            if (!valid) sS[mt][nt][rh * 2 + c] = -INFINITY;
                        }
                }
        }

        // ---- online softmax on fragments ----
        #pragma unroll
        for (int mt = 0; mt < 2; mt++)
            #pragma unroll
            for (int rh = 0; rh < 2; rh++) {
                float rmax = -INFINITY;
                #pragma unroll
                for (int nt = 0; nt < 8; nt++)
                    rmax = fmaxf(rmax, fmaxf(sS[mt][nt][rh*2], sS[mt][nt][rh*2+1]));
                rmax = fmaxf(rmax, __shfl_xor_sync(0xffffffffu, rmax, 1));
                rmax = fmaxf(rmax, __shfl_xor_sync(0xffffffffu, rmax, 2));
                float mn = fmaxf(ms[mt][rh], rmax);
                float corr = __expf(ms[mt][rh] - mn);
                float rs = 0.0f;
                #pragma unroll
                for (int nt = 0; nt < 8; nt++) {
                    float e0 = __expf(sS[mt][nt][rh*2]     - mn);
                    float e1 = __expf(sS[mt][nt][rh*2 + 1] - mn);
                    sS[mt][nt][rh*2] = e0; sS[mt][nt][rh*2+1] = e1;
                    sO[mt][nt][rh*2]   *= corr;
                    sO[mt][nt][rh*2+1] *= corr;
                    rs += e0 + e1;
                }
                rs += __shfl_xor_sync(0xffffffffu, rs, 1);
                rs += __shfl_xor_sync(0xffffffffu, rs, 2);
                ssum[mt][rh] = ssum[mt][rh] * corr + rs;
                ms[mt][rh] = mn;
            }

        // ---- P (hi) -> smem, PV with Vh and Vl ----
        #pragma unroll
        for (int mt = 0; mt < 2; mt++)
            #pragma unroll
            for (int rh = 0; rh < 2; rh++)
                #pragma unroll
                for (int nt = 0; nt < 8; nt++) {
                    float e0 = sS[mt][nt][rh*2], e1 = sS[mt][nt][rh*2+1];
                    uint32_t pk = pack2(__float2bfloat16(e0), __float2bfloat16(e1));
                    uint32_t off = pw + (mt * 16 + (lane >> 2) + rh * 8) * AP
                                 + nt * 8 + (lane & 3) * 2;
                    *(uint32_t*)((char*)fsm + 2 * off) = pk;
                }
        __syncwarp();
        #pragma unroll
        for (int kt = 0; kt < 4; kt++) {
            uint32_t ap[2][4], vh[4][4], vl[4][4];
            #pragma unroll
            for (int mt = 0; mt < 2; mt++) {
                uint32_t ao = smb + 2 * (pw + (mt * 16 + (lane & 15)) * AP
                                         + kt * 16 + ((lane >> 4) << 3));
                ldm4(ap[mt], ao);
            }
            #pragma unroll
            for (int pr = 0; pr < 4; pr++) {
                uint32_t bo = smb + 2 * (VH_OFF
                    + (kt * 16 + (lane & 7) + ((lane >> 3) & 1) * 8) * AP
                    + pr * 16 + (((lane >> 4) & 1) << 3));
                ldm4t(vh[pr], bo);
                ldm4t(vl[pr], bo + 2 * (VL_OFF - VH_OFF));
            }
            #pragma unroll
            for (int mt = 0; mt < 2; mt++)
                #pragma unroll
                for (int nt = 0; nt < 8; nt++) {
                    const uint32_t* f = vh[nt >> 1];
                    mma16816(sO[mt][nt], ap[mt], (nt & 1) ? f[2] : f[0],
                             (nt & 1) ? f[3] : f[1]);
                }
            #pragma unroll
            for (int mt = 0; mt < 2; mt++)
                #pragma unroll
                for (int nt = 0; nt < 8; nt++) {
                    const uint32_t* f = vl[nt >> 1];
                    mma16816(sO[mt][nt], ap[mt], (nt & 1) ? f[2] : f[0],
                             (nt & 1) ? f[3] : f[1]);
                }
        }
        __syncwarp();
        // ---- P (lo) -> smem, PV with Vh ----
        #pragma unroll
        for (int mt = 0; mt < 2; mt++)
            #pragma unroll
            for (int rh = 0; rh < 2; rh++)
                #pragma unroll
                for (int nt = 0; nt < 8; nt++) {
                    float e0 = sS[mt][nt][rh*2], e1 = sS[mt][nt][rh*2+1];
                    float h0 = __bfloat162float(__float2bfloat16(e0));
                    float h1 = __bfloat162float(__float2bfloat16(e1));
                    uint32_t pk = pack2(__float2bfloat16(e0 - h0),
                                        __float2bfloat16(e1 - h1));
                    uint32_t off = pw + (mt * 16 + (lane >> 2) + rh * 8) * AP
                                 + nt * 8 + (lane & 3) * 2;
                    *(uint32_t*)((char*)fsm + 2 * off) = pk;
                }
        __syncwarp();
        #pragma unroll
        for (int kt = 0; kt < 4; kt++) {
            uint32_t ap[2][4], vh[4][4];
            #pragma unroll
            for (int mt = 0; mt < 2; mt++) {
                uint32_t ao = smb + 2 * (pw + (mt * 16 + (lane & 15)) * AP
                                         + kt * 16 + ((lane >> 4) << 3));
                ldm4(ap[mt], ao);
            }
            #pragma unroll
            for (int pr = 0; pr < 4; pr++) {
                uint32_t bo = smb + 2 * (VH_OFF
                    + (kt * 16 + (lane & 7) + ((lane >> 3) & 1) * 8) * AP
                    + pr * 16 + (((lane >> 4) & 1) << 3));
                ldm4t(vh[pr], bo);
            }
            #pragma unroll
            for (int mt = 0; mt < 2; mt++)
                #pragma unroll
                for (int nt = 0; nt < 8; nt++) {
                    const uint32_t* f = vh[nt >> 1];
                    mma16816(sO[mt][nt], ap[mt], (nt & 1) ? f[2] : f[0],
                             (nt & 1) ? f[3] : f[1]);
                }
        }
    };

    // chunk schedule
    if (t > 4) do_chunk(0, false);
    int c0 = t - 4; if (c0 < 0) c0 = 0;
    for (int cc = c0; cc <= t; cc++) {
        bool partial = (cc == t) || (t >= 5 && cc == t - 4);
        do_chunk(cc * 64, partial);
    }

    // ---- epilogue: normalize, write bf16 hi/lo directly ----
    #pragma unroll
    for (int mt = 0; mt < 2; mt++)
        #pragma unroll
        for (int rh = 0; rh < 2; rh++) {
            float inv = 1.0f / ssum[mt][rh];
            int tok = b * L_ + t * 64 + mhalf * 32 + mt * 16 + (lane >> 2) + rh * 8;
            #pragma unroll
            for (int nt = 0; nt < 8; nt++) {
                float v0 = sO[mt][nt][rh*2]     * inv;
                float v1 = sO[mt][nt][rh*2 + 1] * inv;
                __nv_bfloat16 h0 = __float2bfloat16(v0);
                __nv_bfloat16 h1 = __float2bfloat16(v1);
                size_t o = (size_t)tok * DIM_ + h * 64 + nt * 8 + (lane & 3) * 2;
                *(uint32_t*)&g_aoh[o] = pack2(h0, h1);
                *(uint32_t*)&g_aol[o] =
                    pack2(__float2bfloat16(v0 - __bfloat162float(h0)),
                          __float2bfloat16(v1 - __bfloat162float(h1)));
            }
        }
}

// ---------------------------------------------------------------------------
extern "C" void kernel_launch(void* const* d_in, const int* in_sizes, int n_in,
                              void* d_out, int out_size) {
    const float* x  = (const float*)d_in[0];
    const float* wq = (const float*)d_in[1];
    const float* wk = (const float*)d_in[2];
    const float* wv = (const float*)d_in[3];
    const float* wo = (const float*)d_in[4];
    const float* gq = (const float*)d_in[5];
    const float* gk = (const float*)d_in[6];

    float *q, *kv;
    __nv_bfloat16 *xh, *xl, *aoh, *aol, *wqth, *wqtl, *wkvth, *wkvtl, *woth, *wotl;
    cudaGetSymbolAddress((void**)&q,    g_q);
    cudaGetSymbolAddress((void**)&kv,   g_kv);
    cudaGetSymbolAddress((void**)&xh,   g_xh);
    cudaGetSymbolAddress((void**)&xl,   g_xl);
    cudaGetSymbolAddress((void**)&aoh,  g_aoh);
    cudaGetSymbolAddress((void**)&aol,  g_aol);
    cudaGetSymbolAddress((void**)&wqth, g_wqt_h);
    cudaGetSymbolAddress((void**)&wqtl, g_wqt_l);
    cudaGetSymbolAddress((void**)&wkvth,g_wkvt_h);
    cudaGetSymbolAddress((void**)&wkvtl,g_wkvt_l);
    cudaGetSymbolAddress((void**)&woth, g_wot_h);
    cudaGetSymbolAddress((void**)&wotl, g_wot_l);

    cudaFuncSetAttribute(hmma_gemm, cudaFuncAttributeMaxDynamicSharedMemorySize,
                         GSMEM);
    cudaFuncSetAttribute(fattn_kernel, cudaFuncAttributeMaxDynamicSharedMemorySize,
                         FSMEM);

    // input splits / weight transposes
    split4<<<NTOK * DIM_ / 1024, 256>>>(x, xh, xl);
    wtrans<<<dim3(DIM_ / 32, 32), dim3(32, 8)>>>(wq, wqth, wqtl, DIM_);
    wtrans<<<dim3(256 / 32, 32), dim3(32, 8)>>>(wk, wkvth, wkvtl, 256);
    wtrans<<<dim3(256 / 32, 32), dim3(32, 8)>>>(wv, wkvth + 256 * DIM_,
                                                wkvtl + 256 * DIM_, 256);
    wtrans<<<dim3(DIM_ / 32, 32), dim3(32, 8)>>>(wo, woth, wotl, DIM_);

    // projections via HMMA split-bf16 GEMM
    hmma_gemm<<<dim3(DIM_ / 128, NTOK / 128), 256, GSMEM>>>(xh, xl, wqth, wqtl, q, DIM_);
    hmma_gemm<<<dim3(KVW  / 128, NTOK / 128), 256, GSMEM>>>(xh, xl, wkvth, wkvtl, kv, KVW);

    // RMSNorm + RoPE (q and k in place)
    const int nrows = NTOK * NH + NTOK * NKV;
    rmsrope_kernel<<<nrows / 8, 256>>>(gq, gk);

    // flash attention (writes g_aoh/g_aol directly)
    fattn_kernel<<<dim3(32, 8), 256, FSMEM>>>();

    // output projection
    hmma_gemm<<<dim3(DIM_ / 128, NTOK / 128), 256, GSMEM>>>(aoh, aol, woth, wotl,
                                                            (float*)d_out, DIM_);
}

// round 12
// speedup vs baseline: 2.6203x; 1.0287x over previous
#include <cuda_runtime.h>
#include <cuda_bf16.h>
#include <cstdint>
#include <math.h>

#define B_    2
#define L_    2048
#define DIM_  1024
#define NH    16
#define NKV   4
#define HD    64
#define NTOK  (B_*L_)       // 4096
#define QKVW  1536          // fused q|k|v row width

typedef unsigned long long u64;

// ------------------------- scratch (__device__, no mallocs) -----------------
__device__ __align__(16) float g_qkv[NTOK*QKVW];   // Q(0..1023)|K(1024..1279)|V(1280..1535)

__device__ __align__(16) __nv_bfloat16 g_xh [NTOK*DIM_];
__device__ __align__(16) __nv_bfloat16 g_xl [NTOK*DIM_];
__device__ __align__(16) __nv_bfloat16 g_aoh[NTOK*DIM_];
__device__ __align__(16) __nv_bfloat16 g_aol[NTOK*DIM_];

__device__ __align__(16) __nv_bfloat16 g_wt_h [QKVW*DIM_];  // [n][k] fused wq|wk|wv
__device__ __align__(16) __nv_bfloat16 g_wt_l [QKVW*DIM_];
__device__ __align__(16) __nv_bfloat16 g_wot_h[DIM_*DIM_];
__device__ __align__(16) __nv_bfloat16 g_wot_l[DIM_*DIM_];

// ------------------------- helpers ------------------------------------------
__device__ __forceinline__ uint32_t smem_u32(const void* p) {
    uint32_t a;
    asm("{ .reg .u64 t; cvta.to.shared.u64 t, %1; cvt.u32.u64 %0, t; }"
        : "=r"(a) : "l"(p));
    return a;
}
__device__ __forceinline__ void ldm4(uint32_t f[4], uint32_t addr) {
    asm volatile("ldmatrix.sync.aligned.m8n8.x4.shared.b16 {%0,%1,%2,%3}, [%4];"
                 : "=r"(f[0]), "=r"(f[1]), "=r"(f[2]), "=r"(f[3]) : "r"(addr));
}
__device__ __forceinline__ void ldm4t(uint32_t f[4], uint32_t addr) {
    asm volatile("ldmatrix.sync.aligned.m8n8.x4.trans.shared.b16 {%0,%1,%2,%3}, [%4];"
                 : "=r"(f[0]), "=r"(f[1]), "=r"(f[2]), "=r"(f[3]) : "r"(addr));
}
__device__ __forceinline__ void mma16816(float c[4], const uint32_t a[4],
                                         uint32_t b0, uint32_t b1) {
    asm volatile("mma.sync.aligned.m16n8k16.row.col.f32.bf16.bf16.f32 "
                 "{%0,%1,%2,%3},{%4,%5,%6,%7},{%8,%9},{%0,%1,%2,%3};"
                 : "+f"(c[0]), "+f"(c[1]), "+f"(c[2]), "+f"(c[3])
                 : "r"(a[0]), "r"(a[1]), "r"(a[2]), "r"(a[3]), "r"(b0), "r"(b1));
}
__device__ __forceinline__ uint32_t pack2(__nv_bfloat16 a, __nv_bfloat16 b) {
    return (uint32_t)__bfloat16_as_ushort(a) |
           ((uint32_t)__bfloat16_as_ushort(b) << 16);
}
__device__ __forceinline__ void cp16(uint32_t saddr, const void* gptr) {
    asm volatile("cp.async.cg.shared.global [%0], [%1], 16;"
                 :: "r"(saddr), "l"(gptr));
}
#define CP_COMMIT() asm volatile("cp.async.commit_group;" ::: "memory")
#define CP_WAIT(n)  asm volatile("cp.async.wait_group %0;" :: "n"(n) : "memory")

// ---------------------------------------------------------------------------
// HMMA split-bf16 GEMM, cp.async 3-stage pipeline.
// C[4096][Ncols] = A @ B^T via AhBh + AhBl + AlBh (fp32 accum).
// Block 128x128, BK=32, 256 threads (8 warps 4x2), warp tile 32x64.
// ---------------------------------------------------------------------------
#define PITCH     40
#define TILE_B16  (128*PITCH)
#define TILE_BY   (TILE_B16*2)
#define BUF_B16   (4*TILE_B16)
#define BUF_BY    (BUF_B16*2)          // 40960 bytes/stage
#define GSMEM     (3*BUF_BY)           // 122880 bytes
#define NKB       (DIM_/32)            // 32

__global__ __launch_bounds__(256) void hmma_gemm(const __nv_bfloat16* __restrict__ Ah_,
                                                 const __nv_bfloat16* __restrict__ Al_,
                                                 const __nv_bfloat16* __restrict__ Bh_,
                                                 const __nv_bfloat16* __restrict__ Bl_,
                                                 float* __restrict__ C, int Ncols) {
    extern __shared__ __align__(128) __nv_bfloat16 sm[];

    const int tid  = threadIdx.x;
    const int wid  = tid >> 5;
    const int lane = tid & 31;
    const int wm   = (wid & 3) * 32;
    const int wn   = (wid >> 2) * 64;
    const int m0   = blockIdx.y * 128;
    const int n0   = blockIdx.x * 128;

    const uint32_t smb = smem_u32(sm);

    uint32_t aoff[2], boff[4];
    #pragma unroll
    for (int mt = 0; mt < 2; mt++)
        aoff[mt] = ((wm + mt * 16 + (lane & 15)) * PITCH + ((lane >> 4) << 3)) * 2;
    #pragma unroll
    for (int pr = 0; pr < 4; pr++)
        boff[pr] = ((wn + pr * 16 + (lane & 7) + ((lane >> 4) & 1) * 8) * PITCH
                    + (((lane >> 3) & 1) << 3)) * 2;

    float acc[2][8][4];
    #pragma unroll
    for (int i = 0; i < 2; i++)
        #pragma unroll
        for (int j = 0; j < 8; j++)
            #pragma unroll
            for (int r = 0; r < 4; r++) acc[i][j][r] = 0.0f;

    // per-thread staging coordinates (2 chunks of 16B per array per stage)
    const int r0  = (tid * 2)     >> 2, c80 = ((tid * 2)     & 3) << 3;
    const int r1  = (tid * 2 + 1) >> 2, c81 = ((tid * 2 + 1) & 3) << 3;
    const uint32_t so0 = (r0 * PITCH + c80) * 2;
    const uint32_t so1 = (r1 * PITCH + c81) * 2;

    auto stage = [&](int kb, int buf) {
        const int k0 = kb << 5;
        const uint32_t sb = smb + buf * BUF_BY;
        size_t goA0 = (size_t)(m0 + r0) * DIM_ + k0 + c80;
        size_t goB0 = (size_t)(n0 + r0) * DIM_ + k0 + c80;
        size_t goA1 = (size_t)(m0 + r1) * DIM_ + k0 + c81;
        size_t goB1 = (size_t)(n0 + r1) * DIM_ + k0 + c81;
        cp16(sb + so0,               Ah_ + goA0);
        cp16(sb + TILE_BY + so0,     Al_ + goA0);
        cp16(sb + 2 * TILE_BY + so0, Bh_ + goB0);
        cp16(sb + 3 * TILE_BY + so0, Bl_ + goB0);
        cp16(sb + so1,               Ah_ + goA1);
        cp16(sb + TILE_BY + so1,     Al_ + goA1);
        cp16(sb + 2 * TILE_BY + so1, Bh_ + goB1);
        cp16(sb + 3 * TILE_BY + so1, Bl_ + goB1);
        CP_COMMIT();
    };

    stage(0, 0);
    stage(1, 1);

    int buf = 0;
    #pragma unroll 1
    for (int kb = 0; kb < NKB; kb++) {
        if (kb + 1 < NKB) CP_WAIT(1); else CP_WAIT(0);
        __syncthreads();

        const uint32_t sb = smb + buf * BUF_BY;
        #pragma unroll
        for (int ks = 0; ks < 2; ks++) {
            uint32_t ah[2][4], al[2][4], bh[4][4], bl[4][4];
            #pragma unroll
            for (int mt = 0; mt < 2; mt++) {
                uint32_t ao = sb + aoff[mt] + ks * 32;
                ldm4(ah[mt], ao);
                ldm4(al[mt], ao + TILE_BY);
            }
            #pragma unroll
            for (int pr = 0; pr < 4; pr++) {
                uint32_t bo = sb + boff[pr] + ks * 32;
                ldm4(bh[pr], bo + 2 * TILE_BY);
                ldm4(bl[pr], bo + 3 * TILE_BY);
            }
            #pragma unroll
            for (int mt = 0; mt < 2; mt++)
                #pragma unroll
                for (int nt = 0; nt < 8; nt++) {
                    const uint32_t* f = bh[nt >> 1];
                    mma16816(acc[mt][nt], ah[mt], (nt & 1) ? f[2] : f[0],
                             (nt & 1) ? f[3] : f[1]);
                }
            #pragma unroll
            for (int mt = 0; mt < 2; mt++)
                #pragma unroll
                for (int nt = 0; nt < 8; nt++) {
                    const uint32_t* f = bl[nt >> 1];
                    mma16816(acc[mt][nt], ah[mt], (nt & 1) ? f[2] : f[0],
                             (nt & 1) ? f[3] : f[1]);
                }
            #pragma unroll
            for (int mt = 0; mt < 2; mt++)
                #pragma unroll
                for (int nt = 0; nt < 8; nt++) {
                    const uint32_t* f = bh[nt >> 1];
                    mma16816(acc[mt][nt], al[mt], (nt & 1) ? f[2] : f[0],
                             (nt & 1) ? f[3] : f[1]);
                }
        }
        __syncthreads();
        if (kb + 2 < NKB) stage(kb + 2, (kb + 2) % 3);
        buf = (buf + 1 == 3) ? 0 : buf + 1;
    }

    #pragma unroll
    for (int mt = 0; mt < 2; mt++) {
        const int row = m0 + wm + mt * 16 + (lane >> 2);
        #pragma unroll
        for (int nt = 0; nt < 8; nt++) {
            const int col = n0 + wn + nt * 8 + (lane & 3) * 2;
            float2 lo; lo.x = acc[mt][nt][0]; lo.y = acc[mt][nt][1];
            float2 hi; hi.x = acc[mt][nt][2]; hi.y = acc[mt][nt][3];
            *(float2*)&C[(size_t)row * Ncols + col]       = lo;
            *(float2*)&C[(size_t)(row + 8) * Ncols + col] = hi;
        }
    }
}

// ---------------------------------------------------------------------------
__global__ __launch_bounds__(256) void split4(const float* __restrict__ src,
                                              __nv_bfloat16* __restrict__ hi,
                                              __nv_bfloat16* __restrict__ lo) {
    size_t i = ((size_t)blockIdx.x * 256 + threadIdx.x) * 4;
    float4 v = *(const float4*)(src + i);
    float vv[4] = {v.x, v.y, v.z, v.w};
    ushort4 H, Lo;
    unsigned short* hp = &H.x;
    unsigned short* lp = &Lo.x;
    #pragma unroll
    for (int j = 0; j < 4; j++) {
        __nv_bfloat16 h = __float2bfloat16(vv[j]);
        float res = vv[j] - __bfloat162float(h);
        hp[j] = __bfloat16_as_ushort(h);
        lp[j] = __bfloat16_as_ushort(__float2bfloat16(res));
    }
    *(ushort4*)(hi + i) = H;
    *(ushort4*)(lo + i) = Lo;
}

// ---------------------------------------------------------------------------
__global__ void wtrans(const float* __restrict__ W,
                       __nv_bfloat16* __restrict__ Th,
                       __nv_bfloat16* __restrict__ Tl, int N) {
    __shared__ float t[32][33];
    const int tx = threadIdx.x, ty = threadIdx.y;
    const int n0 = blockIdx.x * 32, k0 = blockIdx.y * 32;
    #pragma unroll
    for (int i = 0; i < 4; i++) {
        int r = ty + i * 8;
        t[r][tx] = W[(size_t)(k0 + r) * N + n0 + tx];
    }
    __syncthreads();
    #pragma unroll
    for (int i = 0; i < 4; i++) {
        int r = ty + i * 8;
        float val = t[tx][r];
        __nv_bfloat16 h = __float2bfloat16(val);
        float res = val - __bfloat162float(h);
        size_t o = (size_t)(n0 + r) * DIM_ + k0 + tx;
        Th[o] = h;
        Tl[o] = __float2bfloat16(res);
    }
}

// ---------------------------------------------------------------------------
// RMSNorm + RoPE in place on fused g_qkv (Q cols 0..1023, K cols 1024..1279).
// ---------------------------------------------------------------------------
__global__ __launch_bounds__(256) void rmsrope_kernel(const float* __restrict__ gq,
                                                      const float* __restrict__ gk) {
    const int gw   = blockIdx.x * 8 + (threadIdx.x >> 5);
    const int lane = threadIdx.x & 31;

    float* row;
    const float* g;
    int tok;
    if (gw < NTOK * NH) {
        tok = gw >> 4;
        int h = gw & 15;
        row = g_qkv + (size_t)tok * QKVW + h * HD;
        g   = gq;
    } else {
        int r = gw - NTOK * NH;
        tok = r >> 2;
        int hk = r & 3;
        row = g_qkv + (size_t)tok * QKVW + 1024 + hk * HD;
        g   = gk;
    }
    const int pos = tok & (L_ - 1);

    float2 v = ((const float2*)row)[lane];
    float ss = v.x * v.x + v.y * v.y;
    #pragma unroll
    for (int off = 16; off > 0; off >>= 1)
        ss += __shfl_xor_sync(0xffffffffu, ss, off);
    float rn = rsqrtf(ss * (1.0f / 64.0f) + 1e-6f);

    float2 gg = ((const float2*)g)[lane];
    float t1 = v.x * rn * gg.x;
    float t2 = v.y * rn * gg.y;

    float inv_freq = exp2f((float)lane * (-13.287712379549449f / 32.0f));
    float ang = (float)pos * inv_freq;
    float s, c;
    sincosf(ang, &s, &c);

    ((float2*)row)[lane] = make_float2(t1 * c - t2 * s, t1 * s + t2 * c);
}

// ---------------------------------------------------------------------------
// HMMA flash attention (proven R10 kernel, strides updated to fused g_qkv).
// ---------------------------------------------------------------------------
#define AP      72
#define QH_OFF  0
#define QL_OFF  (4*64*AP)
#define KH_OFF  (2*QL_OFF)
#define KL_OFF  (KH_OFF + 64*AP)
#define VH_OFF  (KL_OFF + 64*AP)
#define VL_OFF  (VH_OFF + 64*AP)
#define P_OFF   (VL_OFF + 64*AP)
#define PW_SZ   (32*AP)
#define FSMEM   ((P_OFF + 8*PW_SZ)*2)

__global__ __launch_bounds__(256, 1) void fattn_kernel() {
    extern __shared__ __align__(16) __nv_bfloat16 fsm[];

    const int tid   = threadIdx.x;
    const int w     = tid >> 5;
    const int lane  = tid & 31;
    const int t     = blockIdx.x;
    const int bz    = blockIdx.y;
    const int b     = bz >> 2;
    const int hk    = bz & 3;
    const int hl    = w >> 1;
    const int h     = hk * 4 + hl;
    const int mhalf = w & 1;
    const uint32_t smb = smem_u32(fsm);

    #pragma unroll
    for (int u = 0; u < 8; u++) {
        int idx = tid + (u << 8);
        int hh  = idx >> 9;
        int rem = idx & 511;
        int row = rem >> 3, c8 = (rem & 7) << 3;
        const float* src = g_qkv + (size_t)(b * L_ + t * 64 + row) * QKVW
                         + (hk * 4 + hh) * 64 + c8;
        float4 v0 = *(const float4*)src, v1 = *(const float4*)(src + 4);
        float f[8] = {v0.x, v0.y, v0.z, v0.w, v1.x, v1.y, v1.z, v1.w};
        uint32_t hi[4], lo[4];
        #pragma unroll
        for (int j = 0; j < 4; j++) {
            float a = f[2*j] * 0.125f, c = f[2*j+1] * 0.125f;
            __nv_bfloat16 ha = __float2bfloat16(a), hc = __float2bfloat16(c);
            hi[j] = pack2(ha, hc);
            lo[j] = pack2(__float2bfloat16(a - __bfloat162float(ha)),
                          __float2bfloat16(c - __bfloat162float(hc)));
        }
        int off = hh * 64 * AP + row * AP + c8;
        *(uint4*)(fsm + QH_OFF + off) = make_uint4(hi[0], hi[1], hi[2], hi[3]);
        *(uint4*)(fsm + QL_OFF + off) = make_uint4(lo[0], lo[1], lo[2], lo[3]);
    }

    float sO[2][8][4];
    #pragma unroll
    for (int i = 0; i < 2; i++)
        #pragma unroll
        for (int j = 0; j < 8; j++)
            #pragma unroll
            for (int r = 0; r < 4; r++) sO[i][j][r] = 0.0f;
    float ms[2][2] = {{-1e30f, -1e30f}, {-1e30f, -1e30f}};
    float ssum[2][2] = {{0.0f, 0.0f}, {0.0f, 0.0f}};

    const uint32_t pw = P_OFF + w * PW_SZ;

    auto do_chunk = [&](int kb, bool partial) {
        __syncthreads();
        #pragma unroll
        for (int u = 0; u < 2; u++) {
            int c = (tid << 1) + u;
            int row = c >> 3, c8 = (c & 7) << 3;
            const float* base = g_qkv + (size_t)(b * L_ + kb + row) * QKVW
                              + 1024 + hk * 64 + c8;
            float4 k0 = *(const float4*)base, k1 = *(const float4*)(base + 4);
            float4 q0 = *(const float4*)(base + 256), q1 = *(const float4*)(base + 260);
            float fk[8] = {k0.x, k0.y, k0.z, k0.w, k1.x, k1.y, k1.z, k1.w};
            float fv[8] = {q0.x, q0.y, q0.z, q0.w, q1.x, q1.y, q1.z, q1.w};
            uint32_t kh[4], kl[4], vh[4], vl[4];
            #pragma unroll
            for (int j = 0; j < 4; j++) {
                float a = fk[2*j], cc = fk[2*j+1];
                __nv_bfloat16 ha = __float2bfloat16(a), hc = __float2bfloat16(cc);
                kh[j] = pack2(ha, hc);
                kl[j] = pack2(__float2bfloat16(a - __bfloat162float(ha)),
                              __float2bfloat16(cc - __bfloat162float(hc)));
                a = fv[2*j]; cc = fv[2*j+1];
                ha = __float2bfloat16(a); hc = __float2bfloat16(cc);
                vh[j] = pack2(ha, hc);
                vl[j] = pack2(__float2bfloat16(a - __bfloat162float(ha)),
                              __float2bfloat16(cc - __bfloat162float(hc)));
            }
            int off = row * AP + c8;
            *(uint4*)(fsm + KH_OFF + off) = make_uint4(kh[0], kh[1], kh[2], kh[3]);
            *(uint4*)(fsm + KL_OFF + off) = make_uint4(kl[0], kl[1], kl[2], kl[3]);
            *(uint4*)(fsm + VH_OFF + off) = make_uint4(vh[0], vh[1], vh[2], vh[3]);
            *(uint4*)(fsm + VL_OFF + off) = make_uint4(vl[0], vl[1], vl[2], vl[3]);
        }
        __syncthreads();

        float sS[2][8][4];
        #pragma unroll
        for (int i = 0; i < 2; i++)
            #pragma unroll
            for (int j = 0; j < 8; j++)
                #pragma unroll
                for (int r = 0; r < 4; r++) sS[i][j][r] = 0.0f;

        #pragma unroll
        for (int kt = 0; kt < 4; kt++) {
            uint32_t ah[2][4], al[2][4], bh[4][4], bl[4][4];
            #pragma unroll
            for (int mt = 0; mt < 2; mt++) {
                uint32_t ao = smb + 2 * (QH_OFF + hl * 64 * AP
                    + (mhalf * 32 + mt * 16 + (lane & 15)) * AP
                    + kt * 16 + ((lane >> 4) << 3));
                ldm4(ah[mt], ao);
                ldm4(al[mt], ao + 2 * QL_OFF);
            }
            #pragma unroll
            for (int pr = 0; pr < 4; pr++) {
                uint32_t bo = smb + 2 * (KH_OFF
                    + (pr * 16 + (lane & 7) + ((lane >> 4) & 1) * 8) * AP
                    + kt * 16 + (((lane >> 3) & 1) << 3));
                ldm4(bh[pr], bo);
                ldm4(bl[pr], bo + 2 * (KL_OFF - KH_OFF));
            }
            #pragma unroll
            for (int mt = 0; mt < 2; mt++)
                #pragma unroll
                for (int nt = 0; nt < 8; nt++) {
                    const uint32_t* f = bh[nt >> 1];
                    mma16816(sS[mt][nt], ah[mt], (nt & 1) ? f[2] : f[0],
                             (nt & 1) ? f[3] : f[1]);
                }
            #pragma unroll
            for (int mt = 0; mt < 2; mt++)
                #pragma unroll
                for (int nt = 0; nt < 8; nt++) {
                    const uint32_t* f = bl[nt >> 1];
                    mma16816(sS[mt][nt], ah[mt], (nt & 1) ? f[2] : f[0],
                             (nt & 1) ? f[3] : f[1]);
                }
            #pragma unroll
            for (int mt = 0; mt < 2; mt++)
                #pragma unroll
                for (int nt = 0; nt < 8; nt++) {
                    const uint32_t* f = bh[nt >> 1];
                    mma16816(sS[mt][nt], al[mt], (nt & 1) ? f[2] : f[0],
                             (nt & 1) ? f[3] : f[1]);
                }
        }

        if (partial) {
            #pragma unroll
            for (int mt = 0; mt < 2; mt++)
                #pragma unroll
                for (int rh = 0; rh < 2; rh++) {
                    int iq = t * 64 + mhalf * 32 + mt * 16 + (lane >> 2) + rh * 8;
                    #pragma unroll
                    for (int nt = 0; nt < 8; nt++)
                        #pragma unroll
                        for (int c = 0; c < 2; c++) {
                            int j = kb + nt * 8 + (lane & 3) * 2 + c;
                            bool valid = (j <= iq) && ((j >= iq - 256) || (j < 64));
                            if (!valid) sS[mt][nt][rh * 2 + c] = -INFINITY;
                        }
                }
        }

        #pragma unroll
        for (int mt = 0; mt < 2; mt++)
            #pragma unroll
            for (int rh = 0; rh < 2; rh++) {
                float rmax = -INFINITY;
                #pragma unroll
                for (int nt = 0; nt < 8; nt++)
                    rmax = fmaxf(rmax, fmaxf(sS[mt][nt][rh*2], sS[mt][nt][rh*2+1]));
                rmax = fmaxf(rmax, __shfl_xor_sync(0xffffffffu, rmax, 1));
                rmax = fmaxf(rmax, __shfl_xor_sync(0xffffffffu, rmax, 2));
                float mn = fmaxf(ms[mt][rh], rmax);
                float corr = __expf(ms[mt][rh] - mn);
                float rs = 0.0f;
                #pragma unroll
                for (int nt = 0; nt < 8; nt++) {
                    float e0 = __expf(sS[mt][nt][rh*2]     - mn);
                    float e1 = __expf(sS[mt][nt][rh*2 + 1] - mn);
                    sS[mt][nt][rh*2] = e0; sS[mt][nt][rh*2+1] = e1;
                    sO[mt][nt][rh*2]   *= corr;
                    sO[mt][nt][rh*2+1] *= corr;
                    rs += e0 + e1;
                }
                rs += __shfl_xor_sync(0xffffffffu, rs, 1);
                rs += __shfl_xor_sync(0xffffffffu, rs, 2);
                ssum[mt][rh] = ssum[mt][rh] * corr + rs;
                ms[mt][rh] = mn;
            }

        #pragma unroll
        for (int mt = 0; mt < 2; mt++)
            #pragma unroll
            for (int rh = 0; rh < 2; rh++)
                #pragma unroll
                for (int nt = 0; nt < 8; nt++) {
                    float e0 = sS[mt][nt][rh*2], e1 = sS[mt][nt][rh*2+1];
                    uint32_t pk = pack2(__float2bfloat16(e0), __float2bfloat16(e1));
                    uint32_t off = pw + (mt * 16 + (lane >> 2) + rh * 8) * AP
                                 + nt * 8 + (lane & 3) * 2;
                    *(uint32_t*)((char*)fsm + 2 * off) = pk;
                }
        __syncwarp();
        #pragma unroll
        for (int kt = 0; kt < 4; kt++) {
            uint32_t ap[2][4], vh[4][4], vl[4][4];
            #pragma unroll
            for (int mt = 0; mt < 2; mt++) {
                uint32_t ao = smb + 2 * (pw + (mt * 16 + (lane & 15)) * AP
                                         + kt * 16 + ((lane >> 4) << 3));
                ldm4(ap[mt], ao);
            }
            #pragma unroll
            for (int pr = 0; pr < 4; pr++) {
                uint32_t bo = smb + 2 * (VH_OFF
                    + (kt * 16 + (lane & 7) + ((lane >> 3) & 1) * 8) * AP
                    + pr * 16 + (((lane >> 4) & 1) << 3));
                ldm4t(vh[pr], bo);
                ldm4t(vl[pr], bo + 2 * (VL_OFF - VH_OFF));
            }
            #pragma unroll
            for (int mt = 0; mt < 2; mt++)
                #pragma unroll
                for (int nt = 0; nt < 8; nt++) {
                    const uint32_t* f = vh[nt >> 1];
                    mma16816(sO[mt][nt], ap[mt], (nt & 1) ? f[2] : f[0],
                             (nt & 1) ? f[3] : f[1]);
                }
            #pragma unroll
            for (int mt = 0; mt < 2; mt++)
                #pragma unroll
                for (int nt = 0; nt < 8; nt++) {
                    const uint32_t* f = vl[nt >> 1];
                    mma16816(sO[mt][nt], ap[mt], (nt & 1) ? f[2] : f[0],
                             (nt & 1) ? f[3] : f[1]);
                }
        }
        __syncwarp();
        #pragma unroll
        for (int mt = 0; mt < 2; mt++)
            #pragma unroll
            for (int rh = 0; rh < 2; rh++)
                #pragma unroll
                for (int nt = 0; nt < 8; nt++) {
                    float e0 = sS[mt][nt][rh*2], e1 = sS[mt][nt][rh*2+1];
                    float h0 = __bfloat162float(__float2bfloat16(e0));
                    float h1 = __bfloat162float(__float2bfloat16(e1));
                    uint32_t pk = pack2(__float2bfloat16(e0 - h0),
                                        __float2bfloat16(e1 - h1));
                    uint32_t off = pw + (mt * 16 + (lane >> 2) + rh * 8) * AP
                                 + nt * 8 + (lane & 3) * 2;
                    *(uint32_t*)((char*)fsm + 2 * off) = pk;
                }
        __syncwarp();
        #pragma unroll
        for (int kt = 0; kt < 4; kt++) {
            uint32_t ap[2][4], vh[4][4];
            #pragma unroll
            for (int mt = 0; mt < 2; mt++) {
                uint32_t ao = smb + 2 * (pw + (mt * 16 + (lane & 15)) * AP
                                         + kt * 16 + ((lane >> 4) << 3));
                ldm4(ap[mt], ao);
            }
            #pragma unroll
            for (int pr = 0; pr < 4; pr++) {
                uint32_t bo = smb + 2 * (VH_OFF
                    + (kt * 16 + (lane & 7) + ((lane >> 3) & 1) * 8) * AP
                    + pr * 16 + (((lane >> 4) & 1) << 3));
                ldm4t(vh[pr], bo);
            }
            #pragma unroll
            for (int mt = 0; mt < 2; mt++)
                #pragma unroll
                for (int nt = 0; nt < 8; nt++) {
                    const uint32_t* f = vh[nt >> 1];
                    mma16816(sO[mt][nt], ap[mt], (nt & 1) ? f[2] : f[0],
                             (nt & 1) ? f[3] : f[1]);
                }
        }
    };

    if (t > 4) do_chunk(0, false);
    int c0 = t - 4; if (c0 < 0) c0 = 0;
    for (int cc = c0; cc <= t; cc++) {
        bool partial = (cc == t) || (t >= 5 && cc == t - 4);
        do_chunk(cc * 64, partial);
    }

    #pragma unroll
    for (int mt = 0; mt < 2; mt++)
        #pragma unroll
        for (int rh = 0; rh < 2; rh++) {
            float inv = 1.0f / ssum[mt][rh];
            int tok = b * L_ + t * 64 + mhalf * 32 + mt * 16 + (lane >> 2) + rh * 8;
            #pragma unroll
            for (int nt = 0; nt < 8; nt++) {
                float v0 = sO[mt][nt][rh*2]     * inv;
                float v1 = sO[mt][nt][rh*2 + 1] * inv;
                __nv_bfloat16 h0 = __float2bfloat16(v0);
                __nv_bfloat16 h1 = __float2bfloat16(v1);
                size_t o = (size_t)tok * DIM_ + h * 64 + nt * 8 + (lane & 3) * 2;
                *(uint32_t*)&g_aoh[o] = pack2(h0, h1);
                *(uint32_t*)&g_aol[o] =
                    pack2(__float2bfloat16(v0 - __bfloat162float(h0)),
                          __float2bfloat16(v1 - __bfloat162float(h1)));
            }
        }
}

// ---------------------------------------------------------------------------
extern "C" void kernel_launch(void* const* d_in, const int* in_sizes, int n_in,
                              void* d_out, int out_size) {
    const float* x  = (const float*)d_in[0];
    const float* wq = (const float*)d_in[1];
    const float* wk = (const float*)d_in[2];
    const float* wv = (const float*)d_in[3];
    const float* wo = (const float*)d_in[4];
    const float* gq = (const float*)d_in[5];
    const float* gk = (const float*)d_in[6];

    float *qkv;
    __nv_bfloat16 *xh, *xl, *aoh, *aol, *wth, *wtl, *woth, *wotl;
    cudaGetSymbolAddress((void**)&qkv,  g_qkv);
    cudaGetSymbolAddress((void**)&xh,   g_xh);
    cudaGetSymbolAddress((void**)&xl,   g_xl);
    cudaGetSymbolAddress((void**)&aoh,  g_aoh);
    cudaGetSymbolAddress((void**)&aol,  g_aol);
    cudaGetSymbolAddress((void**)&wth,  g_wt_h);
    cudaGetSymbolAddress((void**)&wtl,  g_wt_l);
    cudaGetSymbolAddress((void**)&woth, g_wot_h);
    cudaGetSymbolAddress((void**)&wotl, g_wot_l);

    cudaFuncSetAttribute(hmma_gemm, cudaFuncAttributeMaxDynamicSharedMemorySize,
                         GSMEM);
    cudaFuncSetAttribute(fattn_kernel, cudaFuncAttributeMaxDynamicSharedMemorySize,
                         FSMEM);

    // input split / fused weight transpose (wq rows 0..1023, wk 1024.., wv 1280..)
    split4<<<NTOK * DIM_ / 1024, 256>>>(x, xh, xl);
    wtrans<<<dim3(DIM_ / 32, 32), dim3(32, 8)>>>(wq, wth, wtl, DIM_);
    wtrans<<<dim3(256 / 32, 32), dim3(32, 8)>>>(wk, wth + 1024 * DIM_,
                                                wtl + 1024 * DIM_, 256);
    wtrans<<<dim3(256 / 32, 32), dim3(32, 8)>>>(wv, wth + 1280 * DIM_,
                                                wtl + 1280 * DIM_, 256);
    wtrans<<<dim3(DIM_ / 32, 32), dim3(32, 8)>>>(wo, woth, wotl, DIM_);

    // fused Q|K|V projection (one launch)
    hmma_gemm<<<dim3(QKVW / 128, NTOK / 128), 256, GSMEM>>>(xh, xl, wth, wtl,
                                                            qkv, QKVW);

    // RMSNorm + RoPE (q and k in place)
    const int nrows = NTOK * NH + NTOK * NKV;
    rmsrope_kernel<<<nrows / 8, 256>>>(gq, gk);

    // flash attention (writes g_aoh/g_aol directly)
    fattn_kernel<<<dim3(32, 8), 256, FSMEM>>>();

    // output projection
    hmma_gemm<<<dim3(DIM_ / 128, NTOK / 128), 256, GSMEM>>>(aoh, aol, woth, wotl,
                                                            (float*)d_out, DIM_);
}

// round 13
// speedup vs baseline: 3.7401x; 1.4273x over previous
#include <cuda_runtime.h>
#include <cuda_fp16.h>
#include <cstdint>
#include <math.h>

#define B_    2
#define L_    2048
#define DIM_  1024
#define NH    16
#define NKV   4
#define HD    64
#define NTOK  (B_*L_)       // 4096
#define QKVW  1536          // fused q|k|v row width

// ------------------------- scratch (__device__, no mallocs) -----------------
__device__ __align__(16) float g_qkv[NTOK*QKVW];   // Q(0..1023)|K(1024..1279)|V(1280..1535)

__device__ __align__(16) __half g_xh [NTOK*DIM_];
__device__ __align__(16) __half g_xl [NTOK*DIM_];
__device__ __align__(16) __half g_aoh[NTOK*DIM_];
__device__ __align__(16) __half g_aol[NTOK*DIM_];

__device__ __align__(16) __half g_wt  [QKVW*DIM_];  // [n][k] fused wq|wk|wv, fp16
__device__ __align__(16) __half g_wot [DIM_*DIM_];  // [n][k] wo, fp16

// ------------------------- helpers ------------------------------------------
__device__ __forceinline__ uint32_t smem_u32(const void* p) {
    uint32_t a;
    asm("{ .reg .u64 t; cvta.to.shared.u64 t, %1; cvt.u32.u64 %0, t; }"
        : "=r"(a) : "l"(p));
    return a;
}
__device__ __forceinline__ void ldm4(uint32_t f[4], uint32_t addr) {
    asm volatile("ldmatrix.sync.aligned.m8n8.x4.shared.b16 {%0,%1,%2,%3}, [%4];"
                 : "=r"(f[0]), "=r"(f[1]), "=r"(f[2]), "=r"(f[3]) : "r"(addr));
}
__device__ __forceinline__ void ldm4t(uint32_t f[4], uint32_t addr) {
    asm volatile("ldmatrix.sync.aligned.m8n8.x4.trans.shared.b16 {%0,%1,%2,%3}, [%4];"
                 : "=r"(f[0]), "=r"(f[1]), "=r"(f[2]), "=r"(f[3]) : "r"(addr));
}
__device__ __forceinline__ void mma16816(float c[4], const uint32_t a[4],
                                         uint32_t b0, uint32_t b1) {
    asm volatile("mma.sync.aligned.m16n8k16.row.col.f32.f16.f16.f32 "
                 "{%0,%1,%2,%3},{%4,%5,%6,%7},{%8,%9},{%0,%1,%2,%3};"
                 : "+f"(c[0]), "+f"(c[1]), "+f"(c[2]), "+f"(c[3])
                 : "r"(a[0]), "r"(a[1]), "r"(a[2]), "r"(a[3]), "r"(b0), "r"(b1));
}
__device__ __forceinline__ uint32_t pack2h(__half a, __half b) {
    return (uint32_t)__half_as_ushort(a) |
           ((uint32_t)__half_as_ushort(b) << 16);
}
__device__ __forceinline__ void cp16(uint32_t saddr, const void* gptr) {
    asm volatile("cp.async.cg.shared.global [%0], [%1], 16;"
                 :: "r"(saddr), "l"(gptr));
}
#define CP_COMMIT() asm volatile("cp.async.commit_group;" ::: "memory")
#define CP_WAIT(n)  asm volatile("cp.async.wait_group %0;" :: "n"(n) : "memory")

// ---------------------------------------------------------------------------
// HMMA 2-term fp16 GEMM: C[4096][Ncols] = (Ah + Al) @ B^T, fp32 accum.
// A*: [4096][1024] fp16 hi/lo; B: [Ncols][1024] fp16 single.
// Block 128x128, BK=32, 256 threads (8 warps 4x2), cp.async 3-stage ring.
// ---------------------------------------------------------------------------
#define PITCH     40
#define TILE_H    (128*PITCH)          // 5120 halfs / tile
#define TILE_BY   (TILE_H*2)           // 10240 bytes
#define BUF_BY    (3*TILE_BY)          // 30720 bytes/stage (Ah, Al, B)
#define GSMEM     (3*BUF_BY)           // 92160 bytes
#define NKB       (DIM_/32)            // 32

__global__ __launch_bounds__(256) void hmma_gemm(const __half* __restrict__ Ah_,
                                                 const __half* __restrict__ Al_,
                                                 const __half* __restrict__ B_arr,
                                                 float* __restrict__ C, int Ncols) {
    extern __shared__ __align__(128) __half sm[];

    const int tid  = threadIdx.x;
    const int wid  = tid >> 5;
    const int lane = tid & 31;
    const int wm   = (wid & 3) * 32;
    const int wn   = (wid >> 2) * 64;
    const int m0   = blockIdx.y * 128;
    const int n0   = blockIdx.x * 128;

    const uint32_t smb = smem_u32(sm);

    uint32_t aoff[2], boff[4];
    #pragma unroll
    for (int mt = 0; mt < 2; mt++)
        aoff[mt] = ((wm + mt * 16 + (lane & 15)) * PITCH + ((lane >> 4) << 3)) * 2;
    #pragma unroll
    for (int pr = 0; pr < 4; pr++)
        boff[pr] = ((wn + pr * 16 + (lane & 7) + ((lane >> 4) & 1) * 8) * PITCH
                    + (((lane >> 3) & 1) << 3)) * 2;

    float acc[2][8][4];
    #pragma unroll
    for (int i = 0; i < 2; i++)
        #pragma unroll
        for (int j = 0; j < 8; j++)
            #pragma unroll
            for (int r = 0; r < 4; r++) acc[i][j][r] = 0.0f;

    const int r0  = (tid * 2)     >> 2, c80 = ((tid * 2)     & 3) << 3;
    const int r1  = (tid * 2 + 1) >> 2, c81 = ((tid * 2 + 1) & 3) << 3;
    const uint32_t so0 = (r0 * PITCH + c80) * 2;
    const uint32_t so1 = (r1 * PITCH + c81) * 2;

    auto stage = [&](int kb, int buf) {
        const int k0 = kb << 5;
        const uint32_t sb = smb + buf * BUF_BY;
        size_t goA0 = (size_t)(m0 + r0) * DIM_ + k0 + c80;
        size_t goB0 = (size_t)(n0 + r0) * DIM_ + k0 + c80;
        size_t goA1 = (size_t)(m0 + r1) * DIM_ + k0 + c81;
        size_t goB1 = (size_t)(n0 + r1) * DIM_ + k0 + c81;
        cp16(sb + so0,               Ah_   + goA0);
        cp16(sb + TILE_BY + so0,     Al_   + goA0);
        cp16(sb + 2 * TILE_BY + so0, B_arr + goB0);
        cp16(sb + so1,               Ah_   + goA1);
        cp16(sb + TILE_BY + so1,     Al_   + goA1);
        cp16(sb + 2 * TILE_BY + so1, B_arr + goB1);
        CP_COMMIT();
    };

    stage(0, 0);
    stage(1, 1);

    int buf = 0;
    #pragma unroll 1
    for (int kb = 0; kb < NKB; kb++) {
        if (kb + 1 < NKB) CP_WAIT(1); else CP_WAIT(0);
        __syncthreads();

        const uint32_t sb = smb + buf * BUF_BY;
        #pragma unroll
        for (int ks = 0; ks < 2; ks++) {
            uint32_t ah[2][4], al[2][4], bh[4][4];
            #pragma unroll
            for (int mt = 0; mt < 2; mt++) {
                uint32_t ao = sb + aoff[mt] + ks * 32;
                ldm4(ah[mt], ao);
                ldm4(al[mt], ao + TILE_BY);
            }
            #pragma unroll
            for (int pr = 0; pr < 4; pr++) {
                uint32_t bo = sb + boff[pr] + ks * 32;
                ldm4(bh[pr], bo + 2 * TILE_BY);
            }
            #pragma unroll
            for (int mt = 0; mt < 2; mt++)
                #pragma unroll
                for (int nt = 0; nt < 8; nt++) {
                    const uint32_t* f = bh[nt >> 1];
                    mma16816(acc[mt][nt], ah[mt], (nt & 1) ? f[2] : f[0],
                             (nt & 1) ? f[3] : f[1]);
                }
            #pragma unroll
            for (int mt = 0; mt < 2; mt++)
                #pragma unroll
                for (int nt = 0; nt < 8; nt++) {
                    const uint32_t* f = bh[nt >> 1];
                    mma16816(acc[mt][nt], al[mt], (nt & 1) ? f[2] : f[0],
                             (nt & 1) ? f[3] : f[1]);
                }
        }
        __syncthreads();
        if (kb + 2 < NKB) stage(kb + 2, (kb + 2) % 3);
        buf = (buf + 1 == 3) ? 0 : buf + 1;
    }

    #pragma unroll
    for (int mt = 0; mt < 2; mt++) {
        const int row = m0 + wm + mt * 16 + (lane >> 2);
        #pragma unroll
        for (int nt = 0; nt < 8; nt++) {
            const int col = n0 + wn + nt * 8 + (lane & 3) * 2;
            float2 lo; lo.x = acc[mt][nt][0]; lo.y = acc[mt][nt][1];
            float2 hi; hi.x = acc[mt][nt][2]; hi.y = acc[mt][nt][3];
            *(float2*)&C[(size_t)row * Ncols + col]       = lo;
            *(float2*)&C[(size_t)(row + 8) * Ncols + col] = hi;
        }
    }
}

// ---------------------------------------------------------------------------
// fp32 -> fp16 hi/lo split (4 elems/thread)
// ---------------------------------------------------------------------------
__global__ __launch_bounds__(256) void split4(const float* __restrict__ src,
                                              __half* __restrict__ hi,
                                              __half* __restrict__ lo) {
    size_t i = ((size_t)blockIdx.x * 256 + threadIdx.x) * 4;
    float4 v = *(const float4*)(src + i);
    float vv[4] = {v.x, v.y, v.z, v.w};
    ushort4 H, Lo;
    unsigned short* hp = &H.x;
    unsigned short* lp = &Lo.x;
    #pragma unroll
    for (int j = 0; j < 4; j++) {
        __half h = __float2half(vv[j]);
        float res = vv[j] - __half2float(h);
        hp[j] = __half_as_ushort(h);
        lp[j] = __half_as_ushort(__float2half(res));
    }
    *(ushort4*)(hi + i) = H;
    *(ushort4*)(lo + i) = Lo;
}

// ---------------------------------------------------------------------------
// Weight transpose: W[1024][N] fp32 -> T[N][1024] fp16 single.
// ---------------------------------------------------------------------------
__global__ void wtrans(const float* __restrict__ W,
                       __half* __restrict__ T, int N) {
    __shared__ float t[32][33];
    const int tx = threadIdx.x, ty = threadIdx.y;
    const int n0 = blockIdx.x * 32, k0 = blockIdx.y * 32;
    #pragma unroll
    for (int i = 0; i < 4; i++) {
        int r = ty + i * 8;
        t[r][tx] = W[(size_t)(k0 + r) * N + n0 + tx];
    }
    __syncthreads();
    #pragma unroll
    for (int i = 0; i < 4; i++) {
        int r = ty + i * 8;
        T[(size_t)(n0 + r) * DIM_ + k0 + tx] = __float2half(t[tx][r]);
    }
}

// ---------------------------------------------------------------------------
// RMSNorm + RoPE in place on fused g_qkv (Q cols 0..1023, K cols 1024..1279).
// ---------------------------------------------------------------------------
__global__ __launch_bounds__(256) void rmsrope_kernel(const float* __restrict__ gq,
                                                      const float* __restrict__ gk) {
    const int gw   = blockIdx.x * 8 + (threadIdx.x >> 5);
    const int lane = threadIdx.x & 31;

    float* row;
    const float* g;
    int tok;
    if (gw < NTOK * NH) {
        tok = gw >> 4;
        int h = gw & 15;
        row = g_qkv + (size_t)tok * QKVW + h * HD;
        g   = gq;
    } else {
        int r = gw - NTOK * NH;
        tok = r >> 2;
        int hk = r & 3;
        row = g_qkv + (size_t)tok * QKVW + 1024 + hk * HD;
        g   = gk;
    }
    const int pos = tok & (L_ - 1);

    float2 v = ((const float2*)row)[lane];
    float ss = v.x * v.x + v.y * v.y;
    #pragma unroll
    for (int off = 16; off > 0; off >>= 1)
        ss += __shfl_xor_sync(0xffffffffu, ss, off);
    float rn = rsqrtf(ss * (1.0f / 64.0f) + 1e-6f);

    float2 gg = ((const float2*)g)[lane];
    float t1 = v.x * rn * gg.x;
    float t2 = v.y * rn * gg.y;

    float inv_freq = exp2f((float)lane * (-13.287712379549449f / 32.0f));
    float ang = (float)pos * inv_freq;
    float s, c;
    sincosf(ang, &s, &c);

    ((float2*)row)[lane] = make_float2(t1 * c - t2 * s, t1 * s + t2 * c);
}

// ---------------------------------------------------------------------------
// HMMA flash attention, fp16: S = (Qh+Ql)K, O = (Ph+Pl)V; K,V single fp16.
// Block = q-tile(64) x 4 heads of one kv group; 8 warps = (head, m-half).
// ---------------------------------------------------------------------------
#define AP      72
#define QH_OFF  0
#define QL_OFF  (4*64*AP)              // 18432
#define KH_OFF  (2*QL_OFF)             // 36864
#define VH_OFF  (KH_OFF + 64*AP)       // 41472
#define P_OFF   (VH_OFF + 64*AP)       // 46080
#define PW_SZ   (32*AP)                // 2304
#define FSMEM   ((P_OFF + 8*PW_SZ)*2)  // 129024 bytes

__global__ __launch_bounds__(256, 1) void fattn_kernel() {
    extern __shared__ __align__(16) __half fsm[];

    const int tid   = threadIdx.x;
    const int w     = tid >> 5;
    const int lane  = tid & 31;
    const int t     = blockIdx.x;
    const int bz    = blockIdx.y;
    const int b     = bz >> 2;
    const int hk    = bz & 3;
    const int hl    = w >> 1;
    const int h     = hk * 4 + hl;
    const int mhalf = w & 1;
    const uint32_t smb = smem_u32(fsm);

    // ---- load Q (4 heads): scale 1/8, split fp16 hi/lo ----
    #pragma unroll
    for (int u = 0; u < 8; u++) {
        int idx = tid + (u << 8);
        int hh  = idx >> 9;
        int rem = idx & 511;
        int row = rem >> 3, c8 = (rem & 7) << 3;
        const float* src = g_qkv + (size_t)(b * L_ + t * 64 + row) * QKVW
                         + (hk * 4 + hh) * 64 + c8;
        float4 v0 = *(const float4*)src, v1 = *(const float4*)(src + 4);
        float f[8] = {v0.x, v0.y, v0.z, v0.w, v1.x, v1.y, v1.z, v1.w};
        uint32_t hi[4], lo[4];
        #pragma unroll
        for (int j = 0; j < 4; j++) {
            float a = f[2*j] * 0.125f, c = f[2*j+1] * 0.125f;
            __half ha = __float2half(a), hc = __float2half(c);
            hi[j] = pack2h(ha, hc);
            lo[j] = pack2h(__float2half(a - __half2float(ha)),
                           __float2half(c - __half2float(hc)));
        }
        int off = hh * 64 * AP + row * AP + c8;
        *(uint4*)(fsm + QH_OFF + off) = make_uint4(hi[0], hi[1], hi[2], hi[3]);
        *(uint4*)(fsm + QL_OFF + off) = make_uint4(lo[0], lo[1], lo[2], lo[3]);
    }

    float sO[2][8][4];
    #pragma unroll
    for (int i = 0; i < 2; i++)
        #pragma unroll
        for (int j = 0; j < 8; j++)
            #pragma unroll
            for (int r = 0; r < 4; r++) sO[i][j][r] = 0.0f;
    float ms[2][2] = {{-1e30f, -1e30f}, {-1e30f, -1e30f}};
    float ssum[2][2] = {{0.0f, 0.0f}, {0.0f, 0.0f}};

    const uint32_t pw = P_OFF + w * PW_SZ;

    auto do_chunk = [&](int kb, bool partial) {
        __syncthreads();
        // ---- convert K/V chunk to fp16 smem (single term) ----
        #pragma unroll
        for (int u = 0; u < 2; u++) {
            int c = (tid << 1) + u;
            int row = c >> 3, c8 = (c & 7) << 3;
            const float* base = g_qkv + (size_t)(b * L_ + kb + row) * QKVW
                              + 1024 + hk * 64 + c8;
            float4 k0 = *(const float4*)base, k1 = *(const float4*)(base + 4);
            float4 q0 = *(const float4*)(base + 256), q1 = *(const float4*)(base + 260);
            float fk[8] = {k0.x, k0.y, k0.z, k0.w, k1.x, k1.y, k1.z, k1.w};
            float fv[8] = {q0.x, q0.y, q0.z, q0.w, q1.x, q1.y, q1.z, q1.w};
            uint32_t kh[4], vh[4];
            #pragma unroll
            for (int j = 0; j < 4; j++) {
                kh[j] = pack2h(__float2half(fk[2*j]), __float2half(fk[2*j+1]));
                vh[j] = pack2h(__float2half(fv[2*j]), __float2half(fv[2*j+1]));
            }
            int off = row * AP + c8;
            *(uint4*)(fsm + KH_OFF + off) = make_uint4(kh[0], kh[1], kh[2], kh[3]);
            *(uint4*)(fsm + VH_OFF + off) = make_uint4(vh[0], vh[1], vh[2], vh[3]);
        }
        __syncthreads();

        // ---- S = (Qh + Ql) K^T ----
        float sS[2][8][4];
        #pragma unroll
        for (int i = 0; i < 2; i++)
            #pragma unroll
            for (int j = 0; j < 8; j++)
                #pragma unroll
                for (int r = 0; r < 4; r++) sS[i][j][r] = 0.0f;

        #pragma unroll
        for (int kt = 0; kt < 4; kt++) {
            uint32_t ah[2][4], al[2][4], bh[4][4];
            #pragma unroll
            for (int mt = 0; mt < 2; mt++) {
                uint32_t ao = smb + 2 * (QH_OFF + hl * 64 * AP
                    + (mhalf * 32 + mt * 16 + (lane & 15)) * AP
                    + kt * 16 + ((lane >> 4) << 3));
                ldm4(ah[mt], ao);
                ldm4(al[mt], ao + 2 * QL_OFF);
            }
            #pragma unroll
            for (int pr = 0; pr < 4; pr++) {
                uint32_t bo = smb + 2 * (KH_OFF
                    + (pr * 16 + (lane & 7) + ((lane >> 4) & 1) * 8) * AP
                    + kt * 16 + (((lane >> 3) & 1) << 3));
                ldm4(bh[pr], bo);
            }
            #pragma unroll
            for (int mt = 0; mt < 2; mt++)
                #pragma unroll
                for (int nt = 0; nt < 8; nt++) {
                    const uint32_t* f = bh[nt >> 1];
                    mma16816(sS[mt][nt], ah[mt], (nt & 1) ? f[2] : f[0],
                             (nt & 1) ? f[3] : f[1]);
                }
            #pragma unroll
            for (int mt = 0; mt < 2; mt++)
                #pragma unroll
                for (int nt = 0; nt < 8; nt++) {
                    const uint32_t* f = bh[nt >> 1];
                    mma16816(sS[mt][nt], al[mt], (nt & 1) ? f[2] : f[0],
                             (nt & 1) ? f[3] : f[1]);
                }
        }

        if (partial) {
            #pragma unroll
            for (int mt = 0; mt < 2; mt++)
                #pragma unroll
                for (int rh = 0; rh < 2; rh++) {
                    int iq = t * 64 + mhalf * 32 + mt * 16 + (lane >> 2) + rh * 8;
                    #pragma unroll
                    for (int nt = 0; nt < 8; nt++)
                        #pragma unroll
                        for (int c = 0; c < 2; c++) {
                            int j = kb + nt * 8 + (lane & 3) * 2 + c;
                            bool valid = (j <= iq) && ((j >= iq - 256) || (j < 64));
                            if (!valid) sS[mt][nt][rh * 2 + c] = -INFINITY;
                        }
                }
        }

        // ---- online softmax ----
        #pragma unroll
        for (int mt = 0; mt < 2; mt++)
            #pragma unroll
            for (int rh = 0; rh < 2; rh++) {
                float rmax = -INFINITY;
                #pragma unroll
                for (int nt = 0; nt < 8; nt++)
                    rmax = fmaxf(rmax, fmaxf(sS[mt][nt][rh*2], sS[mt][nt][rh*2+1]));
                rmax = fmaxf(rmax, __shfl_xor_sync(0xffffffffu, rmax, 1));
                rmax = fmaxf(rmax, __shfl_xor_sync(0xffffffffu, rmax, 2));
                float mn = fmaxf(ms[mt][rh], rmax);
                float corr = __expf(ms[mt][rh] - mn);
                float rs = 0.0f;
                #pragma unroll
                for (int nt = 0; nt < 8; nt++) {
                    float e0 = __expf(sS[mt][nt][rh*2]     - mn);
                    float e1 = __expf(sS[mt][nt][rh*2 + 1] - mn);
                    sS[mt][nt][rh*2] = e0; sS[mt][nt][rh*2+1] = e1;
                    sO[mt][nt][rh*2]   *= corr;
                    sO[mt][nt][rh*2+1] *= corr;
                    rs += e0 + e1;
                }
                rs += __shfl_xor_sync(0xffffffffu, rs, 1);
                rs += __shfl_xor_sync(0xffffffffu, rs, 2);
                ssum[mt][rh] = ssum[mt][rh] * corr + rs;
                ms[mt][rh] = mn;
            }

        // ---- P(hi) x V ----
        #pragma unroll
        for (int mt = 0; mt < 2; mt++)
            #pragma unroll
            for (int rh = 0; rh < 2; rh++)
                #pragma unroll
                for (int nt = 0; nt < 8; nt++) {
                    float e0 = sS[mt][nt][rh*2], e1 = sS[mt][nt][rh*2+1];
                    uint32_t pk = pack2h(__float2half(e0), __float2half(e1));
                    uint32_t off = pw + (mt * 16 + (lane >> 2) + rh * 8) * AP
                                 + nt * 8 + (lane & 3) * 2;
                    *(uint32_t*)((char*)fsm + 2 * off) = pk;
                }
        __syncwarp();
        #pragma unroll
        for (int kt = 0; kt < 4; kt++) {
            uint32_t ap[2][4], vh[4][4];
            #pragma unroll
            for (int mt = 0; mt < 2; mt++) {
                uint32_t ao = smb + 2 * (pw + (mt * 16 + (lane & 15)) * AP
                                         + kt * 16 + ((lane >> 4) << 3));
                ldm4(ap[mt], ao);
            }
            #pragma unroll
            for (int pr = 0; pr < 4; pr++) {
                uint32_t bo = smb + 2 * (VH_OFF
                    + (kt * 16 + (lane & 7) + ((lane >> 3) & 1) * 8) * AP
                    + pr * 16 + (((lane >> 4) & 1) << 3));
                ldm4t(vh[pr], bo);
            }
            #pragma unroll
            for (int mt = 0; mt < 2; mt++)
                #pragma unroll
                for (int nt = 0; nt < 8; nt++) {
                    const uint32_t* f = vh[nt >> 1];
                    mma16816(sO[mt][nt], ap[mt], (nt & 1) ? f[2] : f[0],
                             (nt & 1) ? f[3] : f[1]);
                }
        }
        __syncwarp();
        // ---- P(lo) x V ----
        #pragma unroll
        for (int mt = 0; mt < 2; mt++)
            #pragma unroll
            for (int rh = 0; rh < 2; rh++)
                #pragma unroll
                for (int nt = 0; nt < 8; nt++) {
                    float e0 = sS[mt][nt][rh*2], e1 = sS[mt][nt][rh*2+1];
                    float h0 = __half2float(__float2half(e0));
                    float h1 = __half2float(__float2half(e1));
                    uint32_t pk = pack2h(__float2half(e0 - h0),
                                         __float2half(e1 - h1));
                    uint32_t off = pw + (mt * 16 + (lane >> 2) + rh * 8) * AP
                                 + nt * 8 + (lane & 3) * 2;
                    *(uint32_t*)((char*)fsm + 2 * off) = pk;
                }
        __syncwarp();
        #pragma unroll
        for (int kt = 0; kt < 4; kt++) {
            uint32_t ap[2][4], vh[4][4];
            #pragma unroll
            for (int mt = 0; mt < 2; mt++) {
                uint32_t ao = smb + 2 * (pw + (mt * 16 + (lane & 15)) * AP
                                         + kt * 16 + ((lane >> 4) << 3));
                ldm4(ap[mt], ao);
            }
            #pragma unroll
            for (int pr = 0; pr < 4; pr++) {
                uint32_t bo = smb + 2 * (VH_OFF
                    + (kt * 16 + (lane & 7) + ((lane >> 3) & 1) * 8) * AP
                    + pr * 16 + (((lane >> 4) & 1) << 3));
                ldm4t(vh[pr], bo);
            }
            #pragma unroll
            for (int mt = 0; mt < 2; mt++)
                #pragma unroll
                for (int nt = 0; nt < 8; nt++) {
                    const uint32_t* f = vh[nt >> 1];
                    mma16816(sO[mt][nt], ap[mt], (nt & 1) ? f[2] : f[0],
                             (nt & 1) ? f[3] : f[1]);
                }
        }
    };

    if (t > 4) do_chunk(0, false);
    int c0 = t - 4; if (c0 < 0) c0 = 0;
    for (int cc = c0; cc <= t; cc++) {
        bool partial = (cc == t) || (t >= 5 && cc == t - 4);
        do_chunk(cc * 64, partial);
    }

    // ---- epilogue: normalize, write fp16 hi/lo ----
    #pragma unroll
    for (int mt = 0; mt < 2; mt++)
        #pragma unroll
        for (int rh = 0; rh < 2; rh++) {
            float inv = 1.0f / ssum[mt][rh];
            int tok = b * L_ + t * 64 + mhalf * 32 + mt * 16 + (lane >> 2) + rh * 8;
            #pragma unroll
            for (int nt = 0; nt < 8; nt++) {
                float v0 = sO[mt][nt][rh*2]     * inv;
                float v1 = sO[mt][nt][rh*2 + 1] * inv;
                __half h0 = __float2half(v0);
                __half h1 = __float2half(v1);
                size_t o = (size_t)tok * DIM_ + h * 64 + nt * 8 + (lane & 3) * 2;
                *(uint32_t*)&g_aoh[o] = pack2h(h0, h1);
                *(uint32_t*)&g_aol[o] =
                    pack2h(__float2half(v0 - __half2float(h0)),
                           __float2half(v1 - __half2float(h1)));
            }
        }
}

// ---------------------------------------------------------------------------
extern "C" void kernel_launch(void* const* d_in, const int* in_sizes, int n_in,
                              void* d_out, int out_size) {
    const float* x  = (const float*)d_in[0];
    const float* wq = (const float*)d_in[1];
    const float* wk = (const float*)d_in[2];
    const float* wv = (const float*)d_in[3];
    const float* wo = (const float*)d_in[4];
    const float* gq = (const float*)d_in[5];
    const float* gk = (const float*)d_in[6];

    float *qkv;
    __half *xh, *xl, *aoh, *aol, *wt, *wot;
    cudaGetSymbolAddress((void**)&qkv, g_qkv);
    cudaGetSymbolAddress((void**)&xh,  g_xh);
    cudaGetSymbolAddress((void**)&xl,  g_xl);
    cudaGetSymbolAddress((void**)&aoh, g_aoh);
    cudaGetSymbolAddress((void**)&aol, g_aol);
    cudaGetSymbolAddress((void**)&wt,  g_wt);
    cudaGetSymbolAddress((void**)&wot, g_wot);

    cudaFuncSetAttribute(hmma_gemm, cudaFuncAttributeMaxDynamicSharedMemorySize,
                         GSMEM);
    cudaFuncSetAttribute(fattn_kernel, cudaFuncAttributeMaxDynamicSharedMemorySize,
                         FSMEM);

    // input split / fused weight transpose
    split4<<<NTOK * DIM_ / 1024, 256>>>(x, xh, xl);
    wtrans<<<dim3(DIM_ / 32, 32), dim3(32, 8)>>>(wq, wt, DIM_);
    wtrans<<<dim3(256 / 32, 32), dim3(32, 8)>>>(wk, wt + 1024 * DIM_, 256);
    wtrans<<<dim3(256 / 32, 32), dim3(32, 8)>>>(wv, wt + 1280 * DIM_, 256);
    wtrans<<<dim3(DIM_ / 32, 32), dim3(32, 8)>>>(wo, wot, DIM_);

    // fused Q|K|V projection
    hmma_gemm<<<dim3(QKVW / 128, NTOK / 128), 256, GSMEM>>>(xh, xl, wt, qkv, QKVW);

    // RMSNorm + RoPE (q and k in place)
    const int nrows = NTOK * NH + NTOK * NKV;
    rmsrope_kernel<<<nrows / 8, 256>>>(gq, gk);

    // flash attention (writes g_aoh/g_aol directly)
    fattn_kernel<<<dim3(32, 8), 256, FSMEM>>>();

    // output projection
    hmma_gemm<<<dim3(DIM_ / 128, NTOK / 128), 256, GSMEM>>>(aoh, aol, wot,
                                                            (float*)d_out, DIM_);
}

// round 14
// speedup vs baseline: 4.3786x; 1.1707x over previous
#include <cuda_runtime.h>
#include <cuda_fp16.h>
#include <cstdint>
#include <math.h>

#define B_    2
#define L_    2048
#define DIM_  1024
#define NH    16
#define NKV   4
#define HD    64
#define NTOK  (B_*L_)       // 4096
#define QKVW  1536          // fused q|k|v row width

// ------------------------- scratch (__device__, no mallocs) -----------------
__device__ __align__(16) float g_qkv[NTOK*QKVW];   // Q(0..1023)|K(1024..1279)|V(1280..1535)

__device__ __align__(16) __half g_xh [NTOK*DIM_];
__device__ __align__(16) __half g_xl [NTOK*DIM_];
__device__ __align__(16) __half g_ao [NTOK*DIM_];  // attention out, single fp16

__device__ __align__(16) __half g_wt  [QKVW*DIM_];  // [n][k] fused wq|wk|wv, fp16
__device__ __align__(16) __half g_wot [DIM_*DIM_];  // [n][k] wo, fp16

// ------------------------- helpers ------------------------------------------
__device__ __forceinline__ uint32_t smem_u32(const void* p) {
    uint32_t a;
    asm("{ .reg .u64 t; cvta.to.shared.u64 t, %1; cvt.u32.u64 %0, t; }"
        : "=r"(a) : "l"(p));
    return a;
}
__device__ __forceinline__ void ldm4(uint32_t f[4], uint32_t addr) {
    asm volatile("ldmatrix.sync.aligned.m8n8.x4.shared.b16 {%0,%1,%2,%3}, [%4];"
                 : "=r"(f[0]), "=r"(f[1]), "=r"(f[2]), "=r"(f[3]) : "r"(addr));
}
__device__ __forceinline__ void ldm4t(uint32_t f[4], uint32_t addr) {
    asm volatile("ldmatrix.sync.aligned.m8n8.x4.trans.shared.b16 {%0,%1,%2,%3}, [%4];"
                 : "=r"(f[0]), "=r"(f[1]), "=r"(f[2]), "=r"(f[3]) : "r"(addr));
}
__device__ __forceinline__ void mma16816(float c[4], const uint32_t a[4],
                                         uint32_t b0, uint32_t b1) {
    asm volatile("mma.sync.aligned.m16n8k16.row.col.f32.f16.f16.f32 "
                 "{%0,%1,%2,%3},{%4,%5,%6,%7},{%8,%9},{%0,%1,%2,%3};"
                 : "+f"(c[0]), "+f"(c[1]), "+f"(c[2]), "+f"(c[3])
                 : "r"(a[0]), "r"(a[1]), "r"(a[2]), "r"(a[3]), "r"(b0), "r"(b1));
}
__device__ __forceinline__ uint32_t pack2h(__half a, __half b) {
    return (uint32_t)__half_as_ushort(a) |
           ((uint32_t)__half_as_ushort(b) << 16);
}
__device__ __forceinline__ void cp16(uint32_t saddr, const void* gptr) {
    asm volatile("cp.async.cg.shared.global [%0], [%1], 16;"
                 :: "r"(saddr), "l"(gptr));
}
#define CP_COMMIT() asm volatile("cp.async.commit_group;" ::: "memory")
#define CP_WAIT(n)  asm volatile("cp.async.wait_group %0;" :: "n"(n) : "memory")

#define PITCH     40
#define TILE_H    (128*PITCH)          // 5120 halfs / tile
#define TILE_BY   (TILE_H*2)           // 10240 bytes
#define NKB       (DIM_/32)            // 32

// ---------------------------------------------------------------------------
// HMMA 2-term fp16 GEMM: C = (Ah + Al) @ B^T, fp32 accum. cp.async 3-stage.
// ---------------------------------------------------------------------------
#define BUF2_BY   (3*TILE_BY)          // Ah, Al, B
#define GSMEM2    (3*BUF2_BY)

__global__ __launch_bounds__(256) void hmma_gemm2(const __half* __restrict__ Ah_,
                                                  const __half* __restrict__ Al_,
                                                  const __half* __restrict__ B_arr,
                                                  float* __restrict__ C, int Ncols) {
    extern __shared__ __align__(128) __half sm[];

    const int tid  = threadIdx.x;
    const int wid  = tid >> 5;
    const int lane = tid & 31;
    const int wm   = (wid & 3) * 32;
    const int wn   = (wid >> 2) * 64;
    const int m0   = blockIdx.y * 128;
    const int n0   = blockIdx.x * 128;

    const uint32_t smb = smem_u32(sm);

    uint32_t aoff[2], boff[4];
    #pragma unroll
    for (int mt = 0; mt < 2; mt++)
        aoff[mt] = ((wm + mt * 16 + (lane & 15)) * PITCH + ((lane >> 4) << 3)) * 2;
    #pragma unroll
    for (int pr = 0; pr < 4; pr++)
        boff[pr] = ((wn + pr * 16 + (lane & 7) + ((lane >> 4) & 1) * 8) * PITCH
                    + (((lane >> 3) & 1) << 3)) * 2;

    float acc[2][8][4];
    #pragma unroll
    for (int i = 0; i < 2; i++)
        #pragma unroll
        for (int j = 0; j < 8; j++)
            #pragma unroll
            for (int r = 0; r < 4; r++) acc[i][j][r] = 0.0f;

    const int r0  = (tid * 2)     >> 2, c80 = ((tid * 2)     & 3) << 3;
    const int r1  = (tid * 2 + 1) >> 2, c81 = ((tid * 2 + 1) & 3) << 3;
    const uint32_t so0 = (r0 * PITCH + c80) * 2;
    const uint32_t so1 = (r1 * PITCH + c81) * 2;

    auto stage = [&](int kb, int buf) {
        const int k0 = kb << 5;
        const uint32_t sb = smb + buf * BUF2_BY;
        size_t goA0 = (size_t)(m0 + r0) * DIM_ + k0 + c80;
        size_t goB0 = (size_t)(n0 + r0) * DIM_ + k0 + c80;
        size_t goA1 = (size_t)(m0 + r1) * DIM_ + k0 + c81;
        size_t goB1 = (size_t)(n0 + r1) * DIM_ + k0 + c81;
        cp16(sb + so0,               Ah_   + goA0);
        cp16(sb + TILE_BY + so0,     Al_   + goA0);
        cp16(sb + 2 * TILE_BY + so0, B_arr + goB0);
        cp16(sb + so1,               Ah_   + goA1);
        cp16(sb + TILE_BY + so1,     Al_   + goA1);
        cp16(sb + 2 * TILE_BY + so1, B_arr + goB1);
        CP_COMMIT();
    };

    stage(0, 0);
    stage(1, 1);

    int buf = 0;
    #pragma unroll 1
    for (int kb = 0; kb < NKB; kb++) {
        if (kb + 1 < NKB) CP_WAIT(1); else CP_WAIT(0);
        __syncthreads();

        const uint32_t sb = smb + buf * BUF2_BY;
        #pragma unroll
        for (int ks = 0; ks < 2; ks++) {
            uint32_t ah[2][4], al[2][4], bh[4][4];
            #pragma unroll
            for (int mt = 0; mt < 2; mt++) {
                uint32_t ao = sb + aoff[mt] + ks * 32;
                ldm4(ah[mt], ao);
                ldm4(al[mt], ao + TILE_BY);
            }
            #pragma unroll
            for (int pr = 0; pr < 4; pr++) {
                uint32_t bo = sb + boff[pr] + ks * 32;
                ldm4(bh[pr], bo + 2 * TILE_BY);
            }
            #pragma unroll
            for (int mt = 0; mt < 2; mt++)
                #pragma unroll
                for (int nt = 0; nt < 8; nt++) {
                    const uint32_t* f = bh[nt >> 1];
                    mma16816(acc[mt][nt], ah[mt], (nt & 1) ? f[2] : f[0],
                             (nt & 1) ? f[3] : f[1]);
                }
            #pragma unroll
            for (int mt = 0; mt < 2; mt++)
                #pragma unroll
                for (int nt = 0; nt < 8; nt++) {
                    const uint32_t* f = bh[nt >> 1];
                    mma16816(acc[mt][nt], al[mt], (nt & 1) ? f[2] : f[0],
                             (nt & 1) ? f[3] : f[1]);
                }
        }
        __syncthreads();
        if (kb + 2 < NKB) stage(kb + 2, (kb + 2) % 3);
        buf = (buf + 1 == 3) ? 0 : buf + 1;
    }

    #pragma unroll
    for (int mt = 0; mt < 2; mt++) {
        const int row = m0 + wm + mt * 16 + (lane >> 2);
        #pragma unroll
        for (int nt = 0; nt < 8; nt++) {
            const int col = n0 + wn + nt * 8 + (lane & 3) * 2;
            float2 lo; lo.x = acc[mt][nt][0]; lo.y = acc[mt][nt][1];
            float2 hi; hi.x = acc[mt][nt][2]; hi.y = acc[mt][nt][3];
            *(float2*)&C[(size_t)row * Ncols + col]       = lo;
            *(float2*)&C[(size_t)(row + 8) * Ncols + col] = hi;
        }
    }
}

// ---------------------------------------------------------------------------
// HMMA 1-term fp16 GEMM: C = A @ B^T, fp32 accum. cp.async 3-stage.
// ---------------------------------------------------------------------------
#define BUF1_BY   (2*TILE_BY)          // A, B
#define GSMEM1    (3*BUF1_BY)

__global__ __launch_bounds__(256) void hmma_gemm1(const __half* __restrict__ A_,
                                                  const __half* __restrict__ B_arr,
                                                  float* __restrict__ C, int Ncols) {
    extern __shared__ __align__(128) __half sm[];

    const int tid  = threadIdx.x;
    const int wid  = tid >> 5;
    const int lane = tid & 31;
    const int wm   = (wid & 3) * 32;
    const int wn   = (wid >> 2) * 64;
    const int m0   = blockIdx.y * 128;
    const int n0   = blockIdx.x * 128;

    const uint32_t smb = smem_u32(sm);

    uint32_t aoff[2], boff[4];
    #pragma unroll
    for (int mt = 0; mt < 2; mt++)
        aoff[mt] = ((wm + mt * 16 + (lane & 15)) * PITCH + ((lane >> 4) << 3)) * 2;
    #pragma unroll
    for (int pr = 0; pr < 4; pr++)
        boff[pr] = ((wn + pr * 16 + (lane & 7) + ((lane >> 4) & 1) * 8) * PITCH
                    + (((lane >> 3) & 1) << 3)) * 2;

    float acc[2][8][4];
    #pragma unroll
    for (int i = 0; i < 2; i++)
        #pragma unroll
        for (int j = 0; j < 8; j++)
            #pragma unroll
            for (int r = 0; r < 4; r++) acc[i][j][r] = 0.0f;

    const int r0  = (tid * 2)     >> 2, c80 = ((tid * 2)     & 3) << 3;
    const int r1  = (tid * 2 + 1) >> 2, c81 = ((tid * 2 + 1) & 3) << 3;
    const uint32_t so0 = (r0 * PITCH + c80) * 2;
    const uint32_t so1 = (r1 * PITCH + c81) * 2;

    auto stage = [&](int kb, int buf) {
        const int k0 = kb << 5;
        const uint32_t sb = smb + buf * BUF1_BY;
        size_t goA0 = (size_t)(m0 + r0) * DIM_ + k0 + c80;
        size_t goB0 = (size_t)(n0 + r0) * DIM_ + k0 + c80;
        size_t goA1 = (size_t)(m0 + r1) * DIM_ + k0 + c81;
        size_t goB1 = (size_t)(n0 + r1) * DIM_ + k0 + c81;
        cp16(sb + so0,           A_    + goA0);
        cp16(sb + TILE_BY + so0, B_arr + goB0);
        cp16(sb + so1,           A_    + goA1);
        cp16(sb + TILE_BY + so1, B_arr + goB1);
        CP_COMMIT();
    };

    stage(0, 0);
    stage(1, 1);

    int buf = 0;
    #pragma unroll 1
    for (int kb = 0; kb < NKB; kb++) {
        if (kb + 1 < NKB) CP_WAIT(1); else CP_WAIT(0);
        __syncthreads();

        const uint32_t sb = smb + buf * BUF1_BY;
        #pragma unroll
        for (int ks = 0; ks < 2; ks++) {
            uint32_t ah[2][4], bh[4][4];
            #pragma unroll
            for (int mt = 0; mt < 2; mt++)
                ldm4(ah[mt], sb + aoff[mt] + ks * 32);
            #pragma unroll
            for (int pr = 0; pr < 4; pr++)
                ldm4(bh[pr], sb + boff[pr] + ks * 32 + TILE_BY);
            #pragma unroll
            for (int mt = 0; mt < 2; mt++)
                #pragma unroll
                for (int nt = 0; nt < 8; nt++) {
                    const uint32_t* f = bh[nt >> 1];
                    mma16816(acc[mt][nt], ah[mt], (nt & 1) ? f[2] : f[0],
                             (nt & 1) ? f[3] : f[1]);
                }
        }
        __syncthreads();
        if (kb + 2 < NKB) stage(kb + 2, (kb + 2) % 3);
        buf = (buf + 1 == 3) ? 0 : buf + 1;
    }

    #pragma unroll
    for (int mt = 0; mt < 2; mt++) {
        const int row = m0 + wm + mt * 16 + (lane >> 2);
        #pragma unroll
        for (int nt = 0; nt < 8; nt++) {
            const int col = n0 + wn + nt * 8 + (lane & 3) * 2;
            float2 lo; lo.x = acc[mt][nt][0]; lo.y = acc[mt][nt][1];
            float2 hi; hi.x = acc[mt][nt][2]; hi.y = acc[mt][nt][3];
            *(float2*)&C[(size_t)row * Ncols + col]       = lo;
            *(float2*)&C[(size_t)(row + 8) * Ncols + col] = hi;
        }
    }
}

// ---------------------------------------------------------------------------
__global__ __launch_bounds__(256) void split4(const float* __restrict__ src,
                                              __half* __restrict__ hi,
                                              __half* __restrict__ lo) {
    size_t i = ((size_t)blockIdx.x * 256 + threadIdx.x) * 4;
    float4 v = *(const float4*)(src + i);
    float vv[4] = {v.x, v.y, v.z, v.w};
    ushort4 H, Lo;
    unsigned short* hp = &H.x;
    unsigned short* lp = &Lo.x;
    #pragma unroll
    for (int j = 0; j < 4; j++) {
        __half h = __float2half(vv[j]);
        float res = vv[j] - __half2float(h);
        hp[j] = __half_as_ushort(h);
        lp[j] = __half_as_ushort(__float2half(res));
    }
    *(ushort4*)(hi + i) = H;
    *(ushort4*)(lo + i) = Lo;
}

// ---------------------------------------------------------------------------
__global__ void wtrans(const float* __restrict__ W,
                       __half* __restrict__ T, int N) {
    __shared__ float t[32][33];
    const int tx = threadIdx.x, ty = threadIdx.y;
    const int n0 = blockIdx.x * 32, k0 = blockIdx.y * 32;
    #pragma unroll
    for (int i = 0; i < 4; i++) {
        int r = ty + i * 8;
        t[r][tx] = W[(size_t)(k0 + r) * N + n0 + tx];
    }
    __syncthreads();
    #pragma unroll
    for (int i = 0; i < 4; i++) {
        int r = ty + i * 8;
        T[(size_t)(n0 + r) * DIM_ + k0 + tx] = __float2half(t[tx][r]);
    }
}

// ---------------------------------------------------------------------------
__global__ __launch_bounds__(256) void rmsrope_kernel(const float* __restrict__ gq,
                                                      const float* __restrict__ gk) {
    const int gw   = blockIdx.x * 8 + (threadIdx.x >> 5);
    const int lane = threadIdx.x & 31;

    float* row;
    const float* g;
    int tok;
    if (gw < NTOK * NH) {
        tok = gw >> 4;
        int h = gw & 15;
        row = g_qkv + (size_t)tok * QKVW + h * HD;
        g   = gq;
    } else {
        int r = gw - NTOK * NH;
        tok = r >> 2;
        int hk = r & 3;
        row = g_qkv + (size_t)tok * QKVW + 1024 + hk * HD;
        g   = gk;
    }
    const int pos = tok & (L_ - 1);

    float2 v = ((const float2*)row)[lane];
    float ss = v.x * v.x + v.y * v.y;
    #pragma unroll
    for (int off = 16; off > 0; off >>= 1)
        ss += __shfl_xor_sync(0xffffffffu, ss, off);
    float rn = rsqrtf(ss * (1.0f / 64.0f) + 1e-6f);

    float2 gg = ((const float2*)g)[lane];
    float t1 = v.x * rn * gg.x;
    float t2 = v.y * rn * gg.y;

    float inv_freq = exp2f((float)lane * (-13.287712379549449f / 32.0f));
    float ang = (float)pos * inv_freq;
    float s, c;
    sincosf(ang, &s, &c);

    ((float2*)row)[lane] = make_float2(t1 * c - t2 * s, t1 * s + t2 * c);
}

// ---------------------------------------------------------------------------
// HMMA flash attention, fp16: S = (Qh+Ql)K, O = P(hi only) V; K,V single fp16.
// Block = q-tile(64) x 4 heads of one kv group; 8 warps = (head, m-half).
// Output written as single fp16 (g_ao).
// ---------------------------------------------------------------------------
#define AP      72
#define QH_OFF  0
#define QL_OFF  (4*64*AP)              // 18432
#define KH_OFF  (2*QL_OFF)             // 36864
#define VH_OFF  (KH_OFF + 64*AP)       // 41472
#define P_OFF   (VH_OFF + 64*AP)       // 46080
#define PW_SZ   (32*AP)                // 2304
#define FSMEM   ((P_OFF + 8*PW_SZ)*2)  // 129024 bytes

__global__ __launch_bounds__(256, 1) void fattn_kernel() {
    extern __shared__ __align__(16) __half fsm[];

    const int tid   = threadIdx.x;
    const int w     = tid >> 5;
    const int lane  = tid & 31;
    const int t     = blockIdx.x;
    const int bz    = blockIdx.y;
    const int b     = bz >> 2;
    const int hk    = bz & 3;
    const int hl    = w >> 1;
    const int h     = hk * 4 + hl;
    const int mhalf = w & 1;
    const uint32_t smb = smem_u32(fsm);

    // ---- load Q (4 heads): scale 1/8, split fp16 hi/lo ----
    #pragma unroll
    for (int u = 0; u < 8; u++) {
        int idx = tid + (u << 8);
        int hh  = idx >> 9;
        int rem = idx & 511;
        int row = rem >> 3, c8 = (rem & 7) << 3;
        const float* src = g_qkv + (size_t)(b * L_ + t * 64 + row) * QKVW
                         + (hk * 4 + hh) * 64 + c8;
        float4 v0 = *(const float4*)src, v1 = *(const float4*)(src + 4);
        float f[8] = {v0.x, v0.y, v0.z, v0.w, v1.x, v1.y, v1.z, v1.w};
        uint32_t hi[4], lo[4];
        #pragma unroll
        for (int j = 0; j < 4; j++) {
            float a = f[2*j] * 0.125f, c = f[2*j+1] * 0.125f;
            __half ha = __float2half(a), hc = __float2half(c);
            hi[j] = pack2h(ha, hc);
            lo[j] = pack2h(__float2half(a - __half2float(ha)),
                           __float2half(c - __half2float(hc)));
        }
        int off = hh * 64 * AP + row * AP + c8;
        *(uint4*)(fsm + QH_OFF + off) = make_uint4(hi[0], hi[1], hi[2], hi[3]);
        *(uint4*)(fsm + QL_OFF + off) = make_uint4(lo[0], lo[1], lo[2], lo[3]);
    }

    float sO[2][8][4];
    #pragma unroll
    for (int i = 0; i < 2; i++)
        #pragma unroll
        for (int j = 0; j < 8; j++)
            #pragma unroll
            for (int r = 0; r < 4; r++) sO[i][j][r] = 0.0f;
    float ms[2][2] = {{-1e30f, -1e30f}, {-1e30f, -1e30f}};
    float ssum[2][2] = {{0.0f, 0.0f}, {0.0f, 0.0f}};

    const uint32_t pw = P_OFF + w * PW_SZ;

    auto do_chunk = [&](int kb, bool partial) {
        __syncthreads();
        // ---- convert K/V chunk to fp16 smem ----
        #pragma unroll
        for (int u = 0; u < 2; u++) {
            int c = (tid << 1) + u;
            int row = c >> 3, c8 = (c & 7) << 3;
            const float* base = g_qkv + (size_t)(b * L_ + kb + row) * QKVW
                              + 1024 + hk * 64 + c8;
            float4 k0 = *(const float4*)base, k1 = *(const float4*)(base + 4);
            float4 q0 = *(const float4*)(base + 256), q1 = *(const float4*)(base + 260);
            float fk[8] = {k0.x, k0.y, k0.z, k0.w, k1.x, k1.y, k1.z, k1.w};
            float fv[8] = {q0.x, q0.y, q0.z, q0.w, q1.x, q1.y, q1.z, q1.w};
            uint32_t kh[4], vh[4];
            #pragma unroll
            for (int j = 0; j < 4; j++) {
                kh[j] = pack2h(__float2half(fk[2*j]), __float2half(fk[2*j+1]));
                vh[j] = pack2h(__float2half(fv[2*j]), __float2half(fv[2*j+1]));
            }
            int off = row * AP + c8;
            *(uint4*)(fsm + KH_OFF + off) = make_uint4(kh[0], kh[1], kh[2], kh[3]);
            *(uint4*)(fsm + VH_OFF + off) = make_uint4(vh[0], vh[1], vh[2], vh[3]);
        }
        __syncthreads();

        // ---- S = (Qh + Ql) K^T ----
        float sS[2][8][4];
        #pragma unroll
        for (int i = 0; i < 2; i++)
            #pragma unroll
            for (int j = 0; j < 8; j++)
                #pragma unroll
                for (int r = 0; r < 4; r++) sS[i][j][r] = 0.0f;

        #pragma unroll
        for (int kt = 0; kt < 4; kt++) {
            uint32_t ah[2][4], al[2][4], bh[4][4];
            #pragma unroll
            for (int mt = 0; mt < 2; mt++) {
                uint32_t ao = smb + 2 * (QH_OFF + hl * 64 * AP
                    + (mhalf * 32 + mt * 16 + (lane & 15)) * AP
                    + kt * 16 + ((lane >> 4) << 3));
                ldm4(ah[mt], ao);
                ldm4(al[mt], ao + 2 * QL_OFF);
            }
            #pragma unroll
            for (int pr = 0; pr < 4; pr++) {
                uint32_t bo = smb + 2 * (KH_OFF
                    + (pr * 16 + (lane & 7) + ((lane >> 4) & 1) * 8) * AP
                    + kt * 16 + (((lane >> 3) & 1) << 3));
                ldm4(bh[pr], bo);
            }
            #pragma unroll
            for (int mt = 0; mt < 2; mt++)
                #pragma unroll
                for (int nt = 0; nt < 8; nt++) {
                    const uint32_t* f = bh[nt >> 1];
                    mma16816(sS[mt][nt], ah[mt], (nt & 1) ? f[2] : f[0],
                             (nt & 1) ? f[3] : f[1]);
                }
            #pragma unroll
            for (int mt = 0; mt < 2; mt++)
                #pragma unroll
                for (int nt = 0; nt < 8; nt++) {
                    const uint32_t* f = bh[nt >> 1];
                    mma16816(sS[mt][nt], al[mt], (nt & 1) ? f[2] : f[0],
                             (nt & 1) ? f[3] : f[1]);
                }
        }

        if (partial) {
            #pragma unroll
            for (int mt = 0; mt < 2; mt++)
                #pragma unroll
                for (int rh = 0; rh < 2; rh++) {
                    int iq = t * 64 + mhalf * 32 + mt * 16 + (lane >> 2) + rh * 8;
                    #pragma unroll
                    for (int nt = 0; nt < 8; nt++)
                        #pragma unroll
                        for (int c = 0; c < 2; c++) {
                            int j = kb + nt * 8 + (lane & 3) * 2 + c;
                            bool valid = (j <= iq) && ((j >= iq - 256) || (j < 64));
                            if (!valid) sS[mt][nt][rh * 2 + c] = -INFINITY;
                        }
                }
        }

        // ---- online softmax ----
        #pragma unroll
        for (int mt = 0; mt < 2; mt++)
            #pragma unroll
            for (int rh = 0; rh < 2; rh++) {
                float rmax = -INFINITY;
                #pragma unroll
                for (int nt = 0; nt < 8; nt++)
                    rmax = fmaxf(rmax, fmaxf(sS[mt][nt][rh*2], sS[mt][nt][rh*2+1]));
                rmax = fmaxf(rmax, __shfl_xor_sync(0xffffffffu, rmax, 1));
                rmax = fmaxf(rmax, __shfl_xor_sync(0xffffffffu, rmax, 2));
                float mn = fmaxf(ms[mt][rh], rmax);
                float corr = __expf(ms[mt][rh] - mn);
                float rs = 0.0f;
                #pragma unroll
                for (int nt = 0; nt < 8; nt++) {
                    float e0 = __expf(sS[mt][nt][rh*2]     - mn);
                    float e1 = __expf(sS[mt][nt][rh*2 + 1] - mn);
                    sS[mt][nt][rh*2] = e0; sS[mt][nt][rh*2+1] = e1;
                    sO[mt][nt][rh*2]   *= corr;
                    sO[mt][nt][rh*2+1] *= corr;
                    rs += e0 + e1;
                }
                rs += __shfl_xor_sync(0xffffffffu, rs, 1);
                rs += __shfl_xor_sync(0xffffffffu, rs, 2);
                ssum[mt][rh] = ssum[mt][rh] * corr + rs;
                ms[mt][rh] = mn;
            }

        // ---- P (fp16) x V ----
        #pragma unroll
        for (int mt = 0; mt < 2; mt++)
            #pragma unroll
            for (int rh = 0; rh < 2; rh++)
                #pragma unroll
                for (int nt = 0; nt < 8; nt++) {
                    float e0 = sS[mt][nt][rh*2], e1 = sS[mt][nt][rh*2+1];
                    uint32_t pk = pack2h(__float2half(e0), __float2half(e1));
                    uint32_t off = pw + (mt * 16 + (lane >> 2) + rh * 8) * AP
                                 + nt * 8 + (lane & 3) * 2;
                    *(uint32_t*)((char*)fsm + 2 * off) = pk;
                }
        __syncwarp();
        #pragma unroll
        for (int kt = 0; kt < 4; kt++) {
            uint32_t ap[2][4], vh[4][4];
            #pragma unroll
            for (int mt = 0; mt < 2; mt++) {
                uint32_t ao = smb + 2 * (pw + (mt * 16 + (lane & 15)) * AP
                                         + kt * 16 + ((lane >> 4) << 3));
                ldm4(ap[mt], ao);
            }
            #pragma unroll
            for (int pr = 0; pr < 4; pr++) {
                uint32_t bo = smb + 2 * (VH_OFF
                    + (kt * 16 + (lane & 7) + ((lane >> 3) & 1) * 8) * AP
                    + pr * 16 + (((lane >> 4) & 1) << 3));
                ldm4t(vh[pr], bo);
            }
            #pragma unroll
            for (int mt = 0; mt < 2; mt++)
                #pragma unroll
                for (int nt = 0; nt < 8; nt++) {
                    const uint32_t* f = vh[nt >> 1];
                    mma16816(sO[mt][nt], ap[mt], (nt & 1) ? f[2] : f[0],
                             (nt & 1) ? f[3] : f[1]);
                }
        }
        __syncwarp();
    };

    if (t > 4) do_chunk(0, false);
    int c0 = t - 4; if (c0 < 0) c0 = 0;
    for (int cc = c0; cc <= t; cc++) {
        bool partial = (cc == t) || (t >= 5 && cc == t - 4);
        do_chunk(cc * 64, partial);
    }

    // ---- epilogue: normalize, write single fp16 ----
    #pragma unroll
    for (int mt = 0; mt < 2; mt++)
        #pragma unroll
        for (int rh = 0; rh < 2; rh++) {
            float inv = 1.0f / ssum[mt][rh];
            int tok = b * L_ + t * 64 + mhalf * 32 + mt * 16 + (lane >> 2) + rh * 8;
            #pragma unroll
            for (int nt = 0; nt < 8; nt++) {
                float v0 = sO[mt][nt][rh*2]     * inv;
                float v1 = sO[mt][nt][rh*2 + 1] * inv;
                size_t o = (size_t)tok * DIM_ + h * 64 + nt * 8 + (lane & 3) * 2;
                *(uint32_t*)&g_ao[o] = pack2h(__float2half(v0), __float2half(v1));
            }
        }
}

// ---------------------------------------------------------------------------
extern "C" void kernel_launch(void* const* d_in, const int* in_sizes, int n_in,
                              void* d_out, int out_size) {
    const float* x  = (const float*)d_in[0];
    const float* wq = (const float*)d_in[1];
    const float* wk = (const float*)d_in[2];
    const float* wv = (const float*)d_in[3];
    const float* wo = (const float*)d_in[4];
    const float* gq = (const float*)d_in[5];
    const float* gk = (const float*)d_in[6];

    float *qkv;
    __half *xh, *xl, *ao, *wt, *wot;
    cudaGetSymbolAddress((void**)&qkv, g_qkv);
    cudaGetSymbolAddress((void**)&xh,  g_xh);
    cudaGetSymbolAddress((void**)&xl,  g_xl);
    cudaGetSymbolAddress((void**)&ao,  g_ao);
    cudaGetSymbolAddress((void**)&wt,  g_wt);
    cudaGetSymbolAddress((void**)&wot, g_wot);

    cudaFuncSetAttribute(hmma_gemm2, cudaFuncAttributeMaxDynamicSharedMemorySize,
                         GSMEM2);
    cudaFuncSetAttribute(hmma_gemm1, cudaFuncAttributeMaxDynamicSharedMemorySize,
                         GSMEM1);
    cudaFuncSetAttribute(fattn_kernel, cudaFuncAttributeMaxDynamicSharedMemorySize,
                         FSMEM);

    // input split / fused weight transpose
    split4<<<NTOK * DIM_ / 1024, 256>>>(x, xh, xl);
    wtrans<<<dim3(DIM_ / 32, 32), dim3(32, 8)>>>(wq, wt, DIM_);
    wtrans<<<dim3(256 / 32, 32), dim3(32, 8)>>>(wk, wt + 1024 * DIM_, 256);
    wtrans<<<dim3(256 / 32, 32), dim3(32, 8)>>>(wv, wt + 1280 * DIM_, 256);
    wtrans<<<dim3(DIM_ / 32, 32), dim3(32, 8)>>>(wo, wot, DIM_);

    // fused Q|K|V projection (2-term activations)
    hmma_gemm2<<<dim3(QKVW / 128, NTOK / 128), 256, GSMEM2>>>(xh, xl, wt, qkv, QKVW);

    // RMSNorm + RoPE (q and k in place)
    const int nrows = NTOK * NH + NTOK * NKV;
    rmsrope_kernel<<<nrows / 8, 256>>>(gq, gk);

    // flash attention (writes g_ao fp16)
    fattn_kernel<<<dim3(32, 8), 256, FSMEM>>>();

    // output projection (1-term activations)
    hmma_gemm1<<<dim3(DIM_ / 128, NTOK / 128), 256, GSMEM1>>>(ao, wot,
                                                              (float*)d_out, DIM_);
}

// round 15
// speedup vs baseline: 5.2089x; 1.1896x over previous
#include <cuda_runtime.h>
#include <cuda_fp16.h>
#include <cstdint>
#include <math.h>

#define B_    2
#define L_    2048
#define DIM_  1024
#define NH    16
#define NKV   4
#define HD    64
#define NTOK  (B_*L_)       // 4096
#define QKVW  1536          // fused q|k|v row width

// ------------------------- scratch (__device__, no mallocs) -----------------
__device__ __align__(16) float g_qkv[NTOK*QKVW];   // Q(0..1023)|K(1024..1279)|V(1280..1535)

__device__ __align__(16) __half g_xh [NTOK*DIM_];  // x, single fp16
__device__ __align__(16) __half g_ao [NTOK*DIM_];  // attention out, single fp16

__device__ __align__(16) __half g_wt  [QKVW*DIM_]; // [n][k] fused wq|wk|wv, fp16
__device__ __align__(16) __half g_wot [DIM_*DIM_]; // [n][k] wo, fp16

// ------------------------- helpers ------------------------------------------
__device__ __forceinline__ uint32_t smem_u32(const void* p) {
    uint32_t a;
    asm("{ .reg .u64 t; cvta.to.shared.u64 t, %1; cvt.u32.u64 %0, t; }"
        : "=r"(a) : "l"(p));
    return a;
}
__device__ __forceinline__ void ldm4(uint32_t f[4], uint32_t addr) {
    asm volatile("ldmatrix.sync.aligned.m8n8.x4.shared.b16 {%0,%1,%2,%3}, [%4];"
                 : "=r"(f[0]), "=r"(f[1]), "=r"(f[2]), "=r"(f[3]) : "r"(addr));
}
__device__ __forceinline__ void ldm4t(uint32_t f[4], uint32_t addr) {
    asm volatile("ldmatrix.sync.aligned.m8n8.x4.trans.shared.b16 {%0,%1,%2,%3}, [%4];"
                 : "=r"(f[0]), "=r"(f[1]), "=r"(f[2]), "=r"(f[3]) : "r"(addr));
}
__device__ __forceinline__ void mma16816(float c[4], const uint32_t a[4],
                                         uint32_t b0, uint32_t b1) {
    asm volatile("mma.sync.aligned.m16n8k16.row.col.f32.f16.f16.f32 "
                 "{%0,%1,%2,%3},{%4,%5,%6,%7},{%8,%9},{%0,%1,%2,%3};"
                 : "+f"(c[0]), "+f"(c[1]), "+f"(c[2]), "+f"(c[3])
                 : "r"(a[0]), "r"(a[1]), "r"(a[2]), "r"(a[3]), "r"(b0), "r"(b1));
}
__device__ __forceinline__ uint32_t pack2h(__half a, __half b) {
    return (uint32_t)__half_as_ushort(a) |
           ((uint32_t)__half_as_ushort(b) << 16);
}
__device__ __forceinline__ void cp16(uint32_t saddr, const void* gptr) {
    asm volatile("cp.async.cg.shared.global [%0], [%1], 16;"
                 :: "r"(saddr), "l"(gptr));
}
#define CP_COMMIT() asm volatile("cp.async.commit_group;" ::: "memory")
#define CP_WAIT(n)  asm volatile("cp.async.wait_group %0;" :: "n"(n) : "memory")

#define PITCH     40
#define TILE_H    (128*PITCH)          // 5120 halfs / tile
#define TILE_BY   (TILE_H*2)           // 10240 bytes
#define NKB       (DIM_/32)            // 32

// ---------------------------------------------------------------------------
// HMMA 1-term fp16 GEMM: C = A @ B^T, fp32 accum. cp.async 3-stage ring.
// Block 128x128, BK=32, 256 threads (8 warps 4x2), warp tile 32x64.
// ---------------------------------------------------------------------------
#define BUF1_BY   (2*TILE_BY)          // A, B
#define GSMEM1    (3*BUF1_BY)          // 61440 bytes

__global__ __launch_bounds__(256) void hmma_gemm1(const __half* __restrict__ A_,
                                                  const __half* __restrict__ B_arr,
                                                  float* __restrict__ C, int Ncols) {
    extern __shared__ __align__(128) __half sm[];

    const int tid  = threadIdx.x;
    const int wid  = tid >> 5;
    const int lane = tid & 31;
    const int wm   = (wid & 3) * 32;
    const int wn   = (wid >> 2) * 64;
    const int m0   = blockIdx.y * 128;
    const int n0   = blockIdx.x * 128;

    const uint32_t smb = smem_u32(sm);

    uint32_t aoff[2], boff[4];
    #pragma unroll
    for (int mt = 0; mt < 2; mt++)
        aoff[mt] = ((wm + mt * 16 + (lane & 15)) * PITCH + ((lane >> 4) << 3)) * 2;
    #pragma unroll
    for (int pr = 0; pr < 4; pr++)
        boff[pr] = ((wn + pr * 16 + (lane & 7) + ((lane >> 4) & 1) * 8) * PITCH
                    + (((lane >> 3) & 1) << 3)) * 2;

    float acc[2][8][4];
    #pragma unroll
    for (int i = 0; i < 2; i++)
        #pragma unroll
        for (int j = 0; j < 8; j++)
            #pragma unroll
            for (int r = 0; r < 4; r++) acc[i][j][r] = 0.0f;

    const int r0  = (tid * 2)     >> 2, c80 = ((tid * 2)     & 3) << 3;
    const int r1  = (tid * 2 + 1) >> 2, c81 = ((tid * 2 + 1) & 3) << 3;
    const uint32_t so0 = (r0 * PITCH + c80) * 2;
    const uint32_t so1 = (r1 * PITCH + c81) * 2;

    auto stage = [&](int kb, int buf) {
        const int k0 = kb << 5;
        const uint32_t sb = smb + buf * BUF1_BY;
        size_t goA0 = (size_t)(m0 + r0) * DIM_ + k0 + c80;
        size_t goB0 = (size_t)(n0 + r0) * DIM_ + k0 + c80;
        size_t goA1 = (size_t)(m0 + r1) * DIM_ + k0 + c81;
        size_t goB1 = (size_t)(n0 + r1) * DIM_ + k0 + c81;
        cp16(sb + so0,           A_    + goA0);
        cp16(sb + TILE_BY + so0, B_arr + goB0);
        cp16(sb + so1,           A_    + goA1);
        cp16(sb + TILE_BY + so1, B_arr + goB1);
        CP_COMMIT();
    };

    stage(0, 0);
    stage(1, 1);

    int buf = 0;
    #pragma unroll 1
    for (int kb = 0; kb < NKB; kb++) {
        if (kb + 1 < NKB) CP_WAIT(1); else CP_WAIT(0);
        __syncthreads();

        const uint32_t sb = smb + buf * BUF1_BY;
        #pragma unroll
        for (int ks = 0; ks < 2; ks++) {
            uint32_t ah[2][4], bh[4][4];
            #pragma unroll
            for (int mt = 0; mt < 2; mt++)
                ldm4(ah[mt], sb + aoff[mt] + ks * 32);
            #pragma unroll
            for (int pr = 0; pr < 4; pr++)
                ldm4(bh[pr], sb + boff[pr] + ks * 32 + TILE_BY);
            #pragma unroll
            for (int mt = 0; mt < 2; mt++)
                #pragma unroll
                for (int nt = 0; nt < 8; nt++) {
                    const uint32_t* f = bh[nt >> 1];
                    mma16816(acc[mt][nt], ah[mt], (nt & 1) ? f[2] : f[0],
                             (nt & 1) ? f[3] : f[1]);
                }
        }
        __syncthreads();
        if (kb + 2 < NKB) stage(kb + 2, (kb + 2) % 3);
        buf = (buf + 1 == 3) ? 0 : buf + 1;
    }

    #pragma unroll
    for (int mt = 0; mt < 2; mt++) {
        const int row = m0 + wm + mt * 16 + (lane >> 2);
        #pragma unroll
        for (int nt = 0; nt < 8; nt++) {
            const int col = n0 + wn + nt * 8 + (lane & 3) * 2;
            float2 lo; lo.x = acc[mt][nt][0]; lo.y = acc[mt][nt][1];
            float2 hi; hi.x = acc[mt][nt][2]; hi.y = acc[mt][nt][3];
            *(float2*)&C[(size_t)row * Ncols + col]       = lo;
            *(float2*)&C[(size_t)(row + 8) * Ncols + col] = hi;
        }
    }
}

// ---------------------------------------------------------------------------
// fp32 -> fp16 convert (4 elems/thread)
// ---------------------------------------------------------------------------
__global__ __launch_bounds__(256) void cvt16(const float* __restrict__ src,
                                             __half* __restrict__ dst) {
    size_t i = ((size_t)blockIdx.x * 256 + threadIdx.x) * 4;
    float4 v = *(const float4*)(src + i);
    ushort4 H;
    H.x = __half_as_ushort(__float2half(v.x));
    H.y = __half_as_ushort(__float2half(v.y));
    H.z = __half_as_ushort(__float2half(v.z));
    H.w = __half_as_ushort(__float2half(v.w));
    *(ushort4*)(dst + i) = H;
}

// ---------------------------------------------------------------------------
// Weight transpose: W[1024][N] fp32 -> T[N][1024] fp16 single.
// ---------------------------------------------------------------------------
__global__ void wtrans(const float* __restrict__ W,
                       __half* __restrict__ T, int N) {
    __shared__ float t[32][33];
    const int tx = threadIdx.x, ty = threadIdx.y;
    const int n0 = blockIdx.x * 32, k0 = blockIdx.y * 32;
    #pragma unroll
    for (int i = 0; i < 4; i++) {
        int r = ty + i * 8;
        t[r][tx] = W[(size_t)(k0 + r) * N + n0 + tx];
    }
    __syncthreads();
    #pragma unroll
    for (int i = 0; i < 4; i++) {
        int r = ty + i * 8;
        T[(size_t)(n0 + r) * DIM_ + k0 + tx] = __float2half(t[tx][r]);
    }
}

// ---------------------------------------------------------------------------
// RMSNorm + RoPE in place on fused g_qkv (Q cols 0..1023, K cols 1024..1279).
// ---------------------------------------------------------------------------
__global__ __launch_bounds__(256) void rmsrope_kernel(const float* __restrict__ gq,
                                                      const float* __restrict__ gk) {
    const int gw   = blockIdx.x * 8 + (threadIdx.x >> 5);
    const int lane = threadIdx.x & 31;

    float* row;
    const float* g;
    int tok;
    if (gw < NTOK * NH) {
        tok = gw >> 4;
        int h = gw & 15;
        row = g_qkv + (size_t)tok * QKVW + h * HD;
        g   = gq;
    } else {
        int r = gw - NTOK * NH;
        tok = r >> 2;
        int hk = r & 3;
        row = g_qkv + (size_t)tok * QKVW + 1024 + hk * HD;
        g   = gk;
    }
    const int pos = tok & (L_ - 1);

    float2 v = ((const float2*)row)[lane];
    float ss = v.x * v.x + v.y * v.y;
    #pragma unroll
    for (int off = 16; off > 0; off >>= 1)
        ss += __shfl_xor_sync(0xffffffffu, ss, off);
    float rn = rsqrtf(ss * (1.0f / 64.0f) + 1e-6f);

    float2 gg = ((const float2*)g)[lane];
    float t1 = v.x * rn * gg.x;
    float t2 = v.y * rn * gg.y;

    float inv_freq = exp2f((float)lane * (-13.287712379549449f / 32.0f));
    float ang = (float)pos * inv_freq;
    float s, c;
    sincosf(ang, &s, &c);

    ((float2*)row)[lane] = make_float2(t1 * c - t2 * s, t1 * s + t2 * c);
}

// ---------------------------------------------------------------------------
// HMMA flash attention, fp16: S = (Qh+Ql)K, O = P V; K,V single fp16.
// Block = q-tile(64) x 4 heads of one kv group; 8 warps = (head, m-half).
// ---------------------------------------------------------------------------
#define AP      72
#define QH_OFF  0
#define QL_OFF  (4*64*AP)              // 18432
#define KH_OFF  (2*QL_OFF)             // 36864
#define VH_OFF  (KH_OFF + 64*AP)       // 41472
#define P_OFF   (VH_OFF + 64*AP)       // 46080
#define PW_SZ   (32*AP)                // 2304
#define FSMEM   ((P_OFF + 8*PW_SZ)*2)  // 129024 bytes

__global__ __launch_bounds__(256, 1) void fattn_kernel() {
    extern __shared__ __align__(16) __half fsm[];

    const int tid   = threadIdx.x;
    const int w     = tid >> 5;
    const int lane  = tid & 31;
    const int t     = blockIdx.x;
    const int bz    = blockIdx.y;
    const int b     = bz >> 2;
    const int hk    = bz & 3;
    const int hl    = w >> 1;
    const int h     = hk * 4 + hl;
    const int mhalf = w & 1;
    const uint32_t smb = smem_u32(fsm);

    // ---- load Q (4 heads): scale 1/8, split fp16 hi/lo ----
    #pragma unroll
    for (int u = 0; u < 8; u++) {
        int idx = tid + (u << 8);
        int hh  = idx >> 9;
        int rem = idx & 511;
        int row = rem >> 3, c8 = (rem & 7) << 3;
        const float* src = g_qkv + (size_t)(b * L_ + t * 64 + row) * QKVW
                         + (hk * 4 + hh) * 64 + c8;
        float4 v0 = *(const float4*)src, v1 = *(const float4*)(src + 4);
        float f[8] = {v0.x, v0.y, v0.z, v0.w, v1.x, v1.y, v1.z, v1.w};
        uint32_t hi[4], lo[4];
        #pragma unroll
        for (int j = 0; j < 4; j++) {
            float a = f[2*j] * 0.125f, c = f[2*j+1] * 0.125f;
            __half ha = __float2half(a), hc = __float2half(c);
            hi[j] = pack2h(ha, hc);
            lo[j] = pack2h(__float2half(a - __half2float(ha)),
                           __float2half(c - __half2float(hc)));
        }
        int off = hh * 64 * AP + row * AP + c8;
        *(uint4*)(fsm + QH_OFF + off) = make_uint4(hi[0], hi[1], hi[2], hi[3]);
        *(uint4*)(fsm + QL_OFF + off) = make_uint4(lo[0], lo[1], lo[2], lo[3]);
    }

    float sO[2][8][4];
    #pragma unroll
    for (int i = 0; i < 2; i++)
        #pragma unroll
        for (int j = 0; j < 8; j++)
            #pragma unroll
            for (int r = 0; r < 4; r++) sO[i][j][r] = 0.0f;
    float ms[2][2] = {{-1e30f, -1e30f}, {-1e30f, -1e30f}};
    float ssum[2][2] = {{0.0f, 0.0f}, {0.0f, 0.0f}};

    const uint32_t pw = P_OFF + w * PW_SZ;

    auto do_chunk = [&](int kb, bool partial) {
        __syncthreads();
        // ---- convert K/V chunk to fp16 smem ----
        #pragma unroll
        for (int u = 0; u < 2; u++) {
            int c = (tid << 1) + u;
            int row = c >> 3, c8 = (c & 7) << 3;
            const float* base = g_qkv + (size_t)(b * L_ + kb + row) * QKVW
                              + 1024 + hk * 64 + c8;
            float4 k0 = *(const float4*)base, k1 = *(const float4*)(base + 4);
            float4 q0 = *(const float4*)(base + 256), q1 = *(const float4*)(base + 260);
            float fk[8] = {k0.x, k0.y, k0.z, k0.w, k1.x, k1.y, k1.z, k1.w};
            float fv[8] = {q0.x, q0.y, q0.z, q0.w, q1.x, q1.y, q1.z, q1.w};
            uint32_t kh[4], vh[4];
            #pragma unroll
            for (int j = 0; j < 4; j++) {
                kh[j] = pack2h(__float2half(fk[2*j]), __float2half(fk[2*j+1]));
                vh[j] = pack2h(__float2half(fv[2*j]), __float2half(fv[2*j+1]));
            }
            int off = row * AP + c8;
            *(uint4*)(fsm + KH_OFF + off) = make_uint4(kh[0], kh[1], kh[2], kh[3]);
            *(uint4*)(fsm + VH_OFF + off) = make_uint4(vh[0], vh[1], vh[2], vh[3]);
        }
        __syncthreads();

        // ---- S = (Qh + Ql) K^T ----
        float sS[2][8][4];
        #pragma unroll
        for (int i = 0; i < 2; i++)
            #pragma unroll
            for (int j = 0; j < 8; j++)
                #pragma unroll
                for (int r = 0; r < 4; r++) sS[i][j][r] = 0.0f;

        #pragma unroll
        for (int kt = 0; kt < 4; kt++) {
            uint32_t ah[2][4], al[2][4], bh[4][4];
            #pragma unroll
            for (int mt = 0; mt < 2; mt++) {
                uint32_t ao = smb + 2 * (QH_OFF + hl * 64 * AP
                    + (mhalf * 32 + mt * 16 + (lane & 15)) * AP
                    + kt * 16 + ((lane >> 4) << 3));
                ldm4(ah[mt], ao);
                ldm4(al[mt], ao + 2 * QL_OFF);
            }
            #pragma unroll
            for (int pr = 0; pr < 4; pr++) {
                uint32_t bo = smb + 2 * (KH_OFF
                    + (pr * 16 + (lane & 7) + ((lane >> 4) & 1) * 8) * AP
                    + kt * 16 + (((lane >> 3) & 1) << 3));
                ldm4(bh[pr], bo);
            }
            #pragma unroll
            for (int mt = 0; mt < 2; mt++)
                #pragma unroll
                for (int nt = 0; nt < 8; nt++) {
                    const uint32_t* f = bh[nt >> 1];
                    mma16816(sS[mt][nt], ah[mt], (nt & 1) ? f[2] : f[0],
                             (nt & 1) ? f[3] : f[1]);
                }
            #pragma unroll
            for (int mt = 0; mt < 2; mt++)
                #pragma unroll
                for (int nt = 0; nt < 8; nt++) {
                    const uint32_t* f = bh[nt >> 1];
                    mma16816(sS[mt][nt], al[mt], (nt & 1) ? f[2] : f[0],
                             (nt & 1) ? f[3] : f[1]);
                }
        }

        if (partial) {
            #pragma unroll
            for (int mt = 0; mt < 2; mt++)
                #pragma unroll
                for (int rh = 0; rh < 2; rh++) {
                    int iq = t * 64 + mhalf * 32 + mt * 16 + (lane >> 2) + rh * 8;
                    #pragma unroll
                    for (int nt = 0; nt < 8; nt++)
                        #pragma unroll
                        for (int c = 0; c < 2; c++) {
                            int j = kb + nt * 8 + (lane & 3) * 2 + c;
                            bool valid = (j <= iq) && ((j >= iq - 256) || (j < 64));
                            if (!valid) sS[mt][nt][rh * 2 + c] = -INFINITY;
                        }
                }
        }

        // ---- online softmax ----
        #pragma unroll
        for (int mt = 0; mt < 2; mt++)
            #pragma unroll
            for (int rh = 0; rh < 2; rh++) {
                float rmax = -INFINITY;
                #pragma unroll
                for (int nt = 0; nt < 8; nt++)
                    rmax = fmaxf(rmax, fmaxf(sS[mt][nt][rh*2], sS[mt][nt][rh*2+1]));
                rmax = fmaxf(rmax, __shfl_xor_sync(0xffffffffu, rmax, 1));
                rmax = fmaxf(rmax, __shfl_xor_sync(0xffffffffu, rmax, 2));
                float mn = fmaxf(ms[mt][rh], rmax);
                float corr = __expf(ms[mt][rh] - mn);
                float rs = 0.0f;
                #pragma unroll
                for (int nt = 0; nt < 8; nt++) {
                    float e0 = __expf(sS[mt][nt][rh*2]     - mn);
                    float e1 = __expf(sS[mt][nt][rh*2 + 1] - mn);
                    sS[mt][nt][rh*2] = e0; sS[mt][nt][rh*2+1] = e1;
                    sO[mt][nt][rh*2]   *= corr;
                    sO[mt][nt][rh*2+1] *= corr;
                    rs += e0 + e1;
                }
                rs += __shfl_xor_sync(0xffffffffu, rs, 1);
                rs += __shfl_xor_sync(0xffffffffu, rs, 2);
                ssum[mt][rh] = ssum[mt][rh] * corr + rs;
                ms[mt][rh] = mn;
            }

        // ---- P (fp16) x V ----
        #pragma unroll
        for (int mt = 0; mt < 2; mt++)
            #pragma unroll
            for (int rh = 0; rh < 2; rh++)
                #pragma unroll
                for (int nt = 0; nt < 8; nt++) {
                    float e0 = sS[mt][nt][rh*2], e1 = sS[mt][nt][rh*2+1];
                    uint32_t pk = pack2h(__float2half(e0), __float2half(e1));
                    uint32_t off = pw + (mt * 16 + (lane >> 2) + rh * 8) * AP
                                 + nt * 8 + (lane & 3) * 2;
                    *(uint32_t*)((char*)fsm + 2 * off) = pk;
                }
        __syncwarp();
        #pragma unroll
        for (int kt = 0; kt < 4; kt++) {
            uint32_t ap[2][4], vh[4][4];
            #pragma unroll
            for (int mt = 0; mt < 2; mt++) {
                uint32_t ao = smb + 2 * (pw + (mt * 16 + (lane & 15)) * AP
                                         + kt * 16 + ((lane >> 4) << 3));
                ldm4(ap[mt], ao);
            }
            #pragma unroll
            for (int pr = 0; pr < 4; pr++) {
                uint32_t bo = smb + 2 * (VH_OFF
                    + (kt * 16 + (lane & 7) + ((lane >> 3) & 1) * 8) * AP
                    + pr * 16 + (((lane >> 4) & 1) << 3));
                ldm4t(vh[pr], bo);
            }
            #pragma unroll
            for (int mt = 0; mt < 2; mt++)
                #pragma unroll
                for (int nt = 0; nt < 8; nt++) {
                    const uint32_t* f = vh[nt >> 1];
                    mma16816(sO[mt][nt], ap[mt], (nt & 1) ? f[2] : f[0],
                             (nt & 1) ? f[3] : f[1]);
                }
        }
        __syncwarp();
    };

    if (t > 4) do_chunk(0, false);
    int c0 = t - 4; if (c0 < 0) c0 = 0;
    for (int cc = c0; cc <= t; cc++) {
        bool partial = (cc == t) || (t >= 5 && cc == t - 4);
        do_chunk(cc * 64, partial);
    }

    // ---- epilogue: normalize, write single fp16 ----
    #pragma unroll
    for (int mt = 0; mt < 2; mt++)
        #pragma unroll
        for (int rh = 0; rh < 2; rh++) {
            float inv = 1.0f / ssum[mt][rh];
            int tok = b * L_ + t * 64 + mhalf * 32 + mt * 16 + (lane >> 2) + rh * 8;
            #pragma unroll
            for (int nt = 0; nt < 8; nt++) {
                float v0 = sO[mt][nt][rh*2]     * inv;
                float v1 = sO[mt][nt][rh*2 + 1] * inv;
                size_t o = (size_t)tok * DIM_ + h * 64 + nt * 8 + (lane & 3) * 2;
                *(uint32_t*)&g_ao[o] = pack2h(__float2half(v0), __float2half(v1));
            }
        }
}

// ---------------------------------------------------------------------------
extern "C" void kernel_launch(void* const* d_in, const int* in_sizes, int n_in,
                              void* d_out, int out_size) {
    const float* x  = (const float*)d_in[0];
    const float* wq = (const float*)d_in[1];
    const float* wk = (const float*)d_in[2];
    const float* wv = (const float*)d_in[3];
    const float* wo = (const float*)d_in[4];
    const float* gq = (const float*)d_in[5];
    const float* gk = (const float*)d_in[6];

    float *qkv;
    __half *xh, *ao, *wt, *wot;
    cudaGetSymbolAddress((void**)&qkv, g_qkv);
    cudaGetSymbolAddress((void**)&xh,  g_xh);
    cudaGetSymbolAddress((void**)&ao,  g_ao);
    cudaGetSymbolAddress((void**)&wt,  g_wt);
    cudaGetSymbolAddress((void**)&wot, g_wot);

    cudaFuncSetAttribute(hmma_gemm1, cudaFuncAttributeMaxDynamicSharedMemorySize,
                         GSMEM1);
    cudaFuncSetAttribute(fattn_kernel, cudaFuncAttributeMaxDynamicSharedMemorySize,
                         FSMEM);

    // input convert / fused weight transpose
    cvt16<<<NTOK * DIM_ / 1024, 256>>>(x, xh);
    wtrans<<<dim3(DIM_ / 32, 32), dim3(32, 8)>>>(wq, wt, DIM_);
    wtrans<<<dim3(256 / 32, 32), dim3(32, 8)>>>(wk, wt + 1024 * DIM_, 256);
    wtrans<<<dim3(256 / 32, 32), dim3(32, 8)>>>(wv, wt + 1280 * DIM_, 256);
    wtrans<<<dim3(DIM_ / 32, 32), dim3(32, 8)>>>(wo, wot, DIM_);

    // fused Q|K|V projection (1-term activations)
    hmma_gemm1<<<dim3(QKVW / 128, NTOK / 128), 256, GSMEM1>>>(xh, wt, qkv, QKVW);

    // RMSNorm + RoPE (q and k in place)
    const int nrows = NTOK * NH + NTOK * NKV;
    rmsrope_kernel<<<nrows / 8, 256>>>(gq, gk);

    // flash attention (writes g_ao fp16)
    fattn_kernel<<<dim3(32, 8), 256, FSMEM>>>();

    // output projection (1-term activations)
    hmma_gemm1<<<dim3(DIM_ / 128, NTOK / 128), 256, GSMEM1>>>(ao, wot,
                                                              (float*)d_out, DIM_);
}

// round 16
// speedup vs baseline: 5.5519x; 1.0658x over previous
#include <cuda_runtime.h>
#include <cuda_fp16.h>
#include <cstdint>
#include <math.h>

#define B_    2
#define L_    2048
#define DIM_  1024
#define NH    16
#define NKV   4
#define HD    64
#define NTOK  (B_*L_)       // 4096

// ------------------------- scratch (__device__, no mallocs) -----------------
__device__ __align__(16) float  g_q  [NTOK*DIM_];  // Q, normed+roped, fp32
__device__ __align__(16) __half g_kvh[NTOK*512];   // K roped (0..255) | V (256..511), fp16
__device__ __align__(16) __half g_xh [NTOK*DIM_];  // x, fp16
__device__ __align__(16) __half g_ao [NTOK*DIM_];  // attention out, fp16

__device__ __align__(16) __half g_wt  [1536*DIM_]; // [n][k] fused wq|wk|wv, fp16
__device__ __align__(16) __half g_wot [DIM_*DIM_]; // [n][k] wo, fp16

// ------------------------- helpers ------------------------------------------
__device__ __forceinline__ uint32_t smem_u32(const void* p) {
    uint32_t a;
    asm("{ .reg .u64 t; cvta.to.shared.u64 t, %1; cvt.u32.u64 %0, t; }"
        : "=r"(a) : "l"(p));
    return a;
}
__device__ __forceinline__ void ldm4(uint32_t f[4], uint32_t addr) {
    asm volatile("ldmatrix.sync.aligned.m8n8.x4.shared.b16 {%0,%1,%2,%3}, [%4];"
                 : "=r"(f[0]), "=r"(f[1]), "=r"(f[2]), "=r"(f[3]) : "r"(addr));
}
__device__ __forceinline__ void ldm4t(uint32_t f[4], uint32_t addr) {
    asm volatile("ldmatrix.sync.aligned.m8n8.x4.trans.shared.b16 {%0,%1,%2,%3}, [%4];"
                 : "=r"(f[0]), "=r"(f[1]), "=r"(f[2]), "=r"(f[3]) : "r"(addr));
}
__device__ __forceinline__ void mma16816(float c[4], const uint32_t a[4],
                                         uint32_t b0, uint32_t b1) {
    asm volatile("mma.sync.aligned.m16n8k16.row.col.f32.f16.f16.f32 "
                 "{%0,%1,%2,%3},{%4,%5,%6,%7},{%8,%9},{%0,%1,%2,%3};"
                 : "+f"(c[0]), "+f"(c[1]), "+f"(c[2]), "+f"(c[3])
                 : "r"(a[0]), "r"(a[1]), "r"(a[2]), "r"(a[3]), "r"(b0), "r"(b1));
}
__device__ __forceinline__ uint32_t pack2h(__half a, __half b) {
    return (uint32_t)__half_as_ushort(a) |
           ((uint32_t)__half_as_ushort(b) << 16);
}
__device__ __forceinline__ void cp16(uint32_t saddr, const void* gptr) {
    asm volatile("cp.async.cg.shared.global [%0], [%1], 16;"
                 :: "r"(saddr), "l"(gptr));
}
#define CP_COMMIT() asm volatile("cp.async.commit_group;" ::: "memory")
#define CP_WAIT(n)  asm volatile("cp.async.wait_group %0;" :: "n"(n) : "memory")

#define PITCH     40
#define TILE_H    (128*PITCH)
#define TILE_BY   (TILE_H*2)
#define NKB       (DIM_/32)
#define BUF1_BY   (2*TILE_BY)          // A, B
#define GSMEM1    (3*BUF1_BY)

// ---------------------------------------------------------------------------
// Shared GEMM mainloop body (1-term fp16, cp.async 3-stage) -> acc
// ---------------------------------------------------------------------------
struct GemmCtx {
    float acc[2][8][4];
    int wm, wn, m0, n0, lane;
};

__device__ __forceinline__ void gemm_mainloop(GemmCtx& g, __half* sm,
                                              const __half* __restrict__ A_,
                                              const __half* __restrict__ B_arr) {
    const int tid  = threadIdx.x;
    const int lane = tid & 31;
    const int wm = g.wm, wn = g.wn, m0 = g.m0, n0 = g.n0;
    const uint32_t smb = smem_u32(sm);

    uint32_t aoff[2], boff[4];
    #pragma unroll
    for (int mt = 0; mt < 2; mt++)
        aoff[mt] = ((wm + mt * 16 + (lane & 15)) * PITCH + ((lane >> 4) << 3)) * 2;
    #pragma unroll
    for (int pr = 0; pr < 4; pr++)
        boff[pr] = ((wn + pr * 16 + (lane & 7) + ((lane >> 4) & 1) * 8) * PITCH
                    + (((lane >> 3) & 1) << 3)) * 2;

    #pragma unroll
    for (int i = 0; i < 2; i++)
        #pragma unroll
        for (int j = 0; j < 8; j++)
            #pragma unroll
            for (int r = 0; r < 4; r++) g.acc[i][j][r] = 0.0f;

    const int r0  = (tid * 2)     >> 2, c80 = ((tid * 2)     & 3) << 3;
    const int r1  = (tid * 2 + 1) >> 2, c81 = ((tid * 2 + 1) & 3) << 3;
    const uint32_t so0 = (r0 * PITCH + c80) * 2;
    const uint32_t so1 = (r1 * PITCH + c81) * 2;

    auto stage = [&](int kb, int buf) {
        const int k0 = kb << 5;
        const uint32_t sb = smb + buf * BUF1_BY;
        cp16(sb + so0,           A_    + (size_t)(m0 + r0) * DIM_ + k0 + c80);
        cp16(sb + TILE_BY + so0, B_arr + (size_t)(n0 + r0) * DIM_ + k0 + c80);
        cp16(sb + so1,           A_    + (size_t)(m0 + r1) * DIM_ + k0 + c81);
        cp16(sb + TILE_BY + so1, B_arr + (size_t)(n0 + r1) * DIM_ + k0 + c81);
        CP_COMMIT();
    };

    stage(0, 0);
    stage(1, 1);

    int buf = 0;
    #pragma unroll 1
    for (int kb = 0; kb < NKB; kb++) {
        if (kb + 1 < NKB) CP_WAIT(1); else CP_WAIT(0);
        __syncthreads();

        const uint32_t sb = smb + buf * BUF1_BY;
        #pragma unroll
        for (int ks = 0; ks < 2; ks++) {
            uint32_t ah[2][4], bh[4][4];
            #pragma unroll
            for (int mt = 0; mt < 2; mt++)
                ldm4(ah[mt], sb + aoff[mt] + ks * 32);
            #pragma unroll
            for (int pr = 0; pr < 4; pr++)
                ldm4(bh[pr], sb + boff[pr] + ks * 32 + TILE_BY);
            #pragma unroll
            for (int mt = 0; mt < 2; mt++)
                #pragma unroll
                for (int nt = 0; nt < 8; nt++) {
                    const uint32_t* f = bh[nt >> 1];
                    mma16816(g.acc[mt][nt], ah[mt], (nt & 1) ? f[2] : f[0],
                             (nt & 1) ? f[3] : f[1]);
                }
        }
        __syncthreads();
        if (kb + 2 < NKB) stage(kb + 2, (kb + 2) % 3);
        buf = (buf + 1 == 3) ? 0 : buf + 1;
    }
}

// ---------------------------------------------------------------------------
// Wo GEMM: plain fp32 epilogue into d_out.
// ---------------------------------------------------------------------------
__global__ __launch_bounds__(256) void hmma_gemm1(const __half* __restrict__ A_,
                                                  const __half* __restrict__ B_arr,
                                                  float* __restrict__ C, int Ncols) {
    extern __shared__ __align__(128) __half sm[];
    GemmCtx g;
    const int tid = threadIdx.x, wid = tid >> 5;
    g.lane = tid & 31;
    g.wm = (wid & 3) * 32;
    g.wn = (wid >> 2) * 64;
    g.m0 = blockIdx.y * 128;
    g.n0 = blockIdx.x * 128;

    gemm_mainloop(g, sm, A_, B_arr);

    #pragma unroll
    for (int mt = 0; mt < 2; mt++) {
        const int row = g.m0 + g.wm + mt * 16 + (g.lane >> 2);
        #pragma unroll
        for (int nt = 0; nt < 8; nt++) {
            const int col = g.n0 + g.wn + nt * 8 + (g.lane & 3) * 2;
            float2 lo; lo.x = g.acc[mt][nt][0]; lo.y = g.acc[mt][nt][1];
            float2 hi; hi.x = g.acc[mt][nt][2]; hi.y = g.acc[mt][nt][3];
            *(float2*)&C[(size_t)row * Ncols + col]       = lo;
            *(float2*)&C[(size_t)(row + 8) * Ncols + col] = hi;
        }
    }
}

// ---------------------------------------------------------------------------
// QKV GEMM with fused RMSNorm+RoPE epilogue.
// Tiles x 0-7: Q -> g_q fp32 (normed, roped, NOT scaled).
// Tiles 8-9:  K -> g_kvh[.. 0..255] fp16 (normed, roped).
// Tiles 10-11: V -> g_kvh[.. 256..511] fp16 (passthrough).
// ---------------------------------------------------------------------------
__global__ __launch_bounds__(256) void hmma_gemm_qkv(const __half* __restrict__ A_,
                                                     const __half* __restrict__ B_arr,
                                                     const float* __restrict__ gq,
                                                     const float* __restrict__ gk) {
    extern __shared__ __align__(128) __half sm[];
    __shared__ float sg[128];
    const int tid = threadIdx.x, wid = tid >> 5;
    if (tid < 64)            sg[tid]      = gq[tid];
    else if (tid < 128)      sg[tid]      = gk[tid - 64];

    GemmCtx g;
    g.lane = tid & 31;
    g.wm = (wid & 3) * 32;
    g.wn = (wid >> 2) * 64;
    g.m0 = blockIdx.y * 128;
    g.n0 = blockIdx.x * 128;

    gemm_mainloop(g, sm, A_, B_arr);   // contains syncthreads -> sg visible

    const int lane = g.lane;
    const bool isQ = g.n0 < 1024;
    const bool isV = g.n0 >= 1280;
    const float* gg = isQ ? sg : sg + 64;

    float ifr[8];
    if (!isV) {
        #pragma unroll
        for (int nt = 0; nt < 8; nt++)
            ifr[nt] = exp2f((float)(nt * 4 + (lane & 3)) *
                            (-13.287712379549449f / 32.0f));
    }

    #pragma unroll
    for (int mt = 0; mt < 2; mt++)
        #pragma unroll
        for (int rh = 0; rh < 2; rh++) {
            const int row = g.m0 + g.wm + mt * 16 + (lane >> 2) + rh * 8;
            if (!isV) {
                float ss = 0.0f;
                #pragma unroll
                for (int nt = 0; nt < 8; nt++) {
                    float a0 = g.acc[mt][nt][rh * 2];
                    float a1 = g.acc[mt][nt][rh * 2 + 1];
                    ss += a0 * a0 + a1 * a1;
                }
                ss += __shfl_xor_sync(0xffffffffu, ss, 1);
                ss += __shfl_xor_sync(0xffffffffu, ss, 2);
                float rn = rsqrtf(ss * (1.0f / 64.0f) + 1e-6f);
                const float pos = (float)(row & (L_ - 1));
                #pragma unroll
                for (int nt = 0; nt < 8; nt++) {
                    int ch = nt * 8 + (lane & 3) * 2;   // col in head
                    float t1 = g.acc[mt][nt][rh * 2]     * rn * gg[ch];
                    float t2 = g.acc[mt][nt][rh * 2 + 1] * rn * gg[ch + 1];
                    float s, c;
                    sincosf(pos * ifr[nt], &s, &c);
                    float o0 = t1 * c - t2 * s;
                    float o1 = t1 * s + t2 * c;
                    int col = g.n0 + g.wn + ch;
                    if (isQ) {
                        float2 f; f.x = o0; f.y = o1;
                        *(float2*)&g_q[(size_t)row * DIM_ + col] = f;
                    } else {
                        *(uint32_t*)&g_kvh[(size_t)row * 512 + (col - 1024)] =
                            pack2h(__float2half(o0), __float2half(o1));
                    }
                }
            } else {
                #pragma unroll
                for (int nt = 0; nt < 8; nt++) {
                    int col = g.n0 + g.wn + nt * 8 + (lane & 3) * 2;
                    *(uint32_t*)&g_kvh[(size_t)row * 512 + 256 + (col - 1280)] =
                        pack2h(__float2half(g.acc[mt][nt][rh * 2]),
                               __float2half(g.acc[mt][nt][rh * 2 + 1]));
                }
            }
        }
}

// ---------------------------------------------------------------------------
// fp32 -> fp16 convert (4 elems/thread)
// ---------------------------------------------------------------------------
__global__ __launch_bounds__(256) void cvt16(const float* __restrict__ src,
                                             __half* __restrict__ dst) {
    size_t i = ((size_t)blockIdx.x * 256 + threadIdx.x) * 4;
    float4 v = *(const float4*)(src + i);
    ushort4 H;
    H.x = __half_as_ushort(__float2half(v.x));
    H.y = __half_as_ushort(__float2half(v.y));
    H.z = __half_as_ushort(__float2half(v.z));
    H.w = __half_as_ushort(__float2half(v.w));
    *(ushort4*)(dst + i) = H;
}

// ---------------------------------------------------------------------------
// Fused weight transpose: z selects {wq, wk, wv, wo}.
// ---------------------------------------------------------------------------
__global__ void wtrans4(const float* __restrict__ wq, const float* __restrict__ wk,
                        const float* __restrict__ wv, const float* __restrict__ wo) {
    const int z = blockIdx.z;
    const float* W;
    __half* T;
    int N;
    if (z == 0)      { W = wq; T = g_wt;               N = 1024; }
    else if (z == 1) { W = wk; T = g_wt + 1024 * DIM_; N = 256;  }
    else if (z == 2) { W = wv; T = g_wt + 1280 * DIM_; N = 256;  }
    else             { W = wo; T = g_wot;              N = 1024; }
    const int n0 = blockIdx.x * 32;
    if (n0 >= N) return;
    const int k0 = blockIdx.y * 32;

    __shared__ float t[32][33];
    const int tx = threadIdx.x, ty = threadIdx.y;
    #pragma unroll
    for (int i = 0; i < 4; i++) {
        int r = ty + i * 8;
        t[r][tx] = W[(size_t)(k0 + r) * N + n0 + tx];
    }
    __syncthreads();
    #pragma unroll
    for (int i = 0; i < 4; i++) {
        int r = ty + i * 8;
        T[(size_t)(n0 + r) * DIM_ + k0 + tx] = __float2half(t[tx][r]);
    }
}

// ---------------------------------------------------------------------------
// HMMA flash attention, fp16: S = (Qh+Ql)K, O = P V.
// K/V pre-converted fp16 in g_kvh (K roped). Q fp32 in g_q (scale 1/8 here).
// ---------------------------------------------------------------------------
#define AP      72
#define QH_OFF  0
#define QL_OFF  (4*64*AP)
#define KH_OFF  (2*QL_OFF)
#define VH_OFF  (KH_OFF + 64*AP)
#define P_OFF   (VH_OFF + 64*AP)
#define PW_SZ   (32*AP)
#define FSMEM   ((P_OFF + 8*PW_SZ)*2)

__global__ __launch_bounds__(256, 1) void fattn_kernel() {
    extern __shared__ __align__(16) __half fsm[];

    const int tid   = threadIdx.x;
    const int w     = tid >> 5;
    const int lane  = tid & 31;
    const int t     = blockIdx.x;
    const int bz    = blockIdx.y;
    const int b     = bz >> 2;
    const int hk    = bz & 3;
    const int hl    = w >> 1;
    const int h     = hk * 4 + hl;
    const int mhalf = w & 1;
    const uint32_t smb = smem_u32(fsm);

    // ---- load Q (4 heads): scale 1/8, split fp16 hi/lo ----
    #pragma unroll
    for (int u = 0; u < 8; u++) {
        int idx = tid + (u << 8);
        int hh  = idx >> 9;
        int rem = idx & 511;
        int row = rem >> 3, c8 = (rem & 7) << 3;
        const float* src = g_q + (size_t)(b * L_ + t * 64 + row) * DIM_
                         + (hk * 4 + hh) * 64 + c8;
        float4 v0 = *(const float4*)src, v1 = *(const float4*)(src + 4);
        float f[8] = {v0.x, v0.y, v0.z, v0.w, v1.x, v1.y, v1.z, v1.w};
        uint32_t hi[4], lo[4];
        #pragma unroll
        for (int j = 0; j < 4; j++) {
            float a = f[2*j] * 0.125f, c = f[2*j+1] * 0.125f;
            __half ha = __float2half(a), hc = __float2half(c);
            hi[j] = pack2h(ha, hc);
            lo[j] = pack2h(__float2half(a - __half2float(ha)),
                           __float2half(c - __half2float(hc)));
        }
        int off = hh * 64 * AP + row * AP + c8;
        *(uint4*)(fsm + QH_OFF + off) = make_uint4(hi[0], hi[1], hi[2], hi[3]);
        *(uint4*)(fsm + QL_OFF + off) = make_uint4(lo[0], lo[1], lo[2], lo[3]);
    }

    float sO[2][8][4];
    #pragma unroll
    for (int i = 0; i < 2; i++)
        #pragma unroll
        for (int j = 0; j < 8; j++)
            #pragma unroll
            for (int r = 0; r < 4; r++) sO[i][j][r] = 0.0f;
    float ms[2][2] = {{-1e30f, -1e30f}, {-1e30f, -1e30f}};
    float ssum[2][2] = {{0.0f, 0.0f}, {0.0f, 0.0f}};

    const uint32_t pw = P_OFF + w * PW_SZ;

    auto do_chunk = [&](int kb, bool partial) {
        __syncthreads();
        // ---- copy K/V fp16 chunk to smem (no conversion) ----
        #pragma unroll
        for (int u = 0; u < 2; u++) {
            int c = (tid << 1) + u;              // 0..511
            int row = c >> 3, h8 = (c & 7) << 3;
            const __half* base = g_kvh + (size_t)(b * L_ + kb + row) * 512
                               + hk * 64 + h8;
            uint4 kk = *(const uint4*)base;
            uint4 vv = *(const uint4*)(base + 256);
            int off = row * AP + h8;
            *(uint4*)(fsm + KH_OFF + off) = kk;
            *(uint4*)(fsm + VH_OFF + off) = vv;
        }
        __syncthreads();

        // ---- S = (Qh + Ql) K^T ----
        float sS[2][8][4];
        #pragma unroll
        for (int i = 0; i < 2; i++)
            #pragma unroll
            for (int j = 0; j < 8; j++)
                #pragma unroll
                for (int r = 0; r < 4; r++) sS[i][j][r] = 0.0f;

        #pragma unroll
        for (int kt = 0; kt < 4; kt++) {
            uint32_t ah[2][4], al[2][4], bh[4][4];
            #pragma unroll
            for (int mt = 0; mt < 2; mt++) {
                uint32_t ao = smb + 2 * (QH_OFF + hl * 64 * AP
                    + (mhalf * 32 + mt * 16 + (lane & 15)) * AP
                    + kt * 16 + ((lane >> 4) << 3));
                ldm4(ah[mt], ao);
                ldm4(al[mt], ao + 2 * QL_OFF);
            }
            #pragma unroll
            for (int pr = 0; pr < 4; pr++) {
                uint32_t bo = smb + 2 * (KH_OFF
                    + (pr * 16 + (lane & 7) + ((lane >> 4) & 1) * 8) * AP
                    + kt * 16 + (((lane >> 3) & 1) << 3));
                ldm4(bh[pr], bo);
            }
            #pragma unroll
            for (int mt = 0; mt < 2; mt++)
                #pragma unroll
                for (int nt = 0; nt < 8; nt++) {
                    const uint32_t* f = bh[nt >> 1];
                    mma16816(sS[mt][nt], ah[mt], (nt & 1) ? f[2] : f[0],
                             (nt & 1) ? f[3] : f[1]);
                }
            #pragma unroll
            for (int mt = 0; mt < 2; mt++)
                #pragma unroll
                for (int nt = 0; nt < 8; nt++) {
                    const uint32_t* f = bh[nt >> 1];
                    mma16816(sS[mt][nt], al[mt], (nt & 1) ? f[2] : f[0],
                             (nt & 1) ? f[3] : f[1]);
                }
        }

        if (partial) {
            #pragma unroll
            for (int mt = 0; mt < 2; mt++)
                #pragma unroll
                for (int rh = 0; rh < 2; rh++) {
                    int iq = t * 64 + mhalf * 32 + mt * 16 + (lane >> 2) + rh * 8;
                    #pragma unroll
                    for (int nt = 0; nt < 8; nt++)
                        #pragma unroll
                        for (int c = 0; c < 2; c++) {
                            int j = kb + nt * 8 + (lane & 3) * 2 + c;
                            bool valid = (j <= iq) && ((j >= iq - 256) || (j < 64));
                            if (!valid) sS[mt][nt][rh * 2 + c] = -INFINITY;
                        }
                }
        }

        // ---- online softmax ----
        #pragma unroll
        for (int mt = 0; mt < 2; mt++)
            #pragma unroll
            for (int rh = 0; rh < 2; rh++) {
                float rmax = -INFINITY;
                #pragma unroll
                for (int nt = 0; nt < 8; nt++)
                    rmax = fmaxf(rmax, fmaxf(sS[mt][nt][rh*2], sS[mt][nt][rh*2+1]));
                rmax = fmaxf(rmax, __shfl_xor_sync(0xffffffffu, rmax, 1));
                rmax = fmaxf(rmax, __shfl_xor_sync(0xffffffffu, rmax, 2));
                float mn = fmaxf(ms[mt][rh], rmax);
                float corr = __expf(ms[mt][rh] - mn);
                float rs = 0.0f;
                #pragma unroll
                for (int nt = 0; nt < 8; nt++) {
                    float e0 = __expf(sS[mt][nt][rh*2]     - mn);
                    float e1 = __expf(sS[mt][nt][rh*2 + 1] - mn);
                    sS[mt][nt][rh*2] = e0; sS[mt][nt][rh*2+1] = e1;
                    sO[mt][nt][rh*2]   *= corr;
                    sO[mt][nt][rh*2+1] *= corr;
                    rs += e0 + e1;
                }
                rs += __shfl_xor_sync(0xffffffffu, rs, 1);
                rs += __shfl_xor_sync(0xffffffffu, rs, 2);
                ssum[mt][rh] = ssum[mt][rh] * corr + rs;
                ms[mt][rh] = mn;
            }

        // ---- P (fp16) x V ----
        #pragma unroll
        for (int mt = 0; mt < 2; mt++)
            #pragma unroll
            for (int rh = 0; rh < 2; rh++)
                #pragma unroll
                for (int nt = 0; nt < 8; nt++) {
                    float e0 = sS[mt][nt][rh*2], e1 = sS[mt][nt][rh*2+1];
                    uint32_t pk = pack2h(__float2half(e0), __float2half(e1));
                    uint32_t off = pw + (mt * 16 + (lane >> 2) + rh * 8) * AP
                                 + nt * 8 + (lane & 3) * 2;
                    *(uint32_t*)((char*)fsm + 2 * off) = pk;
                }
        __syncwarp();
        #pragma unroll
        for (int kt = 0; kt < 4; kt++) {
            uint32_t ap[2][4], vh[4][4];
            #pragma unroll
            for (int mt = 0; mt < 2; mt++) {
                uint32_t ao = smb + 2 * (pw + (mt * 16 + (lane & 15)) * AP
                                         + kt * 16 + ((lane >> 4) << 3));
                ldm4(ap[mt], ao);
            }
            #pragma unroll
            for (int pr = 0; pr < 4; pr++) {
                uint32_t bo = smb + 2 * (VH_OFF
                    + (kt * 16 + (lane & 7) + ((lane >> 3) & 1) * 8) * AP
                    + pr * 16 + (((lane >> 4) & 1) << 3));
                ldm4t(vh[pr], bo);
            }
            #pragma unroll
            for (int mt = 0; mt < 2; mt++)
                #pragma unroll
                for (int nt = 0; nt < 8; nt++) {
                    const uint32_t* f = vh[nt >> 1];
                    mma16816(sO[mt][nt], ap[mt], (nt & 1) ? f[2] : f[0],
                             (nt & 1) ? f[3] : f[1]);
                }
        }
        __syncwarp();
    };

    if (t > 4) do_chunk(0, false);
    int c0 = t - 4; if (c0 < 0) c0 = 0;
    for (int cc = c0; cc <= t; cc++) {
        bool partial = (cc == t) || (t >= 5 && cc == t - 4);
        do_chunk(cc * 64, partial);
    }

    // ---- epilogue: normalize, write single fp16 ----
    #pragma unroll
    for (int mt = 0; mt < 2; mt++)
        #pragma unroll
        for (int rh = 0; rh < 2; rh++) {
            float inv = 1.0f / ssum[mt][rh];
            int tok = b * L_ + t * 64 + mhalf * 32 + mt * 16 + (lane >> 2) + rh * 8;
            #pragma unroll
            for (int nt = 0; nt < 8; nt++) {
                float v0 = sO[mt][nt][rh*2]     * inv;
                float v1 = sO[mt][nt][rh*2 + 1] * inv;
                size_t o = (size_t)tok * DIM_ + h * 64 + nt * 8 + (lane & 3) * 2;
                *(uint32_t*)&g_ao[o] = pack2h(__float2half(v0), __float2half(v1));
            }
        }
}

// ---------------------------------------------------------------------------
extern "C" void kernel_launch(void* const* d_in, const int* in_sizes, int n_in,
                              void* d_out, int out_size) {
    const float* x  = (const float*)d_in[0];
    const float* wq = (const float*)d_in[1];
    const float* wk = (const float*)d_in[2];
    const float* wv = (const float*)d_in[3];
    const float* wo = (const float*)d_in[4];
    const float* gq = (const float*)d_in[5];
    const float* gk = (const float*)d_in[6];

    __half *xh, *ao, *wt, *wot;
    cudaGetSymbolAddress((void**)&xh,  g_xh);
    cudaGetSymbolAddress((void**)&ao,  g_ao);
    cudaGetSymbolAddress((void**)&wt,  g_wt);
    cudaGetSymbolAddress((void**)&wot, g_wot);

    cudaFuncSetAttribute(hmma_gemm1, cudaFuncAttributeMaxDynamicSharedMemorySize,
                         GSMEM1);
    cudaFuncSetAttribute(hmma_gemm_qkv, cudaFuncAttributeMaxDynamicSharedMemorySize,
                         GSMEM1);
    cudaFuncSetAttribute(fattn_kernel, cudaFuncAttributeMaxDynamicSharedMemorySize,
                         FSMEM);

    // preps: input convert + fused weight transposes
    cvt16<<<NTOK * DIM_ / 1024, 256>>>(x, xh);
    wtrans4<<<dim3(32, 32, 4), dim3(32, 8)>>>(wq, wk, wv, wo);

    // fused Q|K|V projection + RMSNorm + RoPE + fp16 K/V emission
    hmma_gemm_qkv<<<dim3(12, NTOK / 128), 256, GSMEM1>>>(xh, wt, gq, gk);

    // flash attention (reads g_q fp32 + g_kvh fp16, writes g_ao fp16)
    fattn_kernel<<<dim3(32, 8), 256, FSMEM>>>();

    // output projection
    hmma_gemm1<<<dim3(DIM_ / 128, NTOK / 128), 256, GSMEM1>>>(ao, wot,
                                                              (float*)d_out, DIM_);
}